// round 3
// baseline (speedup 1.0000x reference)
#include <cuda_runtime.h>
#include <math.h>

// ---------------------------------------------------------------------------
// Problem constants
// ---------------------------------------------------------------------------
#define BB   4
#define SS   1024
#define DD   1024
#define HH   16
#define HD   64
#define DFF  4096
#define MEMN 256
#define ROWS (BB * SS)          // 4096

// Scratch arena: xln | t1 | res | qkv(3 slices) | ffn(4 slices) = 10 slices
#define SZ   ((size_t)ROWS * DD)      // 4,194,304 floats per slice
__device__ float g_scratch[10 * SZ];

// ---------------------------------------------------------------------------
// LayerNorm: one block per row of 1024
// ---------------------------------------------------------------------------
__global__ __launch_bounds__(256)
void ln_kernel(const float* __restrict__ X, const float* __restrict__ gam,
               const float* __restrict__ bet, float* __restrict__ Y)
{
    int row = blockIdx.x;
    int t = threadIdx.x;
    int lane = t & 31, w = t >> 5;
    const float4* x4 = (const float4*)(X + (size_t)row * DD);
    float4 v = x4[t];
    float s  = v.x + v.y + v.z + v.w;
    float ss = v.x * v.x + v.y * v.y + v.z * v.z + v.w * v.w;
    #pragma unroll
    for (int o = 16; o > 0; o >>= 1) {
        s  += __shfl_xor_sync(0xffffffffu, s,  o);
        ss += __shfl_xor_sync(0xffffffffu, ss, o);
    }
    __shared__ float red[16];
    if (lane == 0) { red[w] = s; red[w + 8] = ss; }
    __syncthreads();
    float st = 0.f, sst = 0.f;
    #pragma unroll
    for (int i = 0; i < 8; i++) { st += red[i]; sst += red[i + 8]; }
    float mu   = st * (1.0f / DD);
    float var  = sst * (1.0f / DD) - mu * mu;
    float rstd = rsqrtf(var + 1e-5f);
    const float4* g4 = (const float4*)gam;
    const float4* b4 = (const float4*)bet;
    float4 gg = g4[t], bb = b4[t], o4;
    o4.x = (v.x - mu) * rstd * gg.x + bb.x;
    o4.y = (v.y - mu) * rstd * gg.y + bb.y;
    o4.z = (v.z - mu) * rstd * gg.z + bb.z;
    o4.w = (v.w - mu) * rstd * gg.w + bb.w;
    ((float4*)(Y + (size_t)row * DD))[t] = o4;
}

// ---------------------------------------------------------------------------
// RoPE applied in-place to Q and K sections of the fused qkv buffer
// qkv layout: [row=b*S+s][sec*1024 + h*64 + d], row stride 3072
// ---------------------------------------------------------------------------
__global__ __launch_bounds__(256)
void rope_kernel(float* __restrict__ qkv, const float* __restrict__ cosb,
                 const float* __restrict__ sinb)
{
    int m = blockIdx.x;            // 0..4095
    int s = m & (SS - 1);
    int t = threadIdx.x;
    #pragma unroll
    for (int r = 0; r < 2; r++) {
        int p = t + r * 256;       // 0..511 -> (h, i)
        int h = p >> 5;
        int i = p & 31;
        float c  = cosb[s * 32 + i];
        float sn = sinb[s * 32 + i];
        #pragma unroll
        for (int sec = 0; sec < 2; sec++) {
            size_t base = (size_t)m * 3072 + sec * 1024 + h * 64 + 2 * i;
            float x0 = qkv[base], x1 = qkv[base + 1];
            qkv[base]     = x0 * c - x1 * sn;
            qkv[base + 1] = x0 * sn + x1 * c;
        }
    }
}

// ---------------------------------------------------------------------------
// SGEMM: C[M,N] = A[M,K] @ W[N,K]^T + bias (+gelu) (+residual)
// BM=128, BN=64, BK=16, 256 threads, 8x4 register tile per thread.
// ---------------------------------------------------------------------------
__device__ __forceinline__ float gelu_exact(float x) {
    return 0.5f * x * (1.0f + erff(x * 0.70710678118654752440f));
}

template<int ACT, bool HASRES>
__global__ __launch_bounds__(256)
void gemm_kernel(const float* __restrict__ A, int lda,
                 const float* __restrict__ W, int ldw,
                 const float* __restrict__ bias,
                 const float* R, float* C, int ldc, int K)
{
    __shared__ float As[16][128];
    __shared__ float Bs[16][64];
    int tid = threadIdx.x;
    int m0 = blockIdx.y * 128;
    int n0 = blockIdx.x * 64;

    int ar  = tid >> 2;        // 0..63 (rows ar and ar+64)
    int ac4 = tid & 3;         // k-chunk of 4
    int tm  = (tid >> 4) << 3; // 0..120 step 8
    int tn  = (tid & 15) << 2; // 0..60 step 4

    float acc[8][4];
    #pragma unroll
    for (int i = 0; i < 8; i++)
        #pragma unroll
        for (int j = 0; j < 4; j++) acc[i][j] = 0.f;

    const float* Ap = A + (size_t)m0 * lda;
    const float* Wp = W + (size_t)n0 * ldw;

    for (int k0 = 0; k0 < K; k0 += 16) {
        float4 a0 = *(const float4*)(Ap + (size_t)ar * lda + k0 + ac4 * 4);
        float4 a1 = *(const float4*)(Ap + (size_t)(ar + 64) * lda + k0 + ac4 * 4);
        float4 b0 = *(const float4*)(Wp + (size_t)ar * ldw + k0 + ac4 * 4);
        __syncthreads();
        As[ac4 * 4 + 0][ar] = a0.x; As[ac4 * 4 + 1][ar] = a0.y;
        As[ac4 * 4 + 2][ar] = a0.z; As[ac4 * 4 + 3][ar] = a0.w;
        As[ac4 * 4 + 0][ar + 64] = a1.x; As[ac4 * 4 + 1][ar + 64] = a1.y;
        As[ac4 * 4 + 2][ar + 64] = a1.z; As[ac4 * 4 + 3][ar + 64] = a1.w;
        Bs[ac4 * 4 + 0][ar] = b0.x; Bs[ac4 * 4 + 1][ar] = b0.y;
        Bs[ac4 * 4 + 2][ar] = b0.z; Bs[ac4 * 4 + 3][ar] = b0.w;
        __syncthreads();
        #pragma unroll
        for (int kk = 0; kk < 16; kk++) {
            float4 af0 = *(const float4*)&As[kk][tm];
            float4 af1 = *(const float4*)&As[kk][tm + 4];
            float4 bf  = *(const float4*)&Bs[kk][tn];
            float am[8] = {af0.x, af0.y, af0.z, af0.w, af1.x, af1.y, af1.z, af1.w};
            float bn[4] = {bf.x, bf.y, bf.z, bf.w};
            #pragma unroll
            for (int i = 0; i < 8; i++)
                #pragma unroll
                for (int j = 0; j < 4; j++)
                    acc[i][j] = fmaf(am[i], bn[j], acc[i][j]);
        }
    }

    float4 bv = *(const float4*)(bias + n0 + tn);
    #pragma unroll
    for (int i = 0; i < 8; i++) {
        int m = m0 + tm + i;
        float4 c;
        c.x = acc[i][0] + bv.x;
        c.y = acc[i][1] + bv.y;
        c.z = acc[i][2] + bv.z;
        c.w = acc[i][3] + bv.w;
        if (ACT == 1) {
            c.x = gelu_exact(c.x); c.y = gelu_exact(c.y);
            c.z = gelu_exact(c.z); c.w = gelu_exact(c.w);
        }
        if (HASRES) {
            float4 r = *(const float4*)(R + (size_t)m * ldc + n0 + tn);
            c.x += r.x; c.y += r.y; c.z += r.z; c.w += r.w;
        }
        *(float4*)(C + (size_t)m * ldc + n0 + tn) = c;
    }
}

// ---------------------------------------------------------------------------
// Flash attention: one warp per query row, 32-kv smem tiles (padded to 65),
// online softmax. grid = (S/8, H, B), 256 threads (8 warps).
// Q rows are always b*S+q; KV rows are b*kvlen+j.
// ---------------------------------------------------------------------------
__global__ __launch_bounds__(256)
void attn_kernel(const float* __restrict__ Q, int ldq,
                 const float* __restrict__ Kp, int ldk,
                 const float* __restrict__ Vp, int ldv,
                 float* __restrict__ O, int ldo,
                 int kvlen, int causal)
{
    __shared__ float ks[32][65];
    __shared__ float vs[32][65];
    __shared__ float qs[8][64];

    int b = blockIdx.z, h = blockIdx.y;
    int w = threadIdx.x >> 5, lane = threadIdx.x & 31;
    int q = blockIdx.x * 8 + w;

    const float* qrow = Q + ((size_t)(b * SS + q)) * ldq + h * 64;
    qs[w][lane]      = qrow[lane]      * 0.125f;   // 1/sqrt(64)
    qs[w][lane + 32] = qrow[lane + 32] * 0.125f;
    __syncwarp();

    float mrun = -INFINITY, lrun = 0.f, acc0 = 0.f, acc1 = 0.f;
    int limit  = causal ? (blockIdx.x * 8 + 8) : kvlen;
    int ntiles = (limit + 31) >> 5;

    for (int tile = 0; tile < ntiles; tile++) {
        int t0 = tile * 32;
        __syncthreads();
        {
            int tt = threadIdx.x;
            #pragma unroll
            for (int r = 0; r < 8; r++) {
                int idx = tt + r * 256;
                int row = idx >> 6, col = idx & 63;
                size_t roff = ((size_t)(b * kvlen + t0 + row));
                ks[row][col] = Kp[roff * ldk + h * 64 + col];
                vs[row][col] = Vp[roff * ldv + h * 64 + col];
            }
        }
        __syncthreads();

        int j = t0 + lane;
        float sc = 0.f;
        #pragma unroll
        for (int d = 0; d < 64; d++)
            sc = fmaf(qs[w][d], ks[lane][d], sc);
        bool masked = (causal && j > q) || (j >= kvlen);
        if (masked) sc = -INFINITY;

        float mx = sc;
        #pragma unroll
        for (int o = 16; o > 0; o >>= 1)
            mx = fmaxf(mx, __shfl_xor_sync(0xffffffffu, mx, o));
        float m_new = fmaxf(mrun, mx);
        float p = masked ? 0.f : expf(sc - m_new);
        float corr = expf(mrun - m_new);   // first tile: exp(-inf)=0
        float ps = p;
        #pragma unroll
        for (int o = 16; o > 0; o >>= 1)
            ps += __shfl_xor_sync(0xffffffffu, ps, o);
        lrun = lrun * corr + ps;
        mrun = m_new;
        acc0 *= corr; acc1 *= corr;
        #pragma unroll
        for (int jj = 0; jj < 32; jj++) {
            float pj = __shfl_sync(0xffffffffu, p, jj);
            acc0 = fmaf(pj, vs[jj][lane],      acc0);
            acc1 = fmaf(pj, vs[jj][lane + 32], acc1);
        }
    }

    float inv = 1.f / lrun;
    float* orow = O + ((size_t)(b * SS + q)) * ldo + h * 64;
    orow[lane]      = acc0 * inv;
    orow[lane + 32] = acc1 * inv;
}

// ---------------------------------------------------------------------------
// Host orchestration
// ---------------------------------------------------------------------------
extern "C" void kernel_launch(void* const* d_in, const int* in_sizes, int n_in,
                              void* d_out, int out_size)
{
    const float* tgt      = (const float*)d_in[0];
    const float* memory   = (const float*)d_in[1];
    // d_in[2] = tgt_mask (causal; implemented directly)
    const float* rope_cos = (const float*)d_in[3];
    const float* rope_sin = (const float*)d_in[4];
    const float* qkv_w    = (const float*)d_in[5];
    const float* qkv_b    = (const float*)d_in[6];
    const float* out_w    = (const float*)d_in[7];
    const float* out_b    = (const float*)d_in[8];
    const float* ca_in_w  = (const float*)d_in[9];
    const float* ca_in_b  = (const float*)d_in[10];
    const float* ca_out_w = (const float*)d_in[11];
    const float* ca_out_b = (const float*)d_in[12];
    const float* ffn_w1   = (const float*)d_in[13];
    const float* ffn_b1   = (const float*)d_in[14];
    const float* ffn_w2   = (const float*)d_in[15];
    const float* ffn_b2   = (const float*)d_in[16];
    const float* ln1_g    = (const float*)d_in[17];
    const float* ln1_b    = (const float*)d_in[18];
    const float* ln2_g    = (const float*)d_in[19];
    const float* ln2_b    = (const float*)d_in[20];
    const float* ln3_g    = (const float*)d_in[21];
    const float* ln3_b    = (const float*)d_in[22];
    float* outp = (float*)d_out;

    float* S_ = nullptr;
    cudaGetSymbolAddress((void**)&S_, g_scratch);
    float* xln = S_;
    float* t1  = S_ + SZ;
    float* res = S_ + 2 * SZ;
    float* qkv = S_ + 3 * SZ;          // 4096 x 3072 (also reused for CA q/kv)
    float* ffn = S_ + 6 * SZ;          // 4096 x 4096

    // ---- self-attention block ----
    ln_kernel<<<ROWS, 256>>>(tgt, ln1_g, ln1_b, xln);
    gemm_kernel<0, false><<<dim3(3072 / 64, ROWS / 128), 256>>>(
        xln, DD, qkv_w, DD, qkv_b, nullptr, qkv, 3072, DD);
    rope_kernel<<<ROWS, 256>>>(qkv, rope_cos, rope_sin);
    attn_kernel<<<dim3(SS / 8, HH, BB), 256>>>(
        qkv, 3072, qkv + 1024, 3072, qkv + 2048, 3072, t1, DD, SS, 1);
    gemm_kernel<0, true><<<dim3(DD / 64, ROWS / 128), 256>>>(
        t1, DD, out_w, DD, out_b, tgt, res, DD, DD);

    // ---- cross-attention block ----
    ln_kernel<<<ROWS, 256>>>(res, ln2_g, ln2_b, xln);
    float* caq = qkv;                  // 4096 x 1024
    float* ckv = qkv + SZ;             // 1024 x 2048 (k | v)
    gemm_kernel<0, false><<<dim3(DD / 64, ROWS / 128), 256>>>(
        xln, DD, ca_in_w, DD, ca_in_b, nullptr, caq, DD, DD);
    gemm_kernel<0, false><<<dim3(2048 / 64, (BB * MEMN) / 128), 256>>>(
        memory, DD, ca_in_w + 1024 * 1024, DD, ca_in_b + 1024, nullptr,
        ckv, 2048, DD);
    attn_kernel<<<dim3(SS / 8, HH, BB), 256>>>(
        caq, DD, ckv, 2048, ckv + 1024, 2048, t1, DD, MEMN, 0);
    gemm_kernel<0, true><<<dim3(DD / 64, ROWS / 128), 256>>>(
        t1, DD, ca_out_w, DD, ca_out_b, res, res, DD, DD);

    // ---- FFN block ----
    ln_kernel<<<ROWS, 256>>>(res, ln3_g, ln3_b, xln);
    gemm_kernel<1, false><<<dim3(DFF / 64, ROWS / 128), 256>>>(
        xln, DD, ffn_w1, DD, ffn_b1, nullptr, ffn, DFF, DD);
    gemm_kernel<0, true><<<dim3(DD / 64, ROWS / 128), 256>>>(
        ffn, DFF, ffn_w2, DFF, ffn_b2, res, outp, DD, DFF);
}

// round 5
// speedup vs baseline: 1.5702x; 1.5702x over previous
#include <cuda_runtime.h>
#include <cuda_bf16.h>
#include <math.h>
#include <stdint.h>

// ---------------------------------------------------------------------------
// Problem constants
// ---------------------------------------------------------------------------
#define BB   4
#define SS   1024
#define DD   1024
#define HH   16
#define HD   64
#define DFF  4096
#define MEMN 256
#define ROWS (BB * SS)          // 4096

#define SZ   ((size_t)ROWS * DD)
__device__ float g_scratch[10 * SZ];

// ---------------------------------------------------------------------------
// hi/lo split of 8 fp32 -> 8 bf16 hi + 8 bf16 lo (packed uint4 each)
// ---------------------------------------------------------------------------
__device__ __forceinline__ void split8(float4 a, float4 b, uint4& hi, uint4& lo) {
    __nv_bfloat162 h0 = __floats2bfloat162_rn(a.x, a.y);
    __nv_bfloat162 h1 = __floats2bfloat162_rn(a.z, a.w);
    __nv_bfloat162 h2 = __floats2bfloat162_rn(b.x, b.y);
    __nv_bfloat162 h3 = __floats2bfloat162_rn(b.z, b.w);
    __nv_bfloat162 l0 = __floats2bfloat162_rn(a.x - __low2float(h0), a.y - __high2float(h0));
    __nv_bfloat162 l1 = __floats2bfloat162_rn(a.z - __low2float(h1), a.w - __high2float(h1));
    __nv_bfloat162 l2 = __floats2bfloat162_rn(b.x - __low2float(h2), b.y - __high2float(h2));
    __nv_bfloat162 l3 = __floats2bfloat162_rn(b.z - __low2float(h3), b.w - __high2float(h3));
    hi.x = *(uint32_t*)&h0; hi.y = *(uint32_t*)&h1; hi.z = *(uint32_t*)&h2; hi.w = *(uint32_t*)&h3;
    lo.x = *(uint32_t*)&l0; lo.y = *(uint32_t*)&l1; lo.z = *(uint32_t*)&l2; lo.w = *(uint32_t*)&l3;
}

__device__ __forceinline__ float gelu_exact(float x) {
    return 0.5f * x * (1.0f + erff(x * 0.70710678118654752440f));
}

__device__ __forceinline__ void mma16816(float* d, const uint32_t* a, const uint32_t* b) {
    asm volatile("mma.sync.aligned.m16n8k16.row.col.f32.bf16.bf16.f32 "
        "{%0,%1,%2,%3}, {%4,%5,%6,%7}, {%8,%9}, {%0,%1,%2,%3};"
        : "+f"(d[0]), "+f"(d[1]), "+f"(d[2]), "+f"(d[3])
        : "r"(a[0]), "r"(a[1]), "r"(a[2]), "r"(a[3]), "r"(b[0]), "r"(b[1]));
}

// ---------------------------------------------------------------------------
// bf16 mma.sync GEMM with 3-term hi/lo split for fp32 accuracy.
// C[M,N] = A[M,K] @ W[N,K]^T + bias (+gelu) (+residual)
// BM=128, BN=128, BK=32, 256 threads (8 warps, warp tile 64x32).
// smem: bf16 tiles, row stride 40 (conflict-free fragment LDS).
// ---------------------------------------------------------------------------
#define TSTR 40   // bf16 elements per smem row

template<int ACT, bool HASRES>
__global__ __launch_bounds__(256, 1)
void mma_gemm(const float* __restrict__ A, int lda,
              const float* __restrict__ W, int ldw,
              const float* __restrict__ bias,
              const float* __restrict__ R,
              float* __restrict__ C, int ldc, int K)
{
    __shared__ __nv_bfloat16 Ah[128 * TSTR], Al[128 * TSTR];
    __shared__ __nv_bfloat16 Bh[128 * TSTR], Bl[128 * TSTR];

    int tid  = threadIdx.x;
    int wid  = tid >> 5, lane = tid & 31;
    int m0   = blockIdx.y * 128, n0 = blockIdx.x * 128;

    // fill mapping: each thread owns one row-half (16 fp32) of A and of B
    int frow = tid >> 1;
    int fcol = (tid & 1) * 16;
    const float* arow = A + (size_t)(m0 + frow) * lda + fcol;
    const float* brow = W + (size_t)(n0 + frow) * ldw + fcol;

    // warp tiling: 2 warps in M (64 each), 4 warps in N (32 each)
    int wm = (wid & 1) * 64;
    int wn = (wid >> 1) * 32;
    int r  = lane >> 2;          // 0..7
    int cq = (lane & 3) * 2;     // 0,2,4,6

    float acc[4][4][4];
    #pragma unroll
    for (int mt = 0; mt < 4; mt++)
        #pragma unroll
        for (int nt = 0; nt < 4; nt++)
            #pragma unroll
            for (int i = 0; i < 4; i++) acc[mt][nt][i] = 0.f;

    float4 pa[4], pb[4];
    #pragma unroll
    for (int i = 0; i < 4; i++) {
        pa[i] = *(const float4*)(arow + i * 4);
        pb[i] = *(const float4*)(brow + i * 4);
    }

    for (int k0 = 0; k0 < K; k0 += 32) {
        // convert current chunk into smem
        {
            uint4 hi, lo;
            int base = frow * TSTR + fcol;
            split8(pa[0], pa[1], hi, lo);
            *(uint4*)&Ah[base] = hi; *(uint4*)&Al[base] = lo;
            split8(pa[2], pa[3], hi, lo);
            *(uint4*)&Ah[base + 8] = hi; *(uint4*)&Al[base + 8] = lo;
            split8(pb[0], pb[1], hi, lo);
            *(uint4*)&Bh[base] = hi; *(uint4*)&Bl[base] = lo;
            split8(pb[2], pb[3], hi, lo);
            *(uint4*)&Bh[base + 8] = hi; *(uint4*)&Bl[base + 8] = lo;
        }
        __syncthreads();

        // prefetch next chunk (overlaps with mma phase)
        if (k0 + 32 < K) {
            const float* an = arow + k0 + 32;
            const float* bn = brow + k0 + 32;
            #pragma unroll
            for (int i = 0; i < 4; i++) {
                pa[i] = *(const float4*)(an + i * 4);
                pb[i] = *(const float4*)(bn + i * 4);
            }
        }

        // mma over the two k16 halves
        #pragma unroll
        for (int kh = 0; kh < 2; kh++) {
            int c = cq + kh * 16;
            uint32_t ah[4][4], al[4][4], bh[4][2], bl[4][2];
            #pragma unroll
            for (int mt = 0; mt < 4; mt++) {
                int rb = (wm + mt * 16 + r) * TSTR;
                int rb8 = rb + 8 * TSTR;
                ah[mt][0] = *(const uint32_t*)&Ah[rb + c];
                ah[mt][1] = *(const uint32_t*)&Ah[rb8 + c];
                ah[mt][2] = *(const uint32_t*)&Ah[rb + c + 8];
                ah[mt][3] = *(const uint32_t*)&Ah[rb8 + c + 8];
                al[mt][0] = *(const uint32_t*)&Al[rb + c];
                al[mt][1] = *(const uint32_t*)&Al[rb8 + c];
                al[mt][2] = *(const uint32_t*)&Al[rb + c + 8];
                al[mt][3] = *(const uint32_t*)&Al[rb8 + c + 8];
            }
            #pragma unroll
            for (int nt = 0; nt < 4; nt++) {
                int nb = (wn + nt * 8 + r) * TSTR;
                bh[nt][0] = *(const uint32_t*)&Bh[nb + c];
                bh[nt][1] = *(const uint32_t*)&Bh[nb + c + 8];
                bl[nt][0] = *(const uint32_t*)&Bl[nb + c];
                bl[nt][1] = *(const uint32_t*)&Bl[nb + c + 8];
            }
            #pragma unroll
            for (int mt = 0; mt < 4; mt++)
                #pragma unroll
                for (int nt = 0; nt < 4; nt++) {
                    mma16816(acc[mt][nt], ah[mt], bh[nt]);
                    mma16816(acc[mt][nt], ah[mt], bl[nt]);
                    mma16816(acc[mt][nt], al[mt], bh[nt]);
                }
        }
        __syncthreads();
    }

    // epilogue: bias (+gelu) (+residual), fp32 out
    #pragma unroll
    for (int mt = 0; mt < 4; mt++) {
        int row0 = m0 + wm + mt * 16 + r;
        #pragma unroll
        for (int nt = 0; nt < 4; nt++) {
            int coln = n0 + wn + nt * 8 + cq;
            float2 bv = *(const float2*)(bias + coln);
            float v0 = acc[mt][nt][0] + bv.x;
            float v1 = acc[mt][nt][1] + bv.y;
            float v2 = acc[mt][nt][2] + bv.x;
            float v3 = acc[mt][nt][3] + bv.y;
            if (ACT == 1) {
                v0 = gelu_exact(v0); v1 = gelu_exact(v1);
                v2 = gelu_exact(v2); v3 = gelu_exact(v3);
            }
            if (HASRES) {
                float2 r0 = *(const float2*)(R + (size_t)row0 * ldc + coln);
                float2 r1 = *(const float2*)(R + (size_t)(row0 + 8) * ldc + coln);
                v0 += r0.x; v1 += r0.y; v2 += r1.x; v3 += r1.y;
            }
            *(float2*)(C + (size_t)row0 * ldc + coln)       = make_float2(v0, v1);
            *(float2*)(C + (size_t)(row0 + 8) * ldc + coln) = make_float2(v2, v3);
        }
    }
}

// ---------------------------------------------------------------------------
// LayerNorm
// ---------------------------------------------------------------------------
__global__ __launch_bounds__(256)
void ln_kernel(const float* __restrict__ X, const float* __restrict__ gam,
               const float* __restrict__ bet, float* __restrict__ Y)
{
    int row = blockIdx.x;
    int t = threadIdx.x;
    int lane = t & 31, w = t >> 5;
    const float4* x4 = (const float4*)(X + (size_t)row * DD);
    float4 v = x4[t];
    float s  = v.x + v.y + v.z + v.w;
    float ss = v.x * v.x + v.y * v.y + v.z * v.z + v.w * v.w;
    #pragma unroll
    for (int o = 16; o > 0; o >>= 1) {
        s  += __shfl_xor_sync(0xffffffffu, s,  o);
        ss += __shfl_xor_sync(0xffffffffu, ss, o);
    }
    __shared__ float red[16];
    if (lane == 0) { red[w] = s; red[w + 8] = ss; }
    __syncthreads();
    float st = 0.f, sst = 0.f;
    #pragma unroll
    for (int i = 0; i < 8; i++) { st += red[i]; sst += red[i + 8]; }
    float mu   = st * (1.0f / DD);
    float var  = sst * (1.0f / DD) - mu * mu;
    float rstd = rsqrtf(var + 1e-5f);
    const float4* g4 = (const float4*)gam;
    const float4* b4 = (const float4*)bet;
    float4 gg = g4[t], bb = b4[t], o4;
    o4.x = (v.x - mu) * rstd * gg.x + bb.x;
    o4.y = (v.y - mu) * rstd * gg.y + bb.y;
    o4.z = (v.z - mu) * rstd * gg.z + bb.z;
    o4.w = (v.w - mu) * rstd * gg.w + bb.w;
    ((float4*)(Y + (size_t)row * DD))[t] = o4;
}

// ---------------------------------------------------------------------------
// RoPE (in-place on q,k sections of fused qkv)
// ---------------------------------------------------------------------------
__global__ __launch_bounds__(256)
void rope_kernel(float* __restrict__ qkv, const float* __restrict__ cosb,
                 const float* __restrict__ sinb)
{
    int m = blockIdx.x;
    int s = m & (SS - 1);
    int t = threadIdx.x;
    #pragma unroll
    for (int r = 0; r < 2; r++) {
        int p = t + r * 256;
        int h = p >> 5;
        int i = p & 31;
        float c  = cosb[s * 32 + i];
        float sn = sinb[s * 32 + i];
        #pragma unroll
        for (int sec = 0; sec < 2; sec++) {
            size_t base = (size_t)m * 3072 + sec * 1024 + h * 64 + 2 * i;
            float x0 = qkv[base], x1 = qkv[base + 1];
            qkv[base]     = x0 * c - x1 * sn;
            qkv[base + 1] = x0 * sn + x1 * c;
        }
    }
}

// ---------------------------------------------------------------------------
// Flash attention (unchanged from R3 passing version)
// ---------------------------------------------------------------------------
__global__ __launch_bounds__(256)
void attn_kernel(const float* __restrict__ Q, int ldq,
                 const float* __restrict__ Kp, int ldk,
                 const float* __restrict__ Vp, int ldv,
                 float* __restrict__ O, int ldo,
                 int kvlen, int causal)
{
    __shared__ float ks[32][65];
    __shared__ float vs[32][65];
    __shared__ float qs[8][64];

    int b = blockIdx.z, h = blockIdx.y;
    int w = threadIdx.x >> 5, lane = threadIdx.x & 31;
    int q = blockIdx.x * 8 + w;

    const float* qrow = Q + ((size_t)(b * SS + q)) * ldq + h * 64;
    qs[w][lane]      = qrow[lane]      * 0.125f;
    qs[w][lane + 32] = qrow[lane + 32] * 0.125f;
    __syncwarp();

    float mrun = -INFINITY, lrun = 0.f, acc0 = 0.f, acc1 = 0.f;
    int limit  = causal ? (blockIdx.x * 8 + 8) : kvlen;
    int ntiles = (limit + 31) >> 5;

    for (int tile = 0; tile < ntiles; tile++) {
        int t0 = tile * 32;
        __syncthreads();
        {
            int tt = threadIdx.x;
            #pragma unroll
            for (int r = 0; r < 8; r++) {
                int idx = tt + r * 256;
                int row = idx >> 6, col = idx & 63;
                size_t roff = ((size_t)(b * kvlen + t0 + row));
                ks[row][col] = Kp[roff * ldk + h * 64 + col];
                vs[row][col] = Vp[roff * ldv + h * 64 + col];
            }
        }
        __syncthreads();

        int j = t0 + lane;
        float sc = 0.f;
        #pragma unroll
        for (int d = 0; d < 64; d++)
            sc = fmaf(qs[w][d], ks[lane][d], sc);
        bool masked = (causal && j > q) || (j >= kvlen);
        if (masked) sc = -INFINITY;

        float mx = sc;
        #pragma unroll
        for (int o = 16; o > 0; o >>= 1)
            mx = fmaxf(mx, __shfl_xor_sync(0xffffffffu, mx, o));
        float m_new = fmaxf(mrun, mx);
        float p = masked ? 0.f : expf(sc - m_new);
        float corr = expf(mrun - m_new);
        float ps = p;
        #pragma unroll
        for (int o = 16; o > 0; o >>= 1)
            ps += __shfl_xor_sync(0xffffffffu, ps, o);
        lrun = lrun * corr + ps;
        mrun = m_new;
        acc0 *= corr; acc1 *= corr;
        #pragma unroll
        for (int jj = 0; jj < 32; jj++) {
            float pj = __shfl_sync(0xffffffffu, p, jj);
            acc0 = fmaf(pj, vs[jj][lane],      acc0);
            acc1 = fmaf(pj, vs[jj][lane + 32], acc1);
        }
    }

    float inv = 1.f / lrun;
    float* orow = O + ((size_t)(b * SS + q)) * ldo + h * 64;
    orow[lane]      = acc0 * inv;
    orow[lane + 32] = acc1 * inv;
}

// ---------------------------------------------------------------------------
// Host orchestration
// ---------------------------------------------------------------------------
extern "C" void kernel_launch(void* const* d_in, const int* in_sizes, int n_in,
                              void* d_out, int out_size)
{
    const float* tgt      = (const float*)d_in[0];
    const float* memory   = (const float*)d_in[1];
    const float* rope_cos = (const float*)d_in[3];
    const float* rope_sin = (const float*)d_in[4];
    const float* qkv_w    = (const float*)d_in[5];
    const float* qkv_b    = (const float*)d_in[6];
    const float* out_w    = (const float*)d_in[7];
    const float* out_b    = (const float*)d_in[8];
    const float* ca_in_w  = (const float*)d_in[9];
    const float* ca_in_b  = (const float*)d_in[10];
    const float* ca_out_w = (const float*)d_in[11];
    const float* ca_out_b = (const float*)d_in[12];
    const float* ffn_w1   = (const float*)d_in[13];
    const float* ffn_b1   = (const float*)d_in[14];
    const float* ffn_w2   = (const float*)d_in[15];
    const float* ffn_b2   = (const float*)d_in[16];
    const float* ln1_g    = (const float*)d_in[17];
    const float* ln1_b    = (const float*)d_in[18];
    const float* ln2_g    = (const float*)d_in[19];
    const float* ln2_b    = (const float*)d_in[20];
    const float* ln3_g    = (const float*)d_in[21];
    const float* ln3_b    = (const float*)d_in[22];
    float* outp = (float*)d_out;

    float* S_ = nullptr;
    cudaGetSymbolAddress((void**)&S_, g_scratch);
    float* xln = S_;
    float* t1  = S_ + SZ;
    float* res = S_ + 2 * SZ;
    float* qkv = S_ + 3 * SZ;          // 4096 x 3072 (reused for CA q/kv)
    float* ffn = S_ + 6 * SZ;          // 4096 x 4096

    // ---- self-attention block ----
    ln_kernel<<<ROWS, 256>>>(tgt, ln1_g, ln1_b, xln);
    mma_gemm<0, false><<<dim3(3072 / 128, ROWS / 128), 256>>>(
        xln, DD, qkv_w, DD, qkv_b, nullptr, qkv, 3072, DD);
    rope_kernel<<<ROWS, 256>>>(qkv, rope_cos, rope_sin);
    attn_kernel<<<dim3(SS / 8, HH, BB), 256>>>(
        qkv, 3072, qkv + 1024, 3072, qkv + 2048, 3072, t1, DD, SS, 1);
    mma_gemm<0, true><<<dim3(DD / 128, ROWS / 128), 256>>>(
        t1, DD, out_w, DD, out_b, tgt, res, DD, DD);

    // ---- cross-attention block ----
    ln_kernel<<<ROWS, 256>>>(res, ln2_g, ln2_b, xln);
    float* caq = qkv;                  // 4096 x 1024
    float* ckv = qkv + SZ;             // 1024 x 2048 (k | v)
    mma_gemm<0, false><<<dim3(DD / 128, ROWS / 128), 256>>>(
        xln, DD, ca_in_w, DD, ca_in_b, nullptr, caq, DD, DD);
    mma_gemm<0, false><<<dim3(2048 / 128, (BB * MEMN) / 128), 256>>>(
        memory, DD, ca_in_w + 1024 * 1024, DD, ca_in_b + 1024, nullptr,
        ckv, 2048, DD);
    attn_kernel<<<dim3(SS / 8, HH, BB), 256>>>(
        caq, DD, ckv, 2048, ckv + 1024, 2048, t1, DD, MEMN, 0);
    mma_gemm<0, true><<<dim3(DD / 128, ROWS / 128), 256>>>(
        t1, DD, ca_out_w, DD, ca_out_b, res, res, DD, DD);

    // ---- FFN block ----
    ln_kernel<<<ROWS, 256>>>(res, ln3_g, ln3_b, xln);
    mma_gemm<1, false><<<dim3(DFF / 128, ROWS / 128), 256>>>(
        xln, DD, ffn_w1, DD, ffn_b1, nullptr, ffn, DFF, DD);
    mma_gemm<0, true><<<dim3(DD / 128, ROWS / 128), 256>>>(
        ffn, DFF, ffn_w2, DFF, ffn_b2, res, outp, DD, DFF);
}

// round 6
// speedup vs baseline: 2.4738x; 1.5754x over previous
#include <cuda_runtime.h>
#include <cuda_bf16.h>
#include <math.h>
#include <stdint.h>

// ---------------------------------------------------------------------------
// Problem constants
// ---------------------------------------------------------------------------
#define BB   4
#define SS   1024
#define DD   1024
#define HH   16
#define HD   64
#define DFF  4096
#define MEMN 256
#define ROWS (BB * SS)          // 4096

#define SZ   ((size_t)ROWS * DD)
__device__ float g_scratch[10 * SZ];

// ---------------------------------------------------------------------------
// helpers
// ---------------------------------------------------------------------------
__device__ __forceinline__ void split8(float4 a, float4 b, uint4& hi, uint4& lo) {
    __nv_bfloat162 h0 = __floats2bfloat162_rn(a.x, a.y);
    __nv_bfloat162 h1 = __floats2bfloat162_rn(a.z, a.w);
    __nv_bfloat162 h2 = __floats2bfloat162_rn(b.x, b.y);
    __nv_bfloat162 h3 = __floats2bfloat162_rn(b.z, b.w);
    __nv_bfloat162 l0 = __floats2bfloat162_rn(a.x - __low2float(h0), a.y - __high2float(h0));
    __nv_bfloat162 l1 = __floats2bfloat162_rn(a.z - __low2float(h1), a.w - __high2float(h1));
    __nv_bfloat162 l2 = __floats2bfloat162_rn(b.x - __low2float(h2), b.y - __high2float(h2));
    __nv_bfloat162 l3 = __floats2bfloat162_rn(b.z - __low2float(h3), b.w - __high2float(h3));
    hi.x = *(uint32_t*)&h0; hi.y = *(uint32_t*)&h1; hi.z = *(uint32_t*)&h2; hi.w = *(uint32_t*)&h3;
    lo.x = *(uint32_t*)&l0; lo.y = *(uint32_t*)&l1; lo.z = *(uint32_t*)&l2; lo.w = *(uint32_t*)&l3;
}

__device__ __forceinline__ void split2(float x, float y, uint32_t& hi, uint32_t& lo) {
    __nv_bfloat162 h = __floats2bfloat162_rn(x, y);
    __nv_bfloat162 l = __floats2bfloat162_rn(x - __low2float(h), y - __high2float(h));
    hi = *(uint32_t*)&h; lo = *(uint32_t*)&l;
}

__device__ __forceinline__ float gelu_exact(float x) {
    return 0.5f * x * (1.0f + erff(x * 0.70710678118654752440f));
}

__device__ __forceinline__ void mma16816(float* d, const uint32_t* a, const uint32_t* b) {
    asm volatile("mma.sync.aligned.m16n8k16.row.col.f32.bf16.bf16.f32 "
        "{%0,%1,%2,%3}, {%4,%5,%6,%7}, {%8,%9}, {%0,%1,%2,%3};"
        : "+f"(d[0]), "+f"(d[1]), "+f"(d[2]), "+f"(d[3])
        : "r"(a[0]), "r"(a[1]), "r"(a[2]), "r"(a[3]), "r"(b[0]), "r"(b[1]));
}

// ---------------------------------------------------------------------------
// bf16 mma.sync GEMM with 3-term hi/lo split (unchanged from R5 passing kernel)
// ---------------------------------------------------------------------------
#define TSTR 40

template<int ACT, bool HASRES>
__global__ __launch_bounds__(256, 1)
void mma_gemm(const float* __restrict__ A, int lda,
              const float* __restrict__ W, int ldw,
              const float* __restrict__ bias,
              const float* __restrict__ R,
              float* __restrict__ C, int ldc, int K)
{
    __shared__ __nv_bfloat16 Ah[128 * TSTR], Al[128 * TSTR];
    __shared__ __nv_bfloat16 Bh[128 * TSTR], Bl[128 * TSTR];

    int tid  = threadIdx.x;
    int wid  = tid >> 5, lane = tid & 31;
    int m0   = blockIdx.y * 128, n0 = blockIdx.x * 128;

    int frow = tid >> 1;
    int fcol = (tid & 1) * 16;
    const float* arow = A + (size_t)(m0 + frow) * lda + fcol;
    const float* brow = W + (size_t)(n0 + frow) * ldw + fcol;

    int wm = (wid & 1) * 64;
    int wn = (wid >> 1) * 32;
    int r  = lane >> 2;
    int cq = (lane & 3) * 2;

    float acc[4][4][4];
    #pragma unroll
    for (int mt = 0; mt < 4; mt++)
        #pragma unroll
        for (int nt = 0; nt < 4; nt++)
            #pragma unroll
            for (int i = 0; i < 4; i++) acc[mt][nt][i] = 0.f;

    float4 pa[4], pb[4];
    #pragma unroll
    for (int i = 0; i < 4; i++) {
        pa[i] = *(const float4*)(arow + i * 4);
        pb[i] = *(const float4*)(brow + i * 4);
    }

    for (int k0 = 0; k0 < K; k0 += 32) {
        {
            uint4 hi, lo;
            int base = frow * TSTR + fcol;
            split8(pa[0], pa[1], hi, lo);
            *(uint4*)&Ah[base] = hi; *(uint4*)&Al[base] = lo;
            split8(pa[2], pa[3], hi, lo);
            *(uint4*)&Ah[base + 8] = hi; *(uint4*)&Al[base + 8] = lo;
            split8(pb[0], pb[1], hi, lo);
            *(uint4*)&Bh[base] = hi; *(uint4*)&Bl[base] = lo;
            split8(pb[2], pb[3], hi, lo);
            *(uint4*)&Bh[base + 8] = hi; *(uint4*)&Bl[base + 8] = lo;
        }
        __syncthreads();

        if (k0 + 32 < K) {
            const float* an = arow + k0 + 32;
            const float* bn = brow + k0 + 32;
            #pragma unroll
            for (int i = 0; i < 4; i++) {
                pa[i] = *(const float4*)(an + i * 4);
                pb[i] = *(const float4*)(bn + i * 4);
            }
        }

        #pragma unroll
        for (int kh = 0; kh < 2; kh++) {
            int c = cq + kh * 16;
            uint32_t ah[4][4], al[4][4], bh[4][2], bl[4][2];
            #pragma unroll
            for (int mt = 0; mt < 4; mt++) {
                int rb = (wm + mt * 16 + r) * TSTR;
                int rb8 = rb + 8 * TSTR;
                ah[mt][0] = *(const uint32_t*)&Ah[rb + c];
                ah[mt][1] = *(const uint32_t*)&Ah[rb8 + c];
                ah[mt][2] = *(const uint32_t*)&Ah[rb + c + 8];
                ah[mt][3] = *(const uint32_t*)&Ah[rb8 + c + 8];
                al[mt][0] = *(const uint32_t*)&Al[rb + c];
                al[mt][1] = *(const uint32_t*)&Al[rb8 + c];
                al[mt][2] = *(const uint32_t*)&Al[rb + c + 8];
                al[mt][3] = *(const uint32_t*)&Al[rb8 + c + 8];
            }
            #pragma unroll
            for (int nt = 0; nt < 4; nt++) {
                int nb = (wn + nt * 8 + r) * TSTR;
                bh[nt][0] = *(const uint32_t*)&Bh[nb + c];
                bh[nt][1] = *(const uint32_t*)&Bh[nb + c + 8];
                bl[nt][0] = *(const uint32_t*)&Bl[nb + c];
                bl[nt][1] = *(const uint32_t*)&Bl[nb + c + 8];
            }
            #pragma unroll
            for (int mt = 0; mt < 4; mt++)
                #pragma unroll
                for (int nt = 0; nt < 4; nt++) {
                    mma16816(acc[mt][nt], ah[mt], bh[nt]);
                    mma16816(acc[mt][nt], ah[mt], bl[nt]);
                    mma16816(acc[mt][nt], al[mt], bh[nt]);
                }
        }
        __syncthreads();
    }

    #pragma unroll
    for (int mt = 0; mt < 4; mt++) {
        int row0 = m0 + wm + mt * 16 + r;
        #pragma unroll
        for (int nt = 0; nt < 4; nt++) {
            int coln = n0 + wn + nt * 8 + cq;
            float2 bv = *(const float2*)(bias + coln);
            float v0 = acc[mt][nt][0] + bv.x;
            float v1 = acc[mt][nt][1] + bv.y;
            float v2 = acc[mt][nt][2] + bv.x;
            float v3 = acc[mt][nt][3] + bv.y;
            if (ACT == 1) {
                v0 = gelu_exact(v0); v1 = gelu_exact(v1);
                v2 = gelu_exact(v2); v3 = gelu_exact(v3);
            }
            if (HASRES) {
                float2 r0 = *(const float2*)(R + (size_t)row0 * ldc + coln);
                float2 r1 = *(const float2*)(R + (size_t)(row0 + 8) * ldc + coln);
                v0 += r0.x; v1 += r0.y; v2 += r1.x; v3 += r1.y;
            }
            *(float2*)(C + (size_t)row0 * ldc + coln)       = make_float2(v0, v1);
            *(float2*)(C + (size_t)(row0 + 8) * ldc + coln) = make_float2(v2, v3);
        }
    }
}

// ---------------------------------------------------------------------------
// Tensor-core flash attention.
// CTA: 128 queries of one (b,h); 8 warps x 16 query rows; KV tile = 64.
// K smem [key][dim] hi/lo; V smem transposed [dim][key] hi/lo; Q in registers.
// 3-term hi/lo on both QK^T and P*V; fragment-level online softmax.
// ---------------------------------------------------------------------------
#define FSTR 72   // smem row stride (bf16 elems)

template<int CAUSAL>
__global__ __launch_bounds__(256)
void fa_kernel(const float* __restrict__ Q, int ldq,
               const float* __restrict__ Kp, int ldk,
               const float* __restrict__ Vp, int ldv,
               float* __restrict__ O, int ldo, int kvlen)
{
    __shared__ __nv_bfloat16 Kh[64 * FSTR], Kl[64 * FSTR];
    __shared__ __nv_bfloat16 Vh[64 * FSTR], Vl[64 * FSTR];

    int tid = threadIdx.x;
    int wid = tid >> 5, lane = tid & 31;
    int r   = lane >> 2;
    int cq  = (lane & 3) * 2;
    int b = blockIdx.z, h = blockIdx.y;
    int q0 = blockIdx.x * 128;
    int qrow0 = q0 + wid * 16 + r;      // rows qrow0 and qrow0+8
    int wmin  = q0 + wid * 16;
    int wmax  = wmin + 15;

    // Q fragments in registers (scale 1/8 folded in)
    uint32_t qh[4][4], ql[4][4];
    {
        const float* qb  = Q + (size_t)(b * SS + qrow0) * ldq + h * 64;
        const float* qb8 = qb + (size_t)8 * ldq;
        #pragma unroll
        for (int ks = 0; ks < 4; ks++) {
            float2 v0 = *(const float2*)(qb  + 16 * ks + cq);
            float2 v1 = *(const float2*)(qb8 + 16 * ks + cq);
            float2 v2 = *(const float2*)(qb  + 16 * ks + cq + 8);
            float2 v3 = *(const float2*)(qb8 + 16 * ks + cq + 8);
            split2(v0.x * 0.125f, v0.y * 0.125f, qh[ks][0], ql[ks][0]);
            split2(v1.x * 0.125f, v1.y * 0.125f, qh[ks][1], ql[ks][1]);
            split2(v2.x * 0.125f, v2.y * 0.125f, qh[ks][2], ql[ks][2]);
            split2(v3.x * 0.125f, v3.y * 0.125f, qh[ks][3], ql[ks][3]);
        }
    }

    float oacc[8][4];
    #pragma unroll
    for (int nf = 0; nf < 8; nf++)
        #pragma unroll
        for (int i = 0; i < 4; i++) oacc[nf][i] = 0.f;
    float mrun0 = -INFINITY, mrun1 = -INFINITY, l0 = 0.f, l1 = 0.f;

    int ntiles = CAUSAL ? ((q0 >> 6) + 2) : (kvlen >> 6);

    // tile-load thread mappings
    int kkey = tid >> 2, kdg = (tid & 3) * 16;          // K: 1 key x 16 dims
    int vkp  = tid >> 3, vdg = (tid & 7) * 8;           // V: 2 keys x 8 dims

    for (int tile = 0; tile < ntiles; tile++) {
        int t0 = tile * 64;
        __syncthreads();
        {   // K tile: [key][dim]
            const float* kr = Kp + (size_t)(b * kvlen + t0 + kkey) * ldk + h * 64 + kdg;
            float4 x0 = *(const float4*)(kr);
            float4 x1 = *(const float4*)(kr + 4);
            float4 x2 = *(const float4*)(kr + 8);
            float4 x3 = *(const float4*)(kr + 12);
            uint4 hi, lo;
            int base = kkey * FSTR + kdg;
            split8(x0, x1, hi, lo);
            *(uint4*)&Kh[base] = hi; *(uint4*)&Kl[base] = lo;
            split8(x2, x3, hi, lo);
            *(uint4*)&Kh[base + 8] = hi; *(uint4*)&Kl[base + 8] = lo;
        }
        {   // V tile transposed: [dim][key], packing key pairs
            const float* v0p = Vp + (size_t)(b * kvlen + t0 + 2 * vkp) * ldv + h * 64 + vdg;
            const float* v1p = v0p + ldv;
            float xa[8], ya[8];
            *(float4*)(xa)     = *(const float4*)(v0p);
            *(float4*)(xa + 4) = *(const float4*)(v0p + 4);
            *(float4*)(ya)     = *(const float4*)(v1p);
            *(float4*)(ya + 4) = *(const float4*)(v1p + 4);
            #pragma unroll
            for (int d = 0; d < 8; d++) {
                uint32_t hi, lo;
                split2(xa[d], ya[d], hi, lo);
                int off = (vdg + d) * FSTR + 2 * vkp;
                *(uint32_t*)&Vh[off] = hi;
                *(uint32_t*)&Vl[off] = lo;
            }
        }
        __syncthreads();

        bool active = !CAUSAL || (t0 <= wmax);
        if (!active) continue;

        // scores S = Q K^T (3-term)
        float sc[8][4];
        #pragma unroll
        for (int nf = 0; nf < 8; nf++)
            #pragma unroll
            for (int i = 0; i < 4; i++) sc[nf][i] = 0.f;

        #pragma unroll
        for (int ks = 0; ks < 4; ks++) {
            #pragma unroll
            for (int nf = 0; nf < 8; nf++) {
                int off = (nf * 8 + r) * FSTR + cq + 16 * ks;
                uint32_t bh[2], bl[2];
                bh[0] = *(const uint32_t*)&Kh[off];
                bh[1] = *(const uint32_t*)&Kh[off + 8];
                bl[0] = *(const uint32_t*)&Kl[off];
                bl[1] = *(const uint32_t*)&Kl[off + 8];
                mma16816(sc[nf], qh[ks], bh);
                mma16816(sc[nf], qh[ks], bl);
                mma16816(sc[nf], ql[ks], bh);
            }
        }

        if (CAUSAL && (t0 + 63 > wmin)) {
            #pragma unroll
            for (int nf = 0; nf < 8; nf++) {
                int jb = t0 + nf * 8 + cq;
                if (jb     > qrow0)     sc[nf][0] = -INFINITY;
                if (jb + 1 > qrow0)     sc[nf][1] = -INFINITY;
                if (jb     > qrow0 + 8) sc[nf][2] = -INFINITY;
                if (jb + 1 > qrow0 + 8) sc[nf][3] = -INFINITY;
            }
        }

        // online softmax (rows r and r+8 per lane)
        float mx0 = -INFINITY, mx1 = -INFINITY;
        #pragma unroll
        for (int nf = 0; nf < 8; nf++) {
            mx0 = fmaxf(mx0, fmaxf(sc[nf][0], sc[nf][1]));
            mx1 = fmaxf(mx1, fmaxf(sc[nf][2], sc[nf][3]));
        }
        mx0 = fmaxf(mx0, __shfl_xor_sync(0xffffffffu, mx0, 1));
        mx0 = fmaxf(mx0, __shfl_xor_sync(0xffffffffu, mx0, 2));
        mx1 = fmaxf(mx1, __shfl_xor_sync(0xffffffffu, mx1, 1));
        mx1 = fmaxf(mx1, __shfl_xor_sync(0xffffffffu, mx1, 2));
        float mn0 = fmaxf(mrun0, mx0), mn1 = fmaxf(mrun1, mx1);
        float c0 = __expf(mrun0 - mn0), c1 = __expf(mrun1 - mn1);
        float s0 = 0.f, s1 = 0.f;
        #pragma unroll
        for (int nf = 0; nf < 8; nf++) {
            sc[nf][0] = __expf(sc[nf][0] - mn0);
            sc[nf][1] = __expf(sc[nf][1] - mn0);
            sc[nf][2] = __expf(sc[nf][2] - mn1);
            sc[nf][3] = __expf(sc[nf][3] - mn1);
            s0 += sc[nf][0] + sc[nf][1];
            s1 += sc[nf][2] + sc[nf][3];
        }
        s0 += __shfl_xor_sync(0xffffffffu, s0, 1);
        s0 += __shfl_xor_sync(0xffffffffu, s0, 2);
        s1 += __shfl_xor_sync(0xffffffffu, s1, 1);
        s1 += __shfl_xor_sync(0xffffffffu, s1, 2);
        l0 = l0 * c0 + s0;
        l1 = l1 * c1 + s1;
        mrun0 = mn0; mrun1 = mn1;
        #pragma unroll
        for (int nf = 0; nf < 8; nf++) {
            oacc[nf][0] *= c0; oacc[nf][1] *= c0;
            oacc[nf][2] *= c1; oacc[nf][3] *= c1;
        }

        // O += P V (3-term)
        #pragma unroll
        for (int kg = 0; kg < 4; kg++) {
            uint32_t pah[4], pal[4];
            split2(sc[2 * kg][0],     sc[2 * kg][1],     pah[0], pal[0]);
            split2(sc[2 * kg][2],     sc[2 * kg][3],     pah[1], pal[1]);
            split2(sc[2 * kg + 1][0], sc[2 * kg + 1][1], pah[2], pal[2]);
            split2(sc[2 * kg + 1][2], sc[2 * kg + 1][3], pah[3], pal[3]);
            #pragma unroll
            for (int nf = 0; nf < 8; nf++) {
                int off = (nf * 8 + r) * FSTR + cq + 16 * kg;
                uint32_t bh[2], bl[2];
                bh[0] = *(const uint32_t*)&Vh[off];
                bh[1] = *(const uint32_t*)&Vh[off + 8];
                bl[0] = *(const uint32_t*)&Vl[off];
                bl[1] = *(const uint32_t*)&Vl[off + 8];
                mma16816(oacc[nf], pah, bh);
                mma16816(oacc[nf], pal, bh);
                mma16816(oacc[nf], pah, bl);
            }
        }
    }

    float inv0 = 1.0f / l0, inv1 = 1.0f / l1;
    float* ob  = O + (size_t)(b * SS + qrow0) * ldo + h * 64;
    float* ob8 = ob + (size_t)8 * ldo;
    #pragma unroll
    for (int nf = 0; nf < 8; nf++) {
        *(float2*)(ob  + nf * 8 + cq) = make_float2(oacc[nf][0] * inv0, oacc[nf][1] * inv0);
        *(float2*)(ob8 + nf * 8 + cq) = make_float2(oacc[nf][2] * inv1, oacc[nf][3] * inv1);
    }
}

// ---------------------------------------------------------------------------
// LayerNorm
// ---------------------------------------------------------------------------
__global__ __launch_bounds__(256)
void ln_kernel(const float* __restrict__ X, const float* __restrict__ gam,
               const float* __restrict__ bet, float* __restrict__ Y)
{
    int row = blockIdx.x;
    int t = threadIdx.x;
    int lane = t & 31, w = t >> 5;
    const float4* x4 = (const float4*)(X + (size_t)row * DD);
    float4 v = x4[t];
    float s  = v.x + v.y + v.z + v.w;
    float ss = v.x * v.x + v.y * v.y + v.z * v.z + v.w * v.w;
    #pragma unroll
    for (int o = 16; o > 0; o >>= 1) {
        s  += __shfl_xor_sync(0xffffffffu, s,  o);
        ss += __shfl_xor_sync(0xffffffffu, ss, o);
    }
    __shared__ float red[16];
    if (lane == 0) { red[w] = s; red[w + 8] = ss; }
    __syncthreads();
    float st = 0.f, sst = 0.f;
    #pragma unroll
    for (int i = 0; i < 8; i++) { st += red[i]; sst += red[i + 8]; }
    float mu   = st * (1.0f / DD);
    float var  = sst * (1.0f / DD) - mu * mu;
    float rstd = rsqrtf(var + 1e-5f);
    const float4* g4 = (const float4*)gam;
    const float4* b4 = (const float4*)bet;
    float4 gg = g4[t], bb = b4[t], o4;
    o4.x = (v.x - mu) * rstd * gg.x + bb.x;
    o4.y = (v.y - mu) * rstd * gg.y + bb.y;
    o4.z = (v.z - mu) * rstd * gg.z + bb.z;
    o4.w = (v.w - mu) * rstd * gg.w + bb.w;
    ((float4*)(Y + (size_t)row * DD))[t] = o4;
}

// ---------------------------------------------------------------------------
// RoPE (in-place on q,k sections of fused qkv)
// ---------------------------------------------------------------------------
__global__ __launch_bounds__(256)
void rope_kernel(float* __restrict__ qkv, const float* __restrict__ cosb,
                 const float* __restrict__ sinb)
{
    int m = blockIdx.x;
    int s = m & (SS - 1);
    int t = threadIdx.x;
    #pragma unroll
    for (int r = 0; r < 2; r++) {
        int p = t + r * 256;
        int h = p >> 5;
        int i = p & 31;
        float c  = cosb[s * 32 + i];
        float sn = sinb[s * 32 + i];
        #pragma unroll
        for (int sec = 0; sec < 2; sec++) {
            size_t base = (size_t)m * 3072 + sec * 1024 + h * 64 + 2 * i;
            float x0 = qkv[base], x1 = qkv[base + 1];
            qkv[base]     = x0 * c - x1 * sn;
            qkv[base + 1] = x0 * sn + x1 * c;
        }
    }
}

// ---------------------------------------------------------------------------
// Host orchestration
// ---------------------------------------------------------------------------
extern "C" void kernel_launch(void* const* d_in, const int* in_sizes, int n_in,
                              void* d_out, int out_size)
{
    const float* tgt      = (const float*)d_in[0];
    const float* memory   = (const float*)d_in[1];
    const float* rope_cos = (const float*)d_in[3];
    const float* rope_sin = (const float*)d_in[4];
    const float* qkv_w    = (const float*)d_in[5];
    const float* qkv_b    = (const float*)d_in[6];
    const float* out_w    = (const float*)d_in[7];
    const float* out_b    = (const float*)d_in[8];
    const float* ca_in_w  = (const float*)d_in[9];
    const float* ca_in_b  = (const float*)d_in[10];
    const float* ca_out_w = (const float*)d_in[11];
    const float* ca_out_b = (const float*)d_in[12];
    const float* ffn_w1   = (const float*)d_in[13];
    const float* ffn_b1   = (const float*)d_in[14];
    const float* ffn_w2   = (const float*)d_in[15];
    const float* ffn_b2   = (const float*)d_in[16];
    const float* ln1_g    = (const float*)d_in[17];
    const float* ln1_b    = (const float*)d_in[18];
    const float* ln2_g    = (const float*)d_in[19];
    const float* ln2_b    = (const float*)d_in[20];
    const float* ln3_g    = (const float*)d_in[21];
    const float* ln3_b    = (const float*)d_in[22];
    float* outp = (float*)d_out;

    float* S_ = nullptr;
    cudaGetSymbolAddress((void**)&S_, g_scratch);
    float* xln = S_;
    float* t1  = S_ + SZ;
    float* res = S_ + 2 * SZ;
    float* qkv = S_ + 3 * SZ;          // 4096 x 3072 (reused for CA q/kv)
    float* ffn = S_ + 6 * SZ;          // 4096 x 4096

    // ---- self-attention block ----
    ln_kernel<<<ROWS, 256>>>(tgt, ln1_g, ln1_b, xln);
    mma_gemm<0, false><<<dim3(3072 / 128, ROWS / 128), 256>>>(
        xln, DD, qkv_w, DD, qkv_b, nullptr, qkv, 3072, DD);
    rope_kernel<<<ROWS, 256>>>(qkv, rope_cos, rope_sin);
    fa_kernel<1><<<dim3(SS / 128, HH, BB), 256>>>(
        qkv, 3072, qkv + 1024, 3072, qkv + 2048, 3072, t1, DD, SS);
    mma_gemm<0, true><<<dim3(DD / 128, ROWS / 128), 256>>>(
        t1, DD, out_w, DD, out_b, tgt, res, DD, DD);

    // ---- cross-attention block ----
    ln_kernel<<<ROWS, 256>>>(res, ln2_g, ln2_b, xln);
    float* caq = qkv;                  // 4096 x 1024
    float* ckv = qkv + SZ;             // 1024 x 2048 (k | v)
    mma_gemm<0, false><<<dim3(DD / 128, ROWS / 128), 256>>>(
        xln, DD, ca_in_w, DD, ca_in_b, nullptr, caq, DD, DD);
    mma_gemm<0, false><<<dim3(2048 / 128, (BB * MEMN) / 128), 256>>>(
        memory, DD, ca_in_w + 1024 * 1024, DD, ca_in_b + 1024, nullptr,
        ckv, 2048, DD);
    fa_kernel<0><<<dim3(SS / 128, HH, BB), 256>>>(
        caq, DD, ckv, 2048, ckv + 1024, 2048, t1, DD, MEMN);
    mma_gemm<0, true><<<dim3(DD / 128, ROWS / 128), 256>>>(
        t1, DD, ca_out_w, DD, ca_out_b, res, res, DD, DD);

    // ---- FFN block ----
    ln_kernel<<<ROWS, 256>>>(res, ln3_g, ln3_b, xln);
    mma_gemm<1, false><<<dim3(DFF / 128, ROWS / 128), 256>>>(
        xln, DD, ffn_w1, DD, ffn_b1, nullptr, ffn, DFF, DD);
    mma_gemm<0, true><<<dim3(DD / 128, ROWS / 128), 256>>>(
        ffn, DFF, ffn_w2, DFF, ffn_b2, res, outp, DD, DFF);
}

// round 7
// speedup vs baseline: 2.5864x; 1.0455x over previous
#include <cuda_runtime.h>
#include <cuda_bf16.h>
#include <math.h>
#include <stdint.h>

// ---------------------------------------------------------------------------
// Problem constants
// ---------------------------------------------------------------------------
#define BB   4
#define SS   1024
#define DD   1024
#define HH   16
#define HD   64
#define DFF  4096
#define MEMN 256
#define ROWS (BB * SS)          // 4096

#define SZ   ((size_t)ROWS * DD)
__device__ float g_scratch[10 * SZ];

// ---------------------------------------------------------------------------
// helpers
// ---------------------------------------------------------------------------
__device__ __forceinline__ void split8(float4 a, float4 b, uint4& hi, uint4& lo) {
    __nv_bfloat162 h0 = __floats2bfloat162_rn(a.x, a.y);
    __nv_bfloat162 h1 = __floats2bfloat162_rn(a.z, a.w);
    __nv_bfloat162 h2 = __floats2bfloat162_rn(b.x, b.y);
    __nv_bfloat162 h3 = __floats2bfloat162_rn(b.z, b.w);
    __nv_bfloat162 l0 = __floats2bfloat162_rn(a.x - __low2float(h0), a.y - __high2float(h0));
    __nv_bfloat162 l1 = __floats2bfloat162_rn(a.z - __low2float(h1), a.w - __high2float(h1));
    __nv_bfloat162 l2 = __floats2bfloat162_rn(b.x - __low2float(h2), b.y - __high2float(h2));
    __nv_bfloat162 l3 = __floats2bfloat162_rn(b.z - __low2float(h3), b.w - __high2float(h3));
    hi.x = *(uint32_t*)&h0; hi.y = *(uint32_t*)&h1; hi.z = *(uint32_t*)&h2; hi.w = *(uint32_t*)&h3;
    lo.x = *(uint32_t*)&l0; lo.y = *(uint32_t*)&l1; lo.z = *(uint32_t*)&l2; lo.w = *(uint32_t*)&l3;
}

__device__ __forceinline__ void split2(float x, float y, uint32_t& hi, uint32_t& lo) {
    __nv_bfloat162 h = __floats2bfloat162_rn(x, y);
    __nv_bfloat162 l = __floats2bfloat162_rn(x - __low2float(h), y - __high2float(h));
    hi = *(uint32_t*)&h; lo = *(uint32_t*)&l;
}

__device__ __forceinline__ float gelu_exact(float x) {
    return 0.5f * x * (1.0f + erff(x * 0.70710678118654752440f));
}

__device__ __forceinline__ void mma16816(float* d, const uint32_t* a, const uint32_t* b) {
    asm volatile("mma.sync.aligned.m16n8k16.row.col.f32.bf16.bf16.f32 "
        "{%0,%1,%2,%3}, {%4,%5,%6,%7}, {%8,%9}, {%0,%1,%2,%3};"
        : "+f"(d[0]), "+f"(d[1]), "+f"(d[2]), "+f"(d[3])
        : "r"(a[0]), "r"(a[1]), "r"(a[2]), "r"(a[3]), "r"(b[0]), "r"(b[1]));
}

// ---------------------------------------------------------------------------
// bf16 mma.sync GEMM with 3-term hi/lo split, DOUBLE-BUFFERED smem.
// C[M,N] = A[M,K] @ W[N,K]^T + bias (+gelu) (+residual)
// BM=128, BN=128, BK=32, 256 threads (8 warps, warp tile 64x32).
// One __syncthreads per K-chunk; conversion overlaps MMA across warps.
// ---------------------------------------------------------------------------
#define TSTR 40                       // bf16 elements per smem row
#define GASZ (128 * TSTR)             // elems per array
#define GBUF (4 * GASZ)               // elems per buffer (Ah,Al,Bh,Bl)
#define GSMEM_BYTES (2 * GBUF * 2)    // 81920 bytes

template<int ACT, bool HASRES>
__global__ __launch_bounds__(256, 1)
void mma_gemm(const float* __restrict__ A, int lda,
              const float* __restrict__ W, int ldw,
              const float* __restrict__ bias,
              const float* __restrict__ R,
              float* __restrict__ C, int ldc, int K)
{
    extern __shared__ __nv_bfloat16 dsm[];

    int tid  = threadIdx.x;
    int wid  = tid >> 5, lane = tid & 31;
    int m0   = blockIdx.y * 128, n0 = blockIdx.x * 128;

    int frow = tid >> 1;
    int fcol = (tid & 1) * 16;
    const float* arow = A + (size_t)(m0 + frow) * lda + fcol;
    const float* brow = W + (size_t)(n0 + frow) * ldw + fcol;
    int sbase = frow * TSTR + fcol;

    int wm = (wid & 1) * 64;
    int wn = (wid >> 1) * 32;
    int r  = lane >> 2;
    int cq = (lane & 3) * 2;

    float acc[4][4][4];
    #pragma unroll
    for (int mt = 0; mt < 4; mt++)
        #pragma unroll
        for (int nt = 0; nt < 4; nt++)
            #pragma unroll
            for (int i = 0; i < 4; i++) acc[mt][nt][i] = 0.f;

    float4 pa[4], pb[4];
    #pragma unroll
    for (int i = 0; i < 4; i++) {
        pa[i] = *(const float4*)(arow + i * 4);
        pb[i] = *(const float4*)(brow + i * 4);
    }

    // store chunk 0 into buffer 0
    {
        __nv_bfloat16* Ah = dsm;            __nv_bfloat16* Al = dsm + GASZ;
        __nv_bfloat16* Bh = dsm + 2 * GASZ; __nv_bfloat16* Bl = dsm + 3 * GASZ;
        uint4 hi, lo;
        split8(pa[0], pa[1], hi, lo);
        *(uint4*)&Ah[sbase] = hi; *(uint4*)&Al[sbase] = lo;
        split8(pa[2], pa[3], hi, lo);
        *(uint4*)&Ah[sbase + 8] = hi; *(uint4*)&Al[sbase + 8] = lo;
        split8(pb[0], pb[1], hi, lo);
        *(uint4*)&Bh[sbase] = hi; *(uint4*)&Bl[sbase] = lo;
        split8(pb[2], pb[3], hi, lo);
        *(uint4*)&Bh[sbase + 8] = hi; *(uint4*)&Bl[sbase + 8] = lo;
    }
    __syncthreads();

    int NC = K >> 5;
    for (int c = 0; c < NC; ++c) {
        // prefetch next chunk into registers (latency overlapped with MMAs)
        if (c + 1 < NC) {
            const float* an = arow + (c + 1) * 32;
            const float* bn = brow + (c + 1) * 32;
            #pragma unroll
            for (int i = 0; i < 4; i++) {
                pa[i] = *(const float4*)(an + i * 4);
                pb[i] = *(const float4*)(bn + i * 4);
            }
        }

        // MMAs from buffer c&1
        {
            const __nv_bfloat16* Ah = dsm + (c & 1) * GBUF;
            const __nv_bfloat16* Al = Ah + GASZ;
            const __nv_bfloat16* Bh = Ah + 2 * GASZ;
            const __nv_bfloat16* Bl = Ah + 3 * GASZ;
            #pragma unroll
            for (int kh = 0; kh < 2; kh++) {
                int cc = cq + kh * 16;
                uint32_t ah[4][4], al[4][4], bh[4][2], bl[4][2];
                #pragma unroll
                for (int mt = 0; mt < 4; mt++) {
                    int rb = (wm + mt * 16 + r) * TSTR;
                    int rb8 = rb + 8 * TSTR;
                    ah[mt][0] = *(const uint32_t*)&Ah[rb + cc];
                    ah[mt][1] = *(const uint32_t*)&Ah[rb8 + cc];
                    ah[mt][2] = *(const uint32_t*)&Ah[rb + cc + 8];
                    ah[mt][3] = *(const uint32_t*)&Ah[rb8 + cc + 8];
                    al[mt][0] = *(const uint32_t*)&Al[rb + cc];
                    al[mt][1] = *(const uint32_t*)&Al[rb8 + cc];
                    al[mt][2] = *(const uint32_t*)&Al[rb + cc + 8];
                    al[mt][3] = *(const uint32_t*)&Al[rb8 + cc + 8];
                }
                #pragma unroll
                for (int nt = 0; nt < 4; nt++) {
                    int nb = (wn + nt * 8 + r) * TSTR;
                    bh[nt][0] = *(const uint32_t*)&Bh[nb + cc];
                    bh[nt][1] = *(const uint32_t*)&Bh[nb + cc + 8];
                    bl[nt][0] = *(const uint32_t*)&Bl[nb + cc];
                    bl[nt][1] = *(const uint32_t*)&Bl[nb + cc + 8];
                }
                #pragma unroll
                for (int mt = 0; mt < 4; mt++)
                    #pragma unroll
                    for (int nt = 0; nt < 4; nt++) {
                        mma16816(acc[mt][nt], ah[mt], bh[nt]);
                        mma16816(acc[mt][nt], ah[mt], bl[nt]);
                        mma16816(acc[mt][nt], al[mt], bh[nt]);
                    }
            }
        }

        // convert+store next chunk into the other buffer
        if (c + 1 < NC) {
            __nv_bfloat16* Ah = dsm + ((c + 1) & 1) * GBUF;
            __nv_bfloat16* Al = Ah + GASZ;
            __nv_bfloat16* Bh = Ah + 2 * GASZ;
            __nv_bfloat16* Bl = Ah + 3 * GASZ;
            uint4 hi, lo;
            split8(pa[0], pa[1], hi, lo);
            *(uint4*)&Ah[sbase] = hi; *(uint4*)&Al[sbase] = lo;
            split8(pa[2], pa[3], hi, lo);
            *(uint4*)&Ah[sbase + 8] = hi; *(uint4*)&Al[sbase + 8] = lo;
            split8(pb[0], pb[1], hi, lo);
            *(uint4*)&Bh[sbase] = hi; *(uint4*)&Bl[sbase] = lo;
            split8(pb[2], pb[3], hi, lo);
            *(uint4*)&Bh[sbase + 8] = hi; *(uint4*)&Bl[sbase + 8] = lo;
        }
        __syncthreads();
    }

    #pragma unroll
    for (int mt = 0; mt < 4; mt++) {
        int row0 = m0 + wm + mt * 16 + r;
        #pragma unroll
        for (int nt = 0; nt < 4; nt++) {
            int coln = n0 + wn + nt * 8 + cq;
            float2 bv = *(const float2*)(bias + coln);
            float v0 = acc[mt][nt][0] + bv.x;
            float v1 = acc[mt][nt][1] + bv.y;
            float v2 = acc[mt][nt][2] + bv.x;
            float v3 = acc[mt][nt][3] + bv.y;
            if (ACT == 1) {
                v0 = gelu_exact(v0); v1 = gelu_exact(v1);
                v2 = gelu_exact(v2); v3 = gelu_exact(v3);
            }
            if (HASRES) {
                float2 r0 = *(const float2*)(R + (size_t)row0 * ldc + coln);
                float2 r1 = *(const float2*)(R + (size_t)(row0 + 8) * ldc + coln);
                v0 += r0.x; v1 += r0.y; v2 += r1.x; v3 += r1.y;
            }
            *(float2*)(C + (size_t)row0 * ldc + coln)       = make_float2(v0, v1);
            *(float2*)(C + (size_t)(row0 + 8) * ldc + coln) = make_float2(v2, v3);
        }
    }
}

// ---------------------------------------------------------------------------
// Tensor-core flash attention (R6 version + occupancy 2)
// ---------------------------------------------------------------------------
#define FSTR 72

template<int CAUSAL>
__global__ __launch_bounds__(256, 2)
void fa_kernel(const float* __restrict__ Q, int ldq,
               const float* __restrict__ Kp, int ldk,
               const float* __restrict__ Vp, int ldv,
               float* __restrict__ O, int ldo, int kvlen)
{
    __shared__ __nv_bfloat16 Kh[64 * FSTR], Kl[64 * FSTR];
    __shared__ __nv_bfloat16 Vh[64 * FSTR], Vl[64 * FSTR];

    int tid = threadIdx.x;
    int wid = tid >> 5, lane = tid & 31;
    int r   = lane >> 2;
    int cq  = (lane & 3) * 2;
    int b = blockIdx.z, h = blockIdx.y;
    int q0 = blockIdx.x * 128;
    int qrow0 = q0 + wid * 16 + r;
    int wmin  = q0 + wid * 16;
    int wmax  = wmin + 15;

    uint32_t qh[4][4], ql[4][4];
    {
        const float* qb  = Q + (size_t)(b * SS + qrow0) * ldq + h * 64;
        const float* qb8 = qb + (size_t)8 * ldq;
        #pragma unroll
        for (int ks = 0; ks < 4; ks++) {
            float2 v0 = *(const float2*)(qb  + 16 * ks + cq);
            float2 v1 = *(const float2*)(qb8 + 16 * ks + cq);
            float2 v2 = *(const float2*)(qb  + 16 * ks + cq + 8);
            float2 v3 = *(const float2*)(qb8 + 16 * ks + cq + 8);
            split2(v0.x * 0.125f, v0.y * 0.125f, qh[ks][0], ql[ks][0]);
            split2(v1.x * 0.125f, v1.y * 0.125f, qh[ks][1], ql[ks][1]);
            split2(v2.x * 0.125f, v2.y * 0.125f, qh[ks][2], ql[ks][2]);
            split2(v3.x * 0.125f, v3.y * 0.125f, qh[ks][3], ql[ks][3]);
        }
    }

    float oacc[8][4];
    #pragma unroll
    for (int nf = 0; nf < 8; nf++)
        #pragma unroll
        for (int i = 0; i < 4; i++) oacc[nf][i] = 0.f;
    float mrun0 = -INFINITY, mrun1 = -INFINITY, l0 = 0.f, l1 = 0.f;

    int ntiles = CAUSAL ? ((q0 >> 6) + 2) : (kvlen >> 6);

    int kkey = tid >> 2, kdg = (tid & 3) * 16;
    int vkp  = tid >> 3, vdg = (tid & 7) * 8;

    for (int tile = 0; tile < ntiles; tile++) {
        int t0 = tile * 64;
        __syncthreads();
        {
            const float* kr = Kp + (size_t)(b * kvlen + t0 + kkey) * ldk + h * 64 + kdg;
            float4 x0 = *(const float4*)(kr);
            float4 x1 = *(const float4*)(kr + 4);
            float4 x2 = *(const float4*)(kr + 8);
            float4 x3 = *(const float4*)(kr + 12);
            uint4 hi, lo;
            int base = kkey * FSTR + kdg;
            split8(x0, x1, hi, lo);
            *(uint4*)&Kh[base] = hi; *(uint4*)&Kl[base] = lo;
            split8(x2, x3, hi, lo);
            *(uint4*)&Kh[base + 8] = hi; *(uint4*)&Kl[base + 8] = lo;
        }
        {
            const float* v0p = Vp + (size_t)(b * kvlen + t0 + 2 * vkp) * ldv + h * 64 + vdg;
            const float* v1p = v0p + ldv;
            float xa[8], ya[8];
            *(float4*)(xa)     = *(const float4*)(v0p);
            *(float4*)(xa + 4) = *(const float4*)(v0p + 4);
            *(float4*)(ya)     = *(const float4*)(v1p);
            *(float4*)(ya + 4) = *(const float4*)(v1p + 4);
            #pragma unroll
            for (int d = 0; d < 8; d++) {
                uint32_t hi, lo;
                split2(xa[d], ya[d], hi, lo);
                int off = (vdg + d) * FSTR + 2 * vkp;
                *(uint32_t*)&Vh[off] = hi;
                *(uint32_t*)&Vl[off] = lo;
            }
        }
        __syncthreads();

        bool active = !CAUSAL || (t0 <= wmax);
        if (!active) continue;

        float sc[8][4];
        #pragma unroll
        for (int nf = 0; nf < 8; nf++)
            #pragma unroll
            for (int i = 0; i < 4; i++) sc[nf][i] = 0.f;

        #pragma unroll
        for (int ks = 0; ks < 4; ks++) {
            #pragma unroll
            for (int nf = 0; nf < 8; nf++) {
                int off = (nf * 8 + r) * FSTR + cq + 16 * ks;
                uint32_t bh[2], bl[2];
                bh[0] = *(const uint32_t*)&Kh[off];
                bh[1] = *(const uint32_t*)&Kh[off + 8];
                bl[0] = *(const uint32_t*)&Kl[off];
                bl[1] = *(const uint32_t*)&Kl[off + 8];
                mma16816(sc[nf], qh[ks], bh);
                mma16816(sc[nf], qh[ks], bl);
                mma16816(sc[nf], ql[ks], bh);
            }
        }

        if (CAUSAL && (t0 + 63 > wmin)) {
            #pragma unroll
            for (int nf = 0; nf < 8; nf++) {
                int jb = t0 + nf * 8 + cq;
                if (jb     > qrow0)     sc[nf][0] = -INFINITY;
                if (jb + 1 > qrow0)     sc[nf][1] = -INFINITY;
                if (jb     > qrow0 + 8) sc[nf][2] = -INFINITY;
                if (jb + 1 > qrow0 + 8) sc[nf][3] = -INFINITY;
            }
        }

        float mx0 = -INFINITY, mx1 = -INFINITY;
        #pragma unroll
        for (int nf = 0; nf < 8; nf++) {
            mx0 = fmaxf(mx0, fmaxf(sc[nf][0], sc[nf][1]));
            mx1 = fmaxf(mx1, fmaxf(sc[nf][2], sc[nf][3]));
        }
        mx0 = fmaxf(mx0, __shfl_xor_sync(0xffffffffu, mx0, 1));
        mx0 = fmaxf(mx0, __shfl_xor_sync(0xffffffffu, mx0, 2));
        mx1 = fmaxf(mx1, __shfl_xor_sync(0xffffffffu, mx1, 1));
        mx1 = fmaxf(mx1, __shfl_xor_sync(0xffffffffu, mx1, 2));
        float mn0 = fmaxf(mrun0, mx0), mn1 = fmaxf(mrun1, mx1);
        float c0 = __expf(mrun0 - mn0), c1 = __expf(mrun1 - mn1);
        float s0 = 0.f, s1 = 0.f;
        #pragma unroll
        for (int nf = 0; nf < 8; nf++) {
            sc[nf][0] = __expf(sc[nf][0] - mn0);
            sc[nf][1] = __expf(sc[nf][1] - mn0);
            sc[nf][2] = __expf(sc[nf][2] - mn1);
            sc[nf][3] = __expf(sc[nf][3] - mn1);
            s0 += sc[nf][0] + sc[nf][1];
            s1 += sc[nf][2] + sc[nf][3];
        }
        s0 += __shfl_xor_sync(0xffffffffu, s0, 1);
        s0 += __shfl_xor_sync(0xffffffffu, s0, 2);
        s1 += __shfl_xor_sync(0xffffffffu, s1, 1);
        s1 += __shfl_xor_sync(0xffffffffu, s1, 2);
        l0 = l0 * c0 + s0;
        l1 = l1 * c1 + s1;
        mrun0 = mn0; mrun1 = mn1;
        #pragma unroll
        for (int nf = 0; nf < 8; nf++) {
            oacc[nf][0] *= c0; oacc[nf][1] *= c0;
            oacc[nf][2] *= c1; oacc[nf][3] *= c1;
        }

        #pragma unroll
        for (int kg = 0; kg < 4; kg++) {
            uint32_t pah[4], pal[4];
            split2(sc[2 * kg][0],     sc[2 * kg][1],     pah[0], pal[0]);
            split2(sc[2 * kg][2],     sc[2 * kg][3],     pah[1], pal[1]);
            split2(sc[2 * kg + 1][0], sc[2 * kg + 1][1], pah[2], pal[2]);
            split2(sc[2 * kg + 1][2], sc[2 * kg + 1][3], pah[3], pal[3]);
            #pragma unroll
            for (int nf = 0; nf < 8; nf++) {
                int off = (nf * 8 + r) * FSTR + cq + 16 * kg;
                uint32_t bh[2], bl[2];
                bh[0] = *(const uint32_t*)&Vh[off];
                bh[1] = *(const uint32_t*)&Vh[off + 8];
                bl[0] = *(const uint32_t*)&Vl[off];
                bl[1] = *(const uint32_t*)&Vl[off + 8];
                mma16816(oacc[nf], pah, bh);
                mma16816(oacc[nf], pal, bh);
                mma16816(oacc[nf], pah, bl);
            }
        }
    }

    float inv0 = 1.0f / l0, inv1 = 1.0f / l1;
    float* ob  = O + (size_t)(b * SS + qrow0) * ldo + h * 64;
    float* ob8 = ob + (size_t)8 * ldo;
    #pragma unroll
    for (int nf = 0; nf < 8; nf++) {
        *(float2*)(ob  + nf * 8 + cq) = make_float2(oacc[nf][0] * inv0, oacc[nf][1] * inv0);
        *(float2*)(ob8 + nf * 8 + cq) = make_float2(oacc[nf][2] * inv1, oacc[nf][3] * inv1);
    }
}

// ---------------------------------------------------------------------------
// LayerNorm
// ---------------------------------------------------------------------------
__global__ __launch_bounds__(256)
void ln_kernel(const float* __restrict__ X, const float* __restrict__ gam,
               const float* __restrict__ bet, float* __restrict__ Y)
{
    int row = blockIdx.x;
    int t = threadIdx.x;
    int lane = t & 31, w = t >> 5;
    const float4* x4 = (const float4*)(X + (size_t)row * DD);
    float4 v = x4[t];
    float s  = v.x + v.y + v.z + v.w;
    float ss = v.x * v.x + v.y * v.y + v.z * v.z + v.w * v.w;
    #pragma unroll
    for (int o = 16; o > 0; o >>= 1) {
        s  += __shfl_xor_sync(0xffffffffu, s,  o);
        ss += __shfl_xor_sync(0xffffffffu, ss, o);
    }
    __shared__ float red[16];
    if (lane == 0) { red[w] = s; red[w + 8] = ss; }
    __syncthreads();
    float st = 0.f, sst = 0.f;
    #pragma unroll
    for (int i = 0; i < 8; i++) { st += red[i]; sst += red[i + 8]; }
    float mu   = st * (1.0f / DD);
    float var  = sst * (1.0f / DD) - mu * mu;
    float rstd = rsqrtf(var + 1e-5f);
    const float4* g4 = (const float4*)gam;
    const float4* b4 = (const float4*)bet;
    float4 gg = g4[t], bb = b4[t], o4;
    o4.x = (v.x - mu) * rstd * gg.x + bb.x;
    o4.y = (v.y - mu) * rstd * gg.y + bb.y;
    o4.z = (v.z - mu) * rstd * gg.z + bb.z;
    o4.w = (v.w - mu) * rstd * gg.w + bb.w;
    ((float4*)(Y + (size_t)row * DD))[t] = o4;
}

// ---------------------------------------------------------------------------
// RoPE (in-place on q,k sections of fused qkv)
// ---------------------------------------------------------------------------
__global__ __launch_bounds__(256)
void rope_kernel(float* __restrict__ qkv, const float* __restrict__ cosb,
                 const float* __restrict__ sinb)
{
    int m = blockIdx.x;
    int s = m & (SS - 1);
    int t = threadIdx.x;
    #pragma unroll
    for (int r = 0; r < 2; r++) {
        int p = t + r * 256;
        int h = p >> 5;
        int i = p & 31;
        float c  = cosb[s * 32 + i];
        float sn = sinb[s * 32 + i];
        #pragma unroll
        for (int sec = 0; sec < 2; sec++) {
            size_t base = (size_t)m * 3072 + sec * 1024 + h * 64 + 2 * i;
            float x0 = qkv[base], x1 = qkv[base + 1];
            qkv[base]     = x0 * c - x1 * sn;
            qkv[base + 1] = x0 * sn + x1 * c;
        }
    }
}

// ---------------------------------------------------------------------------
// Host orchestration
// ---------------------------------------------------------------------------
extern "C" void kernel_launch(void* const* d_in, const int* in_sizes, int n_in,
                              void* d_out, int out_size)
{
    const float* tgt      = (const float*)d_in[0];
    const float* memory   = (const float*)d_in[1];
    const float* rope_cos = (const float*)d_in[3];
    const float* rope_sin = (const float*)d_in[4];
    const float* qkv_w    = (const float*)d_in[5];
    const float* qkv_b    = (const float*)d_in[6];
    const float* out_w    = (const float*)d_in[7];
    const float* out_b    = (const float*)d_in[8];
    const float* ca_in_w  = (const float*)d_in[9];
    const float* ca_in_b  = (const float*)d_in[10];
    const float* ca_out_w = (const float*)d_in[11];
    const float* ca_out_b = (const float*)d_in[12];
    const float* ffn_w1   = (const float*)d_in[13];
    const float* ffn_b1   = (const float*)d_in[14];
    const float* ffn_w2   = (const float*)d_in[15];
    const float* ffn_b2   = (const float*)d_in[16];
    const float* ln1_g    = (const float*)d_in[17];
    const float* ln1_b    = (const float*)d_in[18];
    const float* ln2_g    = (const float*)d_in[19];
    const float* ln2_b    = (const float*)d_in[20];
    const float* ln3_g    = (const float*)d_in[21];
    const float* ln3_b    = (const float*)d_in[22];
    float* outp = (float*)d_out;

    float* S_ = nullptr;
    cudaGetSymbolAddress((void**)&S_, g_scratch);
    float* xln = S_;
    float* t1  = S_ + SZ;
    float* res = S_ + 2 * SZ;
    float* qkv = S_ + 3 * SZ;          // 4096 x 3072 (reused for CA q/kv)
    float* ffn = S_ + 6 * SZ;          // 4096 x 4096

    static bool attr_done = false;
    if (!attr_done) {
        cudaFuncSetAttribute(mma_gemm<0, false>, cudaFuncAttributeMaxDynamicSharedMemorySize, GSMEM_BYTES);
        cudaFuncSetAttribute(mma_gemm<0, true>,  cudaFuncAttributeMaxDynamicSharedMemorySize, GSMEM_BYTES);
        cudaFuncSetAttribute(mma_gemm<1, false>, cudaFuncAttributeMaxDynamicSharedMemorySize, GSMEM_BYTES);
        attr_done = true;
    }

    // ---- self-attention block ----
    ln_kernel<<<ROWS, 256>>>(tgt, ln1_g, ln1_b, xln);
    mma_gemm<0, false><<<dim3(3072 / 128, ROWS / 128), 256, GSMEM_BYTES>>>(
        xln, DD, qkv_w, DD, qkv_b, nullptr, qkv, 3072, DD);
    rope_kernel<<<ROWS, 256>>>(qkv, rope_cos, rope_sin);
    fa_kernel<1><<<dim3(SS / 128, HH, BB), 256>>>(
        qkv, 3072, qkv + 1024, 3072, qkv + 2048, 3072, t1, DD, SS);
    mma_gemm<0, true><<<dim3(DD / 128, ROWS / 128), 256, GSMEM_BYTES>>>(
        t1, DD, out_w, DD, out_b, tgt, res, DD, DD);

    // ---- cross-attention block ----
    ln_kernel<<<ROWS, 256>>>(res, ln2_g, ln2_b, xln);
    float* caq = qkv;                  // 4096 x 1024
    float* ckv = qkv + SZ;             // 1024 x 2048 (k | v)
    mma_gemm<0, false><<<dim3(DD / 128, ROWS / 128), 256, GSMEM_BYTES>>>(
        xln, DD, ca_in_w, DD, ca_in_b, nullptr, caq, DD, DD);
    mma_gemm<0, false><<<dim3(2048 / 128, (BB * MEMN) / 128), 256, GSMEM_BYTES>>>(
        memory, DD, ca_in_w + 1024 * 1024, DD, ca_in_b + 1024, nullptr,
        ckv, 2048, DD);
    fa_kernel<0><<<dim3(SS / 128, HH, BB), 256>>>(
        caq, DD, ckv, 2048, ckv + 1024, 2048, t1, DD, MEMN);
    mma_gemm<0, true><<<dim3(DD / 128, ROWS / 128), 256, GSMEM_BYTES>>>(
        t1, DD, ca_out_w, DD, ca_out_b, res, res, DD, DD);

    // ---- FFN block ----
    ln_kernel<<<ROWS, 256>>>(res, ln3_g, ln3_b, xln);
    mma_gemm<1, false><<<dim3(DFF / 128, ROWS / 128), 256, GSMEM_BYTES>>>(
        xln, DD, ffn_w1, DD, ffn_b1, nullptr, ffn, DFF, DD);
    mma_gemm<0, true><<<dim3(DD / 128, ROWS / 128), 256, GSMEM_BYTES>>>(
        ffn, DFF, ffn_w2, DFF, ffn_b2, res, outp, DD, DFF);
}

// round 8
// speedup vs baseline: 2.9138x; 1.1266x over previous
#include <cuda_runtime.h>
#include <cuda_bf16.h>
#include <cuda_fp16.h>
#include <math.h>
#include <stdint.h>

// ---------------------------------------------------------------------------
// Problem constants
// ---------------------------------------------------------------------------
#define BB   4
#define SS   1024
#define DD   1024
#define HH   16
#define HD   64
#define DFF  4096
#define MEMN 256
#define ROWS (BB * SS)          // 4096

#define SZ   ((size_t)ROWS * DD)
__device__ float g_scratch[10 * SZ];

// ---------------------------------------------------------------------------
// helpers
// ---------------------------------------------------------------------------
// fp16 split: 8 fp32 -> 8 fp16 hi + 8 fp16 lo (residual)
__device__ __forceinline__ void split8h(float4 a, float4 b, uint4& hi, uint4& lo) {
    __half2 h0 = __floats2half2_rn(a.x, a.y);
    __half2 h1 = __floats2half2_rn(a.z, a.w);
    __half2 h2 = __floats2half2_rn(b.x, b.y);
    __half2 h3 = __floats2half2_rn(b.z, b.w);
    __half2 l0 = __floats2half2_rn(a.x - __low2float(h0), a.y - __high2float(h0));
    __half2 l1 = __floats2half2_rn(a.z - __low2float(h1), a.w - __high2float(h1));
    __half2 l2 = __floats2half2_rn(b.x - __low2float(h2), b.y - __high2float(h2));
    __half2 l3 = __floats2half2_rn(b.z - __low2float(h3), b.w - __high2float(h3));
    hi.x = *(uint32_t*)&h0; hi.y = *(uint32_t*)&h1; hi.z = *(uint32_t*)&h2; hi.w = *(uint32_t*)&h3;
    lo.x = *(uint32_t*)&l0; lo.y = *(uint32_t*)&l1; lo.z = *(uint32_t*)&l2; lo.w = *(uint32_t*)&l3;
}
// fp16 round only: 8 fp32 -> 8 fp16
__device__ __forceinline__ void round8h(float4 a, float4 b, uint4& hi) {
    __half2 h0 = __floats2half2_rn(a.x, a.y);
    __half2 h1 = __floats2half2_rn(a.z, a.w);
    __half2 h2 = __floats2half2_rn(b.x, b.y);
    __half2 h3 = __floats2half2_rn(b.z, b.w);
    hi.x = *(uint32_t*)&h0; hi.y = *(uint32_t*)&h1; hi.z = *(uint32_t*)&h2; hi.w = *(uint32_t*)&h3;
}
// bf16 splits (attention path)
__device__ __forceinline__ void split8(float4 a, float4 b, uint4& hi, uint4& lo) {
    __nv_bfloat162 h0 = __floats2bfloat162_rn(a.x, a.y);
    __nv_bfloat162 h1 = __floats2bfloat162_rn(a.z, a.w);
    __nv_bfloat162 h2 = __floats2bfloat162_rn(b.x, b.y);
    __nv_bfloat162 h3 = __floats2bfloat162_rn(b.z, b.w);
    __nv_bfloat162 l0 = __floats2bfloat162_rn(a.x - __low2float(h0), a.y - __high2float(h0));
    __nv_bfloat162 l1 = __floats2bfloat162_rn(a.z - __low2float(h1), a.w - __high2float(h1));
    __nv_bfloat162 l2 = __floats2bfloat162_rn(b.x - __low2float(h2), b.y - __high2float(h2));
    __nv_bfloat162 l3 = __floats2bfloat162_rn(b.z - __low2float(h3), b.w - __high2float(h3));
    hi.x = *(uint32_t*)&h0; hi.y = *(uint32_t*)&h1; hi.z = *(uint32_t*)&h2; hi.w = *(uint32_t*)&h3;
    lo.x = *(uint32_t*)&l0; lo.y = *(uint32_t*)&l1; lo.z = *(uint32_t*)&l2; lo.w = *(uint32_t*)&l3;
}
__device__ __forceinline__ void split2(float x, float y, uint32_t& hi, uint32_t& lo) {
    __nv_bfloat162 h = __floats2bfloat162_rn(x, y);
    __nv_bfloat162 l = __floats2bfloat162_rn(x - __low2float(h), y - __high2float(h));
    hi = *(uint32_t*)&h; lo = *(uint32_t*)&l;
}

__device__ __forceinline__ float gelu_exact(float x) {
    return 0.5f * x * (1.0f + erff(x * 0.70710678118654752440f));
}

__device__ __forceinline__ void mma16816(float* d, const uint32_t* a, const uint32_t* b) {
    asm volatile("mma.sync.aligned.m16n8k16.row.col.f32.bf16.bf16.f32 "
        "{%0,%1,%2,%3}, {%4,%5,%6,%7}, {%8,%9}, {%0,%1,%2,%3};"
        : "+f"(d[0]), "+f"(d[1]), "+f"(d[2]), "+f"(d[3])
        : "r"(a[0]), "r"(a[1]), "r"(a[2]), "r"(a[3]), "r"(b[0]), "r"(b[1]));
}
__device__ __forceinline__ void mma16816h(float* d, const uint32_t* a, const uint32_t* b) {
    asm volatile("mma.sync.aligned.m16n8k16.row.col.f32.f16.f16.f32 "
        "{%0,%1,%2,%3}, {%4,%5,%6,%7}, {%8,%9}, {%0,%1,%2,%3};"
        : "+f"(d[0]), "+f"(d[1]), "+f"(d[2]), "+f"(d[3])
        : "r"(a[0]), "r"(a[1]), "r"(a[2]), "r"(a[3]), "r"(b[0]), "r"(b[1]));
}

// ---------------------------------------------------------------------------
// fp16 2-term mma.sync GEMM: A split hi/lo (exact to ~2^-22), W rounded fp16.
// C[M,N] = A[M,K] @ W[N,K]^T + bias (+gelu) (+residual)
// BM=128, BN=128, BK=32, 256 threads (8 warps, warp tile 64x32).
// Double-buffered smem (3 arrays per buffer), one __syncthreads per chunk.
// ---------------------------------------------------------------------------
#define TSTR 40                       // fp16 elements per smem row
#define GASZ (128 * TSTR)             // elems per array
#define GBUF (3 * GASZ)               // elems per buffer (Ah,Al,Bh)
#define GSMEM_BYTES (2 * GBUF * 2)    // 61440 bytes

template<int ACT, bool HASRES>
__global__ __launch_bounds__(256, 1)
void mma_gemm(const float* __restrict__ A, int lda,
              const float* __restrict__ W, int ldw,
              const float* __restrict__ bias,
              const float* __restrict__ R,
              float* __restrict__ C, int ldc, int K)
{
    extern __shared__ __half dsm[];

    int tid  = threadIdx.x;
    int wid  = tid >> 5, lane = tid & 31;
    int m0   = blockIdx.y * 128, n0 = blockIdx.x * 128;

    int frow = tid >> 1;
    int fcol = (tid & 1) * 16;
    const float* arow = A + (size_t)(m0 + frow) * lda + fcol;
    const float* brow = W + (size_t)(n0 + frow) * ldw + fcol;
    int sbase = frow * TSTR + fcol;

    int wm = (wid & 1) * 64;
    int wn = (wid >> 1) * 32;
    int r  = lane >> 2;
    int cq = (lane & 3) * 2;

    float acc[4][4][4];
    #pragma unroll
    for (int mt = 0; mt < 4; mt++)
        #pragma unroll
        for (int nt = 0; nt < 4; nt++)
            #pragma unroll
            for (int i = 0; i < 4; i++) acc[mt][nt][i] = 0.f;

    float4 pa[4], pb[4];
    #pragma unroll
    for (int i = 0; i < 4; i++) {
        pa[i] = *(const float4*)(arow + i * 4);
        pb[i] = *(const float4*)(brow + i * 4);
    }

    // store chunk 0 into buffer 0
    {
        __half* Ah = dsm; __half* Al = dsm + GASZ; __half* Bh = dsm + 2 * GASZ;
        uint4 hi, lo;
        split8h(pa[0], pa[1], hi, lo);
        *(uint4*)&Ah[sbase] = hi; *(uint4*)&Al[sbase] = lo;
        split8h(pa[2], pa[3], hi, lo);
        *(uint4*)&Ah[sbase + 8] = hi; *(uint4*)&Al[sbase + 8] = lo;
        round8h(pb[0], pb[1], hi);
        *(uint4*)&Bh[sbase] = hi;
        round8h(pb[2], pb[3], hi);
        *(uint4*)&Bh[sbase + 8] = hi;
    }
    __syncthreads();

    int NC = K >> 5;
    for (int c = 0; c < NC; ++c) {
        if (c + 1 < NC) {
            const float* an = arow + (c + 1) * 32;
            const float* bn = brow + (c + 1) * 32;
            #pragma unroll
            for (int i = 0; i < 4; i++) {
                pa[i] = *(const float4*)(an + i * 4);
                pb[i] = *(const float4*)(bn + i * 4);
            }
        }

        {
            const __half* Ah = dsm + (c & 1) * GBUF;
            const __half* Al = Ah + GASZ;
            const __half* Bh = Ah + 2 * GASZ;
            #pragma unroll
            for (int kh = 0; kh < 2; kh++) {
                int cc = cq + kh * 16;
                uint32_t ah[4][4], al[4][4], bh[4][2];
                #pragma unroll
                for (int mt = 0; mt < 4; mt++) {
                    int rb = (wm + mt * 16 + r) * TSTR;
                    int rb8 = rb + 8 * TSTR;
                    ah[mt][0] = *(const uint32_t*)&Ah[rb + cc];
                    ah[mt][1] = *(const uint32_t*)&Ah[rb8 + cc];
                    ah[mt][2] = *(const uint32_t*)&Ah[rb + cc + 8];
                    ah[mt][3] = *(const uint32_t*)&Ah[rb8 + cc + 8];
                    al[mt][0] = *(const uint32_t*)&Al[rb + cc];
                    al[mt][1] = *(const uint32_t*)&Al[rb8 + cc];
                    al[mt][2] = *(const uint32_t*)&Al[rb + cc + 8];
                    al[mt][3] = *(const uint32_t*)&Al[rb8 + cc + 8];
                }
                #pragma unroll
                for (int nt = 0; nt < 4; nt++) {
                    int nb = (wn + nt * 8 + r) * TSTR;
                    bh[nt][0] = *(const uint32_t*)&Bh[nb + cc];
                    bh[nt][1] = *(const uint32_t*)&Bh[nb + cc + 8];
                }
                #pragma unroll
                for (int mt = 0; mt < 4; mt++)
                    #pragma unroll
                    for (int nt = 0; nt < 4; nt++) {
                        mma16816h(acc[mt][nt], ah[mt], bh[nt]);
                        mma16816h(acc[mt][nt], al[mt], bh[nt]);
                    }
            }
        }

        if (c + 1 < NC) {
            __half* Ah = dsm + ((c + 1) & 1) * GBUF;
            __half* Al = Ah + GASZ;
            __half* Bh = Ah + 2 * GASZ;
            uint4 hi, lo;
            split8h(pa[0], pa[1], hi, lo);
            *(uint4*)&Ah[sbase] = hi; *(uint4*)&Al[sbase] = lo;
            split8h(pa[2], pa[3], hi, lo);
            *(uint4*)&Ah[sbase + 8] = hi; *(uint4*)&Al[sbase + 8] = lo;
            round8h(pb[0], pb[1], hi);
            *(uint4*)&Bh[sbase] = hi;
            round8h(pb[2], pb[3], hi);
            *(uint4*)&Bh[sbase + 8] = hi;
        }
        __syncthreads();
    }

    #pragma unroll
    for (int mt = 0; mt < 4; mt++) {
        int row0 = m0 + wm + mt * 16 + r;
        #pragma unroll
        for (int nt = 0; nt < 4; nt++) {
            int coln = n0 + wn + nt * 8 + cq;
            float2 bv = *(const float2*)(bias + coln);
            float v0 = acc[mt][nt][0] + bv.x;
            float v1 = acc[mt][nt][1] + bv.y;
            float v2 = acc[mt][nt][2] + bv.x;
            float v3 = acc[mt][nt][3] + bv.y;
            if (ACT == 1) {
                v0 = gelu_exact(v0); v1 = gelu_exact(v1);
                v2 = gelu_exact(v2); v3 = gelu_exact(v3);
            }
            if (HASRES) {
                float2 r0 = *(const float2*)(R + (size_t)row0 * ldc + coln);
                float2 r1 = *(const float2*)(R + (size_t)(row0 + 8) * ldc + coln);
                v0 += r0.x; v1 += r0.y; v2 += r1.x; v3 += r1.y;
            }
            *(float2*)(C + (size_t)row0 * ldc + coln)       = make_float2(v0, v1);
            *(float2*)(C + (size_t)(row0 + 8) * ldc + coln) = make_float2(v2, v3);
        }
    }
}

// ---------------------------------------------------------------------------
// Tensor-core flash attention (bf16 3-term, occupancy 2)
// ---------------------------------------------------------------------------
#define FSTR 72

template<int CAUSAL>
__global__ __launch_bounds__(256, 2)
void fa_kernel(const float* __restrict__ Q, int ldq,
               const float* __restrict__ Kp, int ldk,
               const float* __restrict__ Vp, int ldv,
               float* __restrict__ O, int ldo, int kvlen)
{
    __shared__ __nv_bfloat16 Kh[64 * FSTR], Kl[64 * FSTR];
    __shared__ __nv_bfloat16 Vh[64 * FSTR], Vl[64 * FSTR];

    int tid = threadIdx.x;
    int wid = tid >> 5, lane = tid & 31;
    int r   = lane >> 2;
    int cq  = (lane & 3) * 2;
    int b = blockIdx.z, h = blockIdx.y;
    int q0 = blockIdx.x * 128;
    int qrow0 = q0 + wid * 16 + r;
    int wmin  = q0 + wid * 16;
    int wmax  = wmin + 15;

    uint32_t qh[4][4], ql[4][4];
    {
        const float* qb  = Q + (size_t)(b * SS + qrow0) * ldq + h * 64;
        const float* qb8 = qb + (size_t)8 * ldq;
        #pragma unroll
        for (int ks = 0; ks < 4; ks++) {
            float2 v0 = *(const float2*)(qb  + 16 * ks + cq);
            float2 v1 = *(const float2*)(qb8 + 16 * ks + cq);
            float2 v2 = *(const float2*)(qb  + 16 * ks + cq + 8);
            float2 v3 = *(const float2*)(qb8 + 16 * ks + cq + 8);
            split2(v0.x * 0.125f, v0.y * 0.125f, qh[ks][0], ql[ks][0]);
            split2(v1.x * 0.125f, v1.y * 0.125f, qh[ks][1], ql[ks][1]);
            split2(v2.x * 0.125f, v2.y * 0.125f, qh[ks][2], ql[ks][2]);
            split2(v3.x * 0.125f, v3.y * 0.125f, qh[ks][3], ql[ks][3]);
        }
    }

    float oacc[8][4];
    #pragma unroll
    for (int nf = 0; nf < 8; nf++)
        #pragma unroll
        for (int i = 0; i < 4; i++) oacc[nf][i] = 0.f;
    float mrun0 = -INFINITY, mrun1 = -INFINITY, l0 = 0.f, l1 = 0.f;

    int ntiles = CAUSAL ? ((q0 >> 6) + 2) : (kvlen >> 6);

    int kkey = tid >> 2, kdg = (tid & 3) * 16;
    int vkp  = tid >> 3, vdg = (tid & 7) * 8;

    for (int tile = 0; tile < ntiles; tile++) {
        int t0 = tile * 64;
        __syncthreads();
        {
            const float* kr = Kp + (size_t)(b * kvlen + t0 + kkey) * ldk + h * 64 + kdg;
            float4 x0 = *(const float4*)(kr);
            float4 x1 = *(const float4*)(kr + 4);
            float4 x2 = *(const float4*)(kr + 8);
            float4 x3 = *(const float4*)(kr + 12);
            uint4 hi, lo;
            int base = kkey * FSTR + kdg;
            split8(x0, x1, hi, lo);
            *(uint4*)&Kh[base] = hi; *(uint4*)&Kl[base] = lo;
            split8(x2, x3, hi, lo);
            *(uint4*)&Kh[base + 8] = hi; *(uint4*)&Kl[base + 8] = lo;
        }
        {
            const float* v0p = Vp + (size_t)(b * kvlen + t0 + 2 * vkp) * ldv + h * 64 + vdg;
            const float* v1p = v0p + ldv;
            float xa[8], ya[8];
            *(float4*)(xa)     = *(const float4*)(v0p);
            *(float4*)(xa + 4) = *(const float4*)(v0p + 4);
            *(float4*)(ya)     = *(const float4*)(v1p);
            *(float4*)(ya + 4) = *(const float4*)(v1p + 4);
            #pragma unroll
            for (int d = 0; d < 8; d++) {
                uint32_t hi, lo;
                split2(xa[d], ya[d], hi, lo);
                int off = (vdg + d) * FSTR + 2 * vkp;
                *(uint32_t*)&Vh[off] = hi;
                *(uint32_t*)&Vl[off] = lo;
            }
        }
        __syncthreads();

        bool active = !CAUSAL || (t0 <= wmax);
        if (!active) continue;

        float sc[8][4];
        #pragma unroll
        for (int nf = 0; nf < 8; nf++)
            #pragma unroll
            for (int i = 0; i < 4; i++) sc[nf][i] = 0.f;

        #pragma unroll
        for (int ks = 0; ks < 4; ks++) {
            #pragma unroll
            for (int nf = 0; nf < 8; nf++) {
                int off = (nf * 8 + r) * FSTR + cq + 16 * ks;
                uint32_t bh[2], bl[2];
                bh[0] = *(const uint32_t*)&Kh[off];
                bh[1] = *(const uint32_t*)&Kh[off + 8];
                bl[0] = *(const uint32_t*)&Kl[off];
                bl[1] = *(const uint32_t*)&Kl[off + 8];
                mma16816(sc[nf], qh[ks], bh);
                mma16816(sc[nf], qh[ks], bl);
                mma16816(sc[nf], ql[ks], bh);
            }
        }

        if (CAUSAL && (t0 + 63 > wmin)) {
            #pragma unroll
            for (int nf = 0; nf < 8; nf++) {
                int jb = t0 + nf * 8 + cq;
                if (jb     > qrow0)     sc[nf][0] = -INFINITY;
                if (jb + 1 > qrow0)     sc[nf][1] = -INFINITY;
                if (jb     > qrow0 + 8) sc[nf][2] = -INFINITY;
                if (jb + 1 > qrow0 + 8) sc[nf][3] = -INFINITY;
            }
        }

        float mx0 = -INFINITY, mx1 = -INFINITY;
        #pragma unroll
        for (int nf = 0; nf < 8; nf++) {
            mx0 = fmaxf(mx0, fmaxf(sc[nf][0], sc[nf][1]));
            mx1 = fmaxf(mx1, fmaxf(sc[nf][2], sc[nf][3]));
        }
        mx0 = fmaxf(mx0, __shfl_xor_sync(0xffffffffu, mx0, 1));
        mx0 = fmaxf(mx0, __shfl_xor_sync(0xffffffffu, mx0, 2));
        mx1 = fmaxf(mx1, __shfl_xor_sync(0xffffffffu, mx1, 1));
        mx1 = fmaxf(mx1, __shfl_xor_sync(0xffffffffu, mx1, 2));
        float mn0 = fmaxf(mrun0, mx0), mn1 = fmaxf(mrun1, mx1);
        float c0 = __expf(mrun0 - mn0), c1 = __expf(mrun1 - mn1);
        float s0 = 0.f, s1 = 0.f;
        #pragma unroll
        for (int nf = 0; nf < 8; nf++) {
            sc[nf][0] = __expf(sc[nf][0] - mn0);
            sc[nf][1] = __expf(sc[nf][1] - mn0);
            sc[nf][2] = __expf(sc[nf][2] - mn1);
            sc[nf][3] = __expf(sc[nf][3] - mn1);
            s0 += sc[nf][0] + sc[nf][1];
            s1 += sc[nf][2] + sc[nf][3];
        }
        s0 += __shfl_xor_sync(0xffffffffu, s0, 1);
        s0 += __shfl_xor_sync(0xffffffffu, s0, 2);
        s1 += __shfl_xor_sync(0xffffffffu, s1, 1);
        s1 += __shfl_xor_sync(0xffffffffu, s1, 2);
        l0 = l0 * c0 + s0;
        l1 = l1 * c1 + s1;
        mrun0 = mn0; mrun1 = mn1;
        #pragma unroll
        for (int nf = 0; nf < 8; nf++) {
            oacc[nf][0] *= c0; oacc[nf][1] *= c0;
            oacc[nf][2] *= c1; oacc[nf][3] *= c1;
        }

        #pragma unroll
        for (int kg = 0; kg < 4; kg++) {
            uint32_t pah[4], pal[4];
            split2(sc[2 * kg][0],     sc[2 * kg][1],     pah[0], pal[0]);
            split2(sc[2 * kg][2],     sc[2 * kg][3],     pah[1], pal[1]);
            split2(sc[2 * kg + 1][0], sc[2 * kg + 1][1], pah[2], pal[2]);
            split2(sc[2 * kg + 1][2], sc[2 * kg + 1][3], pah[3], pal[3]);
            #pragma unroll
            for (int nf = 0; nf < 8; nf++) {
                int off = (nf * 8 + r) * FSTR + cq + 16 * kg;
                uint32_t bh[2], bl[2];
                bh[0] = *(const uint32_t*)&Vh[off];
                bh[1] = *(const uint32_t*)&Vh[off + 8];
                bl[0] = *(const uint32_t*)&Vl[off];
                bl[1] = *(const uint32_t*)&Vl[off + 8];
                mma16816(oacc[nf], pah, bh);
                mma16816(oacc[nf], pal, bh);
                mma16816(oacc[nf], pah, bl);
            }
        }
    }

    float inv0 = 1.0f / l0, inv1 = 1.0f / l1;
    float* ob  = O + (size_t)(b * SS + qrow0) * ldo + h * 64;
    float* ob8 = ob + (size_t)8 * ldo;
    #pragma unroll
    for (int nf = 0; nf < 8; nf++) {
        *(float2*)(ob  + nf * 8 + cq) = make_float2(oacc[nf][0] * inv0, oacc[nf][1] * inv0);
        *(float2*)(ob8 + nf * 8 + cq) = make_float2(oacc[nf][2] * inv1, oacc[nf][3] * inv1);
    }
}

// ---------------------------------------------------------------------------
// LayerNorm
// ---------------------------------------------------------------------------
__global__ __launch_bounds__(256)
void ln_kernel(const float* __restrict__ X, const float* __restrict__ gam,
               const float* __restrict__ bet, float* __restrict__ Y)
{
    int row = blockIdx.x;
    int t = threadIdx.x;
    int lane = t & 31, w = t >> 5;
    const float4* x4 = (const float4*)(X + (size_t)row * DD);
    float4 v = x4[t];
    float s  = v.x + v.y + v.z + v.w;
    float ss = v.x * v.x + v.y * v.y + v.z * v.z + v.w * v.w;
    #pragma unroll
    for (int o = 16; o > 0; o >>= 1) {
        s  += __shfl_xor_sync(0xffffffffu, s,  o);
        ss += __shfl_xor_sync(0xffffffffu, ss, o);
    }
    __shared__ float red[16];
    if (lane == 0) { red[w] = s; red[w + 8] = ss; }
    __syncthreads();
    float st = 0.f, sst = 0.f;
    #pragma unroll
    for (int i = 0; i < 8; i++) { st += red[i]; sst += red[i + 8]; }
    float mu   = st * (1.0f / DD);
    float var  = sst * (1.0f / DD) - mu * mu;
    float rstd = rsqrtf(var + 1e-5f);
    const float4* g4 = (const float4*)gam;
    const float4* b4 = (const float4*)bet;
    float4 gg = g4[t], bb = b4[t], o4;
    o4.x = (v.x - mu) * rstd * gg.x + bb.x;
    o4.y = (v.y - mu) * rstd * gg.y + bb.y;
    o4.z = (v.z - mu) * rstd * gg.z + bb.z;
    o4.w = (v.w - mu) * rstd * gg.w + bb.w;
    ((float4*)(Y + (size_t)row * DD))[t] = o4;
}

// ---------------------------------------------------------------------------
// RoPE (in-place on q,k sections of fused qkv)
// ---------------------------------------------------------------------------
__global__ __launch_bounds__(256)
void rope_kernel(float* __restrict__ qkv, const float* __restrict__ cosb,
                 const float* __restrict__ sinb)
{
    int m = blockIdx.x;
    int s = m & (SS - 1);
    int t = threadIdx.x;
    #pragma unroll
    for (int r = 0; r < 2; r++) {
        int p = t + r * 256;
        int h = p >> 5;
        int i = p & 31;
        float c  = cosb[s * 32 + i];
        float sn = sinb[s * 32 + i];
        #pragma unroll
        for (int sec = 0; sec < 2; sec++) {
            size_t base = (size_t)m * 3072 + sec * 1024 + h * 64 + 2 * i;
            float x0 = qkv[base], x1 = qkv[base + 1];
            qkv[base]     = x0 * c - x1 * sn;
            qkv[base + 1] = x0 * sn + x1 * c;
        }
    }
}

// ---------------------------------------------------------------------------
// Host orchestration
// ---------------------------------------------------------------------------
extern "C" void kernel_launch(void* const* d_in, const int* in_sizes, int n_in,
                              void* d_out, int out_size)
{
    const float* tgt      = (const float*)d_in[0];
    const float* memory   = (const float*)d_in[1];
    const float* rope_cos = (const float*)d_in[3];
    const float* rope_sin = (const float*)d_in[4];
    const float* qkv_w    = (const float*)d_in[5];
    const float* qkv_b    = (const float*)d_in[6];
    const float* out_w    = (const float*)d_in[7];
    const float* out_b    = (const float*)d_in[8];
    const float* ca_in_w  = (const float*)d_in[9];
    const float* ca_in_b  = (const float*)d_in[10];
    const float* ca_out_w = (const float*)d_in[11];
    const float* ca_out_b = (const float*)d_in[12];
    const float* ffn_w1   = (const float*)d_in[13];
    const float* ffn_b1   = (const float*)d_in[14];
    const float* ffn_w2   = (const float*)d_in[15];
    const float* ffn_b2   = (const float*)d_in[16];
    const float* ln1_g    = (const float*)d_in[17];
    const float* ln1_b    = (const float*)d_in[18];
    const float* ln2_g    = (const float*)d_in[19];
    const float* ln2_b    = (const float*)d_in[20];
    const float* ln3_g    = (const float*)d_in[21];
    const float* ln3_b    = (const float*)d_in[22];
    float* outp = (float*)d_out;

    float* S_ = nullptr;
    cudaGetSymbolAddress((void**)&S_, g_scratch);
    float* xln = S_;
    float* t1  = S_ + SZ;
    float* res = S_ + 2 * SZ;
    float* qkv = S_ + 3 * SZ;          // 4096 x 3072 (reused for CA q/kv)
    float* ffn = S_ + 6 * SZ;          // 4096 x 4096

    static bool attr_done = false;
    if (!attr_done) {
        cudaFuncSetAttribute(mma_gemm<0, false>, cudaFuncAttributeMaxDynamicSharedMemorySize, GSMEM_BYTES);
        cudaFuncSetAttribute(mma_gemm<0, true>,  cudaFuncAttributeMaxDynamicSharedMemorySize, GSMEM_BYTES);
        cudaFuncSetAttribute(mma_gemm<1, false>, cudaFuncAttributeMaxDynamicSharedMemorySize, GSMEM_BYTES);
        attr_done = true;
    }

    // ---- self-attention block ----
    ln_kernel<<<ROWS, 256>>>(tgt, ln1_g, ln1_b, xln);
    mma_gemm<0, false><<<dim3(3072 / 128, ROWS / 128), 256, GSMEM_BYTES>>>(
        xln, DD, qkv_w, DD, qkv_b, nullptr, qkv, 3072, DD);
    rope_kernel<<<ROWS, 256>>>(qkv, rope_cos, rope_sin);
    fa_kernel<1><<<dim3(SS / 128, HH, BB), 256>>>(
        qkv, 3072, qkv + 1024, 3072, qkv + 2048, 3072, t1, DD, SS);
    mma_gemm<0, true><<<dim3(DD / 128, ROWS / 128), 256, GSMEM_BYTES>>>(
        t1, DD, out_w, DD, out_b, tgt, res, DD, DD);

    // ---- cross-attention block ----
    ln_kernel<<<ROWS, 256>>>(res, ln2_g, ln2_b, xln);
    float* caq = qkv;                  // 4096 x 1024
    float* ckv = qkv + SZ;             // 1024 x 2048 (k | v)
    mma_gemm<0, false><<<dim3(DD / 128, ROWS / 128), 256, GSMEM_BYTES>>>(
        xln, DD, ca_in_w, DD, ca_in_b, nullptr, caq, DD, DD);
    mma_gemm<0, false><<<dim3(2048 / 128, (BB * MEMN) / 128), 256, GSMEM_BYTES>>>(
        memory, DD, ca_in_w + 1024 * 1024, DD, ca_in_b + 1024, nullptr,
        ckv, 2048, DD);
    fa_kernel<0><<<dim3(SS / 128, HH, BB), 256>>>(
        caq, DD, ckv, 2048, ckv + 1024, 2048, t1, DD, MEMN);
    mma_gemm<0, true><<<dim3(DD / 128, ROWS / 128), 256, GSMEM_BYTES>>>(
        t1, DD, ca_out_w, DD, ca_out_b, res, res, DD, DD);

    // ---- FFN block ----
    ln_kernel<<<ROWS, 256>>>(res, ln3_g, ln3_b, xln);
    mma_gemm<1, false><<<dim3(DFF / 128, ROWS / 128), 256, GSMEM_BYTES>>>(
        xln, DD, ffn_w1, DD, ffn_b1, nullptr, ffn, DFF, DD);
    mma_gemm<0, true><<<dim3(DD / 128, ROWS / 128), 256, GSMEM_BYTES>>>(
        ffn, DFF, ffn_w2, DFF, ffn_b2, res, outp, DD, DFF);
}

// round 9
// speedup vs baseline: 4.1910x; 1.4383x over previous
#include <cuda_runtime.h>
#include <cuda_fp16.h>
#include <math.h>
#include <stdint.h>

// ---------------------------------------------------------------------------
// Problem constants
// ---------------------------------------------------------------------------
#define BB   4
#define SS   1024
#define DD   1024
#define HH   16
#define HD   64
#define DFF  4096
#define MEMN 256
#define ROWS (BB * SS)          // 4096

#define SZ   ((size_t)ROWS * DD)        // 4M floats per slice
// fp32 slices: res(0), qkv(1-3). half buffers (8M halves per slice):
// AH(4-5) AL(6-7) FH(8-9) FL(10-11) WH(12-13)
__device__ float g_scratch[14 * SZ];
#define HM 16777216u   // 16M halves region size

// ---------------------------------------------------------------------------
// helpers
// ---------------------------------------------------------------------------
__device__ __forceinline__ uint32_t smem_u32(const void* p) {
    uint32_t a;
    asm("{ .reg .u64 t; cvta.to.shared.u64 t, %1; cvt.u32.u64 %0, t; }"
        : "=r"(a) : "l"(p));
    return a;
}
#define CPA16(dst, src) \
    asm volatile("cp.async.ca.shared.global [%0], [%1], 16;" :: "r"(dst), "l"(src))
#define CP_COMMIT() asm volatile("cp.async.commit_group;" ::: "memory")
#define CP_WAIT1()  asm volatile("cp.async.wait_group 1;"  ::: "memory")
#define CP_WAIT0()  asm volatile("cp.async.wait_group 0;"  ::: "memory")

__device__ __forceinline__ void split8h(float4 a, float4 b, uint4& hi, uint4& lo) {
    __half2 h0 = __floats2half2_rn(a.x, a.y);
    __half2 h1 = __floats2half2_rn(a.z, a.w);
    __half2 h2 = __floats2half2_rn(b.x, b.y);
    __half2 h3 = __floats2half2_rn(b.z, b.w);
    __half2 l0 = __floats2half2_rn(a.x - __low2float(h0), a.y - __high2float(h0));
    __half2 l1 = __floats2half2_rn(a.z - __low2float(h1), a.w - __high2float(h1));
    __half2 l2 = __floats2half2_rn(b.x - __low2float(h2), b.y - __high2float(h2));
    __half2 l3 = __floats2half2_rn(b.z - __low2float(h3), b.w - __high2float(h3));
    hi.x = *(uint32_t*)&h0; hi.y = *(uint32_t*)&h1; hi.z = *(uint32_t*)&h2; hi.w = *(uint32_t*)&h3;
    lo.x = *(uint32_t*)&l0; lo.y = *(uint32_t*)&l1; lo.z = *(uint32_t*)&l2; lo.w = *(uint32_t*)&l3;
}
__device__ __forceinline__ void round8h(float4 a, float4 b, uint4& hi) {
    __half2 h0 = __floats2half2_rn(a.x, a.y);
    __half2 h1 = __floats2half2_rn(a.z, a.w);
    __half2 h2 = __floats2half2_rn(b.x, b.y);
    __half2 h3 = __floats2half2_rn(b.z, b.w);
    hi.x = *(uint32_t*)&h0; hi.y = *(uint32_t*)&h1; hi.z = *(uint32_t*)&h2; hi.w = *(uint32_t*)&h3;
}
__device__ __forceinline__ void split2h(float x, float y, uint32_t& hi, uint32_t& lo) {
    __half2 h = __floats2half2_rn(x, y);
    __half2 l = __floats2half2_rn(x - __low2float(h), y - __high2float(h));
    hi = *(uint32_t*)&h; lo = *(uint32_t*)&l;
}
__device__ __forceinline__ float gelu_exact(float x) {
    return 0.5f * x * (1.0f + erff(x * 0.70710678118654752440f));
}
__device__ __forceinline__ void mma16816h(float* d, const uint32_t* a, const uint32_t* b) {
    asm volatile("mma.sync.aligned.m16n8k16.row.col.f32.f16.f16.f32 "
        "{%0,%1,%2,%3}, {%4,%5,%6,%7}, {%8,%9}, {%0,%1,%2,%3};"
        : "+f"(d[0]), "+f"(d[1]), "+f"(d[2]), "+f"(d[3])
        : "r"(a[0]), "r"(a[1]), "r"(a[2]), "r"(a[3]), "r"(b[0]), "r"(b[1]));
}

// ---------------------------------------------------------------------------
// Conversion kernels (bandwidth-bound, run once per call per tensor)
// ---------------------------------------------------------------------------
__global__ __launch_bounds__(256)
void conv_round(const float* __restrict__ in, __half* __restrict__ out) {
    int i = (blockIdx.x * 256 + threadIdx.x) * 8;
    float4 a = *(const float4*)(in + i);
    float4 b = *(const float4*)(in + i + 4);
    uint4 h;
    round8h(a, b, h);
    *(uint4*)(out + i) = h;
}
__global__ __launch_bounds__(256)
void conv_split(const float* __restrict__ in, __half* __restrict__ oh,
                __half* __restrict__ ol) {
    int i = (blockIdx.x * 256 + threadIdx.x) * 8;
    float4 a = *(const float4*)(in + i);
    float4 b = *(const float4*)(in + i + 4);
    uint4 h, l;
    split8h(a, b, h, l);
    *(uint4*)(oh + i) = h;
    *(uint4*)(ol + i) = l;
}

// ---------------------------------------------------------------------------
// Pure-fp16 mma.sync GEMM: A pre-split (hi/lo fp16), W pre-rounded fp16.
// C = A@W^T + bias (+gelu) (+residual). Output fp32 or split fp16 (OSPLIT).
// BM=BN=128, BK=32, 256 threads, cp.async double-buffered, 2 CTAs/SM.
// ---------------------------------------------------------------------------
#define TSTR 40
#define GASZ (128 * TSTR)
#define GBUF (3 * GASZ)
#define GBUFB (GBUF * 2)
#define GSMEM_BYTES (2 * GBUFB)   // 61440

template<int ACT, bool HASRES, bool OSPLIT>
__global__ __launch_bounds__(256, 2)
void mma_gemm(const __half* __restrict__ AH, const __half* __restrict__ AL,
              const __half* __restrict__ WH, int K,
              const float* __restrict__ bias, const float* __restrict__ R,
              float* __restrict__ C, __half* __restrict__ OH,
              __half* __restrict__ OL, int ldc)
{
    extern __shared__ __half dsm[];
    uint32_t sb = smem_u32(dsm);

    int tid  = threadIdx.x;
    int wid  = tid >> 5, lane = tid & 31;
    int m0   = blockIdx.y * 128, n0 = blockIdx.x * 128;

    // cp.async segment mapping: 1536 16B segments per chunk, 6 per thread
    const __half* gp[6];
    uint32_t smoff[6];
    #pragma unroll
    for (int s = 0; s < 6; s++) {
        int seg = tid + s * 256;
        int arr = seg >> 9;
        int rem = seg & 511;
        int row = rem >> 2;
        int col = (rem & 3) * 8;
        const __half* base = (arr == 0) ? AH + (size_t)(m0 + row) * K
                           : (arr == 1) ? AL + (size_t)(m0 + row) * K
                                        : WH + (size_t)(n0 + row) * K;
        gp[s] = base + col;
        smoff[s] = (uint32_t)(arr * GASZ + row * TSTR + col) * 2;
    }

    int wm = (wid & 1) * 64;
    int wn = (wid >> 1) * 32;
    int r  = lane >> 2;
    int cq = (lane & 3) * 2;

    float acc[4][4][4];
    #pragma unroll
    for (int mt = 0; mt < 4; mt++)
        #pragma unroll
        for (int nt = 0; nt < 4; nt++)
            #pragma unroll
            for (int i = 0; i < 4; i++) acc[mt][nt][i] = 0.f;

    // issue chunk 0
    #pragma unroll
    for (int s = 0; s < 6; s++) CPA16(sb + smoff[s], gp[s]);
    CP_COMMIT();

    int NC = K >> 5;
    for (int c = 0; c < NC; ++c) {
        if (c + 1 < NC) {
            uint32_t boff = (uint32_t)(((c + 1) & 1) * GBUFB);
            #pragma unroll
            for (int s = 0; s < 6; s++) CPA16(sb + boff + smoff[s], gp[s] + (c + 1) * 32);
            CP_COMMIT();
            CP_WAIT1();
        } else {
            CP_WAIT0();
        }
        __syncthreads();

        {
            const __half* Ah = dsm + (c & 1) * GBUF;
            const __half* Al = Ah + GASZ;
            const __half* Bh = Ah + 2 * GASZ;
            #pragma unroll
            for (int kh = 0; kh < 2; kh++) {
                int cc = cq + kh * 16;
                uint32_t ah[4][4], al[4][4], bh[4][2];
                #pragma unroll
                for (int mt = 0; mt < 4; mt++) {
                    int rb = (wm + mt * 16 + r) * TSTR;
                    int rb8 = rb + 8 * TSTR;
                    ah[mt][0] = *(const uint32_t*)&Ah[rb + cc];
                    ah[mt][1] = *(const uint32_t*)&Ah[rb8 + cc];
                    ah[mt][2] = *(const uint32_t*)&Ah[rb + cc + 8];
                    ah[mt][3] = *(const uint32_t*)&Ah[rb8 + cc + 8];
                    al[mt][0] = *(const uint32_t*)&Al[rb + cc];
                    al[mt][1] = *(const uint32_t*)&Al[rb8 + cc];
                    al[mt][2] = *(const uint32_t*)&Al[rb + cc + 8];
                    al[mt][3] = *(const uint32_t*)&Al[rb8 + cc + 8];
                }
                #pragma unroll
                for (int nt = 0; nt < 4; nt++) {
                    int nb = (wn + nt * 8 + r) * TSTR;
                    bh[nt][0] = *(const uint32_t*)&Bh[nb + cc];
                    bh[nt][1] = *(const uint32_t*)&Bh[nb + cc + 8];
                }
                #pragma unroll
                for (int mt = 0; mt < 4; mt++)
                    #pragma unroll
                    for (int nt = 0; nt < 4; nt++) {
                        mma16816h(acc[mt][nt], ah[mt], bh[nt]);
                        mma16816h(acc[mt][nt], al[mt], bh[nt]);
                    }
            }
        }
        __syncthreads();
    }

    #pragma unroll
    for (int mt = 0; mt < 4; mt++) {
        int row0 = m0 + wm + mt * 16 + r;
        #pragma unroll
        for (int nt = 0; nt < 4; nt++) {
            int coln = n0 + wn + nt * 8 + cq;
            float2 bv = *(const float2*)(bias + coln);
            float v0 = acc[mt][nt][0] + bv.x;
            float v1 = acc[mt][nt][1] + bv.y;
            float v2 = acc[mt][nt][2] + bv.x;
            float v3 = acc[mt][nt][3] + bv.y;
            if (ACT == 1) {
                v0 = gelu_exact(v0); v1 = gelu_exact(v1);
                v2 = gelu_exact(v2); v3 = gelu_exact(v3);
            }
            if (HASRES) {
                float2 r0 = *(const float2*)(R + (size_t)row0 * ldc + coln);
                float2 r1 = *(const float2*)(R + (size_t)(row0 + 8) * ldc + coln);
                v0 += r0.x; v1 += r0.y; v2 += r1.x; v3 += r1.y;
            }
            if (OSPLIT) {
                uint32_t h, l;
                split2h(v0, v1, h, l);
                *(uint32_t*)(OH + (size_t)row0 * ldc + coln) = h;
                *(uint32_t*)(OL + (size_t)row0 * ldc + coln) = l;
                split2h(v2, v3, h, l);
                *(uint32_t*)(OH + (size_t)(row0 + 8) * ldc + coln) = h;
                *(uint32_t*)(OL + (size_t)(row0 + 8) * ldc + coln) = l;
            } else {
                *(float2*)(C + (size_t)row0 * ldc + coln)       = make_float2(v0, v1);
                *(float2*)(C + (size_t)(row0 + 8) * ldc + coln) = make_float2(v2, v3);
            }
        }
    }
}

// ---------------------------------------------------------------------------
// fp16 2-term flash attention. Q/P split hi/lo (exact), K/V rounded fp16.
// Writes output directly as split fp16 (feeds the next GEMM).
// ---------------------------------------------------------------------------
#define FSTR 72

template<int CAUSAL>
__global__ __launch_bounds__(256, 2)
void fa_kernel(const float* __restrict__ Q, int ldq,
               const float* __restrict__ Kp, int ldk,
               const float* __restrict__ Vp, int ldv,
               __half* __restrict__ OH, __half* __restrict__ OL,
               int ldo, int kvlen)
{
    __shared__ __half Kv[64 * FSTR];
    __shared__ __half Vv[64 * FSTR];

    int tid = threadIdx.x;
    int wid = tid >> 5, lane = tid & 31;
    int r   = lane >> 2;
    int cq  = (lane & 3) * 2;
    int b = blockIdx.z, h = blockIdx.y;
    int q0 = blockIdx.x * 128;
    int qrow0 = q0 + wid * 16 + r;
    int wmin  = q0 + wid * 16;
    int wmax  = wmin + 15;

    uint32_t qh[4][4], ql[4][4];
    {
        const float* qb  = Q + (size_t)(b * SS + qrow0) * ldq + h * 64;
        const float* qb8 = qb + (size_t)8 * ldq;
        #pragma unroll
        for (int ks = 0; ks < 4; ks++) {
            float2 v0 = *(const float2*)(qb  + 16 * ks + cq);
            float2 v1 = *(const float2*)(qb8 + 16 * ks + cq);
            float2 v2 = *(const float2*)(qb  + 16 * ks + cq + 8);
            float2 v3 = *(const float2*)(qb8 + 16 * ks + cq + 8);
            split2h(v0.x * 0.125f, v0.y * 0.125f, qh[ks][0], ql[ks][0]);
            split2h(v1.x * 0.125f, v1.y * 0.125f, qh[ks][1], ql[ks][1]);
            split2h(v2.x * 0.125f, v2.y * 0.125f, qh[ks][2], ql[ks][2]);
            split2h(v3.x * 0.125f, v3.y * 0.125f, qh[ks][3], ql[ks][3]);
        }
    }

    float oacc[8][4];
    #pragma unroll
    for (int nf = 0; nf < 8; nf++)
        #pragma unroll
        for (int i = 0; i < 4; i++) oacc[nf][i] = 0.f;
    float mrun0 = -INFINITY, mrun1 = -INFINITY, l0 = 0.f, l1 = 0.f;

    int ntiles = CAUSAL ? ((q0 >> 6) + 2) : (kvlen >> 6);

    int kkey = tid >> 2, kdg = (tid & 3) * 16;
    int vkp  = tid >> 3, vdg = (tid & 7) * 8;

    for (int tile = 0; tile < ntiles; tile++) {
        int t0 = tile * 64;
        __syncthreads();
        {
            const float* kr = Kp + (size_t)(b * kvlen + t0 + kkey) * ldk + h * 64 + kdg;
            float4 x0 = *(const float4*)(kr);
            float4 x1 = *(const float4*)(kr + 4);
            float4 x2 = *(const float4*)(kr + 8);
            float4 x3 = *(const float4*)(kr + 12);
            uint4 hv;
            int base = kkey * FSTR + kdg;
            round8h(x0, x1, hv);
            *(uint4*)&Kv[base] = hv;
            round8h(x2, x3, hv);
            *(uint4*)&Kv[base + 8] = hv;
        }
        {
            const float* v0p = Vp + (size_t)(b * kvlen + t0 + 2 * vkp) * ldv + h * 64 + vdg;
            const float* v1p = v0p + ldv;
            float xa[8], ya[8];
            *(float4*)(xa)     = *(const float4*)(v0p);
            *(float4*)(xa + 4) = *(const float4*)(v0p + 4);
            *(float4*)(ya)     = *(const float4*)(v1p);
            *(float4*)(ya + 4) = *(const float4*)(v1p + 4);
            #pragma unroll
            for (int d = 0; d < 8; d++) {
                __half2 hv = __floats2half2_rn(xa[d], ya[d]);
                *(uint32_t*)&Vv[(vdg + d) * FSTR + 2 * vkp] = *(uint32_t*)&hv;
            }
        }
        __syncthreads();

        bool active = !CAUSAL || (t0 <= wmax);
        if (!active) continue;

        float sc[8][4];
        #pragma unroll
        for (int nf = 0; nf < 8; nf++)
            #pragma unroll
            for (int i = 0; i < 4; i++) sc[nf][i] = 0.f;

        #pragma unroll
        for (int ks = 0; ks < 4; ks++) {
            #pragma unroll
            for (int nf = 0; nf < 8; nf++) {
                int off = (nf * 8 + r) * FSTR + cq + 16 * ks;
                uint32_t bh[2];
                bh[0] = *(const uint32_t*)&Kv[off];
                bh[1] = *(const uint32_t*)&Kv[off + 8];
                mma16816h(sc[nf], qh[ks], bh);
                mma16816h(sc[nf], ql[ks], bh);
            }
        }

        if (CAUSAL && (t0 + 63 > wmin)) {
            #pragma unroll
            for (int nf = 0; nf < 8; nf++) {
                int jb = t0 + nf * 8 + cq;
                if (jb     > qrow0)     sc[nf][0] = -INFINITY;
                if (jb + 1 > qrow0)     sc[nf][1] = -INFINITY;
                if (jb     > qrow0 + 8) sc[nf][2] = -INFINITY;
                if (jb + 1 > qrow0 + 8) sc[nf][3] = -INFINITY;
            }
        }

        float mx0 = -INFINITY, mx1 = -INFINITY;
        #pragma unroll
        for (int nf = 0; nf < 8; nf++) {
            mx0 = fmaxf(mx0, fmaxf(sc[nf][0], sc[nf][1]));
            mx1 = fmaxf(mx1, fmaxf(sc[nf][2], sc[nf][3]));
        }
        mx0 = fmaxf(mx0, __shfl_xor_sync(0xffffffffu, mx0, 1));
        mx0 = fmaxf(mx0, __shfl_xor_sync(0xffffffffu, mx0, 2));
        mx1 = fmaxf(mx1, __shfl_xor_sync(0xffffffffu, mx1, 1));
        mx1 = fmaxf(mx1, __shfl_xor_sync(0xffffffffu, mx1, 2));
        float mn0 = fmaxf(mrun0, mx0), mn1 = fmaxf(mrun1, mx1);
        float c0 = __expf(mrun0 - mn0), c1 = __expf(mrun1 - mn1);
        float s0 = 0.f, s1 = 0.f;
        #pragma unroll
        for (int nf = 0; nf < 8; nf++) {
            sc[nf][0] = __expf(sc[nf][0] - mn0);
            sc[nf][1] = __expf(sc[nf][1] - mn0);
            sc[nf][2] = __expf(sc[nf][2] - mn1);
            sc[nf][3] = __expf(sc[nf][3] - mn1);
            s0 += sc[nf][0] + sc[nf][1];
            s1 += sc[nf][2] + sc[nf][3];
        }
        s0 += __shfl_xor_sync(0xffffffffu, s0, 1);
        s0 += __shfl_xor_sync(0xffffffffu, s0, 2);
        s1 += __shfl_xor_sync(0xffffffffu, s1, 1);
        s1 += __shfl_xor_sync(0xffffffffu, s1, 2);
        l0 = l0 * c0 + s0;
        l1 = l1 * c1 + s1;
        mrun0 = mn0; mrun1 = mn1;
        #pragma unroll
        for (int nf = 0; nf < 8; nf++) {
            oacc[nf][0] *= c0; oacc[nf][1] *= c0;
            oacc[nf][2] *= c1; oacc[nf][3] *= c1;
        }

        #pragma unroll
        for (int kg = 0; kg < 4; kg++) {
            uint32_t pah[4], pal[4];
            split2h(sc[2 * kg][0],     sc[2 * kg][1],     pah[0], pal[0]);
            split2h(sc[2 * kg][2],     sc[2 * kg][3],     pah[1], pal[1]);
            split2h(sc[2 * kg + 1][0], sc[2 * kg + 1][1], pah[2], pal[2]);
            split2h(sc[2 * kg + 1][2], sc[2 * kg + 1][3], pah[3], pal[3]);
            #pragma unroll
            for (int nf = 0; nf < 8; nf++) {
                int off = (nf * 8 + r) * FSTR + cq + 16 * kg;
                uint32_t bh[2];
                bh[0] = *(const uint32_t*)&Vv[off];
                bh[1] = *(const uint32_t*)&Vv[off + 8];
                mma16816h(oacc[nf], pah, bh);
                mma16816h(oacc[nf], pal, bh);
            }
        }
    }

    float inv0 = 1.0f / l0, inv1 = 1.0f / l1;
    size_t ob  = (size_t)(b * SS + qrow0) * ldo + h * 64;
    size_t ob8 = ob + (size_t)8 * ldo;
    #pragma unroll
    for (int nf = 0; nf < 8; nf++) {
        uint32_t h0, l0b, h1, l1b;
        split2h(oacc[nf][0] * inv0, oacc[nf][1] * inv0, h0, l0b);
        split2h(oacc[nf][2] * inv1, oacc[nf][3] * inv1, h1, l1b);
        *(uint32_t*)(OH + ob  + nf * 8 + cq) = h0;
        *(uint32_t*)(OL + ob  + nf * 8 + cq) = l0b;
        *(uint32_t*)(OH + ob8 + nf * 8 + cq) = h1;
        *(uint32_t*)(OL + ob8 + nf * 8 + cq) = l1b;
    }
}

// ---------------------------------------------------------------------------
// LayerNorm with fused fp16 hi/lo output
// ---------------------------------------------------------------------------
__global__ __launch_bounds__(256)
void ln_split_kernel(const float* __restrict__ X, const float* __restrict__ gam,
                     const float* __restrict__ bet,
                     __half* __restrict__ OH, __half* __restrict__ OL)
{
    int row = blockIdx.x;
    int t = threadIdx.x;
    int lane = t & 31, w = t >> 5;
    const float4* x4 = (const float4*)(X + (size_t)row * DD);
    float4 v = x4[t];
    float s  = v.x + v.y + v.z + v.w;
    float ss = v.x * v.x + v.y * v.y + v.z * v.z + v.w * v.w;
    #pragma unroll
    for (int o = 16; o > 0; o >>= 1) {
        s  += __shfl_xor_sync(0xffffffffu, s,  o);
        ss += __shfl_xor_sync(0xffffffffu, ss, o);
    }
    __shared__ float red[16];
    if (lane == 0) { red[w] = s; red[w + 8] = ss; }
    __syncthreads();
    float st = 0.f, sst = 0.f;
    #pragma unroll
    for (int i = 0; i < 8; i++) { st += red[i]; sst += red[i + 8]; }
    float mu   = st * (1.0f / DD);
    float var  = sst * (1.0f / DD) - mu * mu;
    float rstd = rsqrtf(var + 1e-5f);
    const float4* g4 = (const float4*)gam;
    const float4* b4 = (const float4*)bet;
    float4 gg = g4[t], bb = b4[t], o4;
    o4.x = (v.x - mu) * rstd * gg.x + bb.x;
    o4.y = (v.y - mu) * rstd * gg.y + bb.y;
    o4.z = (v.z - mu) * rstd * gg.z + bb.z;
    o4.w = (v.w - mu) * rstd * gg.w + bb.w;
    uint32_t h0, l0, h1, l1;
    split2h(o4.x, o4.y, h0, l0);
    split2h(o4.z, o4.w, h1, l1);
    size_t off = (size_t)row * DD + t * 4;
    *(uint2*)(OH + off) = make_uint2(h0, h1);
    *(uint2*)(OL + off) = make_uint2(l0, l1);
}

// ---------------------------------------------------------------------------
// RoPE (in-place on q,k sections of fused qkv)
// ---------------------------------------------------------------------------
__global__ __launch_bounds__(256)
void rope_kernel(float* __restrict__ qkv, const float* __restrict__ cosb,
                 const float* __restrict__ sinb)
{
    int m = blockIdx.x;
    int s = m & (SS - 1);
    int t = threadIdx.x;
    #pragma unroll
    for (int r = 0; r < 2; r++) {
        int p = t + r * 256;
        int h = p >> 5;
        int i = p & 31;
        float c  = cosb[s * 32 + i];
        float sn = sinb[s * 32 + i];
        #pragma unroll
        for (int sec = 0; sec < 2; sec++) {
            size_t base = (size_t)m * 3072 + sec * 1024 + h * 64 + 2 * i;
            float x0 = qkv[base], x1 = qkv[base + 1];
            qkv[base]     = x0 * c - x1 * sn;
            qkv[base + 1] = x0 * sn + x1 * c;
        }
    }
}

// ---------------------------------------------------------------------------
// Host orchestration
// ---------------------------------------------------------------------------
extern "C" void kernel_launch(void* const* d_in, const int* in_sizes, int n_in,
                              void* d_out, int out_size)
{
    const float* tgt      = (const float*)d_in[0];
    const float* memory   = (const float*)d_in[1];
    const float* rope_cos = (const float*)d_in[3];
    const float* rope_sin = (const float*)d_in[4];
    const float* qkv_w    = (const float*)d_in[5];
    const float* qkv_b    = (const float*)d_in[6];
    const float* out_w    = (const float*)d_in[7];
    const float* out_b    = (const float*)d_in[8];
    const float* ca_in_w  = (const float*)d_in[9];
    const float* ca_in_b  = (const float*)d_in[10];
    const float* ca_out_w = (const float*)d_in[11];
    const float* ca_out_b = (const float*)d_in[12];
    const float* ffn_w1   = (const float*)d_in[13];
    const float* ffn_b1   = (const float*)d_in[14];
    const float* ffn_w2   = (const float*)d_in[15];
    const float* ffn_b2   = (const float*)d_in[16];
    const float* ln1_g    = (const float*)d_in[17];
    const float* ln1_b    = (const float*)d_in[18];
    const float* ln2_g    = (const float*)d_in[19];
    const float* ln2_b    = (const float*)d_in[20];
    const float* ln3_g    = (const float*)d_in[21];
    const float* ln3_b    = (const float*)d_in[22];
    float* outp = (float*)d_out;

    float* S_ = nullptr;
    cudaGetSymbolAddress((void**)&S_, g_scratch);
    float*  res = S_;                       // slice 0
    float*  qkv = S_ + SZ;                  // slices 1-3 (4096x3072)
    float*  caq = qkv;                      // reuse: 4096x1024
    float*  ckv = qkv + SZ;                 // 1024x2048
    __half* hb  = (__half*)(S_ + 4 * SZ);
    __half* AH  = hb;                       // 16M halves
    __half* AL  = hb + HM;
    __half* FH  = hb + 2 * HM;
    __half* FL  = hb + 3 * HM;
    __half* WHb = hb + 4 * HM;
    __half* w_qkv  = WHb;
    __half* w_out  = WHb + 3145728;
    __half* w_caq  = WHb + 4194304;
    __half* w_cakv = WHb + 5242880;
    __half* w_caout= WHb + 7340032;
    __half* w_ffn1 = WHb + 8388608;
    __half* w_ffn2 = WHb + 12582912;

    static bool attr_done = false;
    if (!attr_done) {
        cudaFuncSetAttribute(mma_gemm<0, false, false>, cudaFuncAttributeMaxDynamicSharedMemorySize, GSMEM_BYTES);
        cudaFuncSetAttribute(mma_gemm<0, true,  false>, cudaFuncAttributeMaxDynamicSharedMemorySize, GSMEM_BYTES);
        cudaFuncSetAttribute(mma_gemm<1, false, true>,  cudaFuncAttributeMaxDynamicSharedMemorySize, GSMEM_BYTES);
        attr_done = true;
    }

    // ---- one-time conversions (weights + memory) ----
    conv_round<<<1536, 256>>>(qkv_w,  w_qkv);
    conv_round<<<512,  256>>>(out_w,  w_out);
    conv_round<<<512,  256>>>(ca_in_w, w_caq);
    conv_round<<<1024, 256>>>(ca_in_w + 1024 * 1024, w_cakv);
    conv_round<<<512,  256>>>(ca_out_w, w_caout);
    conv_round<<<2048, 256>>>(ffn_w1, w_ffn1);
    conv_round<<<2048, 256>>>(ffn_w2, w_ffn2);
    conv_split<<<512,  256>>>(memory, FH, FL);

    // ---- self-attention block ----
    ln_split_kernel<<<ROWS, 256>>>(tgt, ln1_g, ln1_b, AH, AL);
    mma_gemm<0, false, false><<<dim3(24, 32), 256, GSMEM_BYTES>>>(
        AH, AL, w_qkv, DD, qkv_b, nullptr, qkv, nullptr, nullptr, 3072);
    rope_kernel<<<ROWS, 256>>>(qkv, rope_cos, rope_sin);
    fa_kernel<1><<<dim3(SS / 128, HH, BB), 256>>>(
        qkv, 3072, qkv + 1024, 3072, qkv + 2048, 3072, AH, AL, DD, SS);
    mma_gemm<0, true, false><<<dim3(8, 32), 256, GSMEM_BYTES>>>(
        AH, AL, w_out, DD, out_b, tgt, res, nullptr, nullptr, DD);

    // ---- cross-attention block ----
    ln_split_kernel<<<ROWS, 256>>>(res, ln2_g, ln2_b, AH, AL);
    mma_gemm<0, false, false><<<dim3(8, 32), 256, GSMEM_BYTES>>>(
        AH, AL, w_caq, DD, ca_in_b, nullptr, caq, nullptr, nullptr, DD);
    mma_gemm<0, false, false><<<dim3(16, 8), 256, GSMEM_BYTES>>>(
        FH, FL, w_cakv, DD, ca_in_b + 1024, nullptr, ckv, nullptr, nullptr, 2048);
    fa_kernel<0><<<dim3(SS / 128, HH, BB), 256>>>(
        caq, DD, ckv, 2048, ckv + 1024, 2048, AH, AL, DD, MEMN);
    mma_gemm<0, true, false><<<dim3(8, 32), 256, GSMEM_BYTES>>>(
        AH, AL, w_caout, DD, ca_out_b, res, res, nullptr, nullptr, DD);

    // ---- FFN block ----
    ln_split_kernel<<<ROWS, 256>>>(res, ln3_g, ln3_b, AH, AL);
    mma_gemm<1, false, true><<<dim3(32, 32), 256, GSMEM_BYTES>>>(
        AH, AL, w_ffn1, DD, ffn_b1, nullptr, nullptr, FH, FL, DFF);
    mma_gemm<0, true, false><<<dim3(8, 32), 256, GSMEM_BYTES>>>(
        FH, FL, w_ffn2, DFF, ffn_b2, res, outp, nullptr, nullptr, DD);
}

// round 10
// speedup vs baseline: 6.3758x; 1.5213x over previous
#include <cuda_runtime.h>
#include <cuda_fp16.h>
#include <math.h>
#include <stdint.h>

// ---------------------------------------------------------------------------
// Problem constants
// ---------------------------------------------------------------------------
#define BB   4
#define SS   1024
#define DD   1024
#define HH   16
#define HD   64
#define DFF  4096
#define MEMN 256
#define ROWS (BB * SS)          // 4096

#define SZ   ((size_t)ROWS * DD)        // 4M floats per slice
__device__ float g_scratch[14 * SZ];
#define HM 16777216u   // 16M halves region size

// ---------------------------------------------------------------------------
// helpers
// ---------------------------------------------------------------------------
__device__ __forceinline__ uint32_t smem_u32(const void* p) {
    uint32_t a;
    asm("{ .reg .u64 t; cvta.to.shared.u64 t, %1; cvt.u32.u64 %0, t; }"
        : "=r"(a) : "l"(p));
    return a;
}
#define CPA16(dst, src) \
    asm volatile("cp.async.ca.shared.global [%0], [%1], 16;" :: "r"(dst), "l"(src))
#define CP_COMMIT() asm volatile("cp.async.commit_group;" ::: "memory")
#define CP_WAIT1()  asm volatile("cp.async.wait_group 1;"  ::: "memory")
#define CP_WAIT0()  asm volatile("cp.async.wait_group 0;"  ::: "memory")

__device__ __forceinline__ void round8h(float4 a, float4 b, uint4& hi) {
    __half2 h0 = __floats2half2_rn(a.x, a.y);
    __half2 h1 = __floats2half2_rn(a.z, a.w);
    __half2 h2 = __floats2half2_rn(b.x, b.y);
    __half2 h3 = __floats2half2_rn(b.z, b.w);
    hi.x = *(uint32_t*)&h0; hi.y = *(uint32_t*)&h1; hi.z = *(uint32_t*)&h2; hi.w = *(uint32_t*)&h3;
}
__device__ __forceinline__ uint32_t pack2h(float x, float y) {
    __half2 h = __floats2half2_rn(x, y);
    return *(uint32_t*)&h;
}
__device__ __forceinline__ float gelu_exact(float x) {
    return 0.5f * x * (1.0f + erff(x * 0.70710678118654752440f));
}
__device__ __forceinline__ void mma16816h(float* d, const uint32_t* a, const uint32_t* b) {
    asm volatile("mma.sync.aligned.m16n8k16.row.col.f32.f16.f16.f32 "
        "{%0,%1,%2,%3}, {%4,%5,%6,%7}, {%8,%9}, {%0,%1,%2,%3};"
        : "+f"(d[0]), "+f"(d[1]), "+f"(d[2]), "+f"(d[3])
        : "r"(a[0]), "r"(a[1]), "r"(a[2]), "r"(a[3]), "r"(b[0]), "r"(b[1]));
}

// ---------------------------------------------------------------------------
// Conversion kernel (bandwidth-bound, once per tensor per call)
// ---------------------------------------------------------------------------
__global__ __launch_bounds__(256)
void conv_round(const float* __restrict__ in, __half* __restrict__ out) {
    int i = (blockIdx.x * 256 + threadIdx.x) * 8;
    float4 a = *(const float4*)(in + i);
    float4 b = *(const float4*)(in + i + 4);
    uint4 h;
    round8h(a, b, h);
    *(uint4*)(out + i) = h;
}

// ---------------------------------------------------------------------------
// Plain fp16 mma.sync GEMM (A and W both pre-rounded fp16, fp32 accumulate).
// C = A@W^T + bias (+gelu) (+residual). Output fp32 or rounded fp16 (OHALF).
// BM=BN=128, BK=32, 256 threads, cp.async double-buffered, 2 CTAs/SM.
// ---------------------------------------------------------------------------
#define TSTR 40
#define GASZ (128 * TSTR)
#define GBUF (2 * GASZ)
#define GBUFB (GBUF * 2)
#define GSMEM_BYTES (2 * GBUFB)   // 40960

template<int ACT, bool HASRES, bool OHALF>
__global__ __launch_bounds__(256, 2)
void mma_gemm(const __half* __restrict__ AH, const __half* __restrict__ WH,
              int K, const float* __restrict__ bias, const float* __restrict__ R,
              float* __restrict__ C, __half* __restrict__ OH, int ldc)
{
    extern __shared__ __half dsm[];
    uint32_t sb = smem_u32(dsm);

    int tid  = threadIdx.x;
    int wid  = tid >> 5, lane = tid & 31;
    int m0   = blockIdx.y * 128, n0 = blockIdx.x * 128;

    // cp.async segment mapping: 1024 16B segments per chunk, 4 per thread
    const __half* gp[4];
    uint32_t smoff[4];
    #pragma unroll
    for (int s = 0; s < 4; s++) {
        int seg = tid + s * 256;
        int arr = seg >> 9;                 // 0 = A, 1 = W
        int rem = seg & 511;
        int row = rem >> 2;
        int col = (rem & 3) * 8;
        const __half* base = (arr == 0) ? AH + (size_t)(m0 + row) * K
                                        : WH + (size_t)(n0 + row) * K;
        gp[s] = base + col;
        smoff[s] = (uint32_t)(arr * GASZ + row * TSTR + col) * 2;
    }

    int wm = (wid & 1) * 64;
    int wn = (wid >> 1) * 32;
    int r  = lane >> 2;
    int cq = (lane & 3) * 2;

    float acc[4][4][4];
    #pragma unroll
    for (int mt = 0; mt < 4; mt++)
        #pragma unroll
        for (int nt = 0; nt < 4; nt++)
            #pragma unroll
            for (int i = 0; i < 4; i++) acc[mt][nt][i] = 0.f;

    #pragma unroll
    for (int s = 0; s < 4; s++) CPA16(sb + smoff[s], gp[s]);
    CP_COMMIT();

    int NC = K >> 5;
    for (int c = 0; c < NC; ++c) {
        if (c + 1 < NC) {
            uint32_t boff = (uint32_t)(((c + 1) & 1) * GBUFB);
            #pragma unroll
            for (int s = 0; s < 4; s++) CPA16(sb + boff + smoff[s], gp[s] + (c + 1) * 32);
            CP_COMMIT();
            CP_WAIT1();
        } else {
            CP_WAIT0();
        }
        __syncthreads();

        {
            const __half* Ah = dsm + (c & 1) * GBUF;
            const __half* Bh = Ah + GASZ;
            #pragma unroll
            for (int kh = 0; kh < 2; kh++) {
                int cc = cq + kh * 16;
                uint32_t ah[4][4], bh[4][2];
                #pragma unroll
                for (int mt = 0; mt < 4; mt++) {
                    int rb = (wm + mt * 16 + r) * TSTR;
                    int rb8 = rb + 8 * TSTR;
                    ah[mt][0] = *(const uint32_t*)&Ah[rb + cc];
                    ah[mt][1] = *(const uint32_t*)&Ah[rb8 + cc];
                    ah[mt][2] = *(const uint32_t*)&Ah[rb + cc + 8];
                    ah[mt][3] = *(const uint32_t*)&Ah[rb8 + cc + 8];
                }
                #pragma unroll
                for (int nt = 0; nt < 4; nt++) {
                    int nb = (wn + nt * 8 + r) * TSTR;
                    bh[nt][0] = *(const uint32_t*)&Bh[nb + cc];
                    bh[nt][1] = *(const uint32_t*)&Bh[nb + cc + 8];
                }
                #pragma unroll
                for (int mt = 0; mt < 4; mt++)
                    #pragma unroll
                    for (int nt = 0; nt < 4; nt++)
                        mma16816h(acc[mt][nt], ah[mt], bh[nt]);
            }
        }
        __syncthreads();
    }

    #pragma unroll
    for (int mt = 0; mt < 4; mt++) {
        int row0 = m0 + wm + mt * 16 + r;
        #pragma unroll
        for (int nt = 0; nt < 4; nt++) {
            int coln = n0 + wn + nt * 8 + cq;
            float2 bv = *(const float2*)(bias + coln);
            float v0 = acc[mt][nt][0] + bv.x;
            float v1 = acc[mt][nt][1] + bv.y;
            float v2 = acc[mt][nt][2] + bv.x;
            float v3 = acc[mt][nt][3] + bv.y;
            if (ACT == 1) {
                v0 = gelu_exact(v0); v1 = gelu_exact(v1);
                v2 = gelu_exact(v2); v3 = gelu_exact(v3);
            }
            if (HASRES) {
                float2 r0 = *(const float2*)(R + (size_t)row0 * ldc + coln);
                float2 r1 = *(const float2*)(R + (size_t)(row0 + 8) * ldc + coln);
                v0 += r0.x; v1 += r0.y; v2 += r1.x; v3 += r1.y;
            }
            if (OHALF) {
                *(uint32_t*)(OH + (size_t)row0 * ldc + coln)       = pack2h(v0, v1);
                *(uint32_t*)(OH + (size_t)(row0 + 8) * ldc + coln) = pack2h(v2, v3);
            } else {
                *(float2*)(C + (size_t)row0 * ldc + coln)       = make_float2(v0, v1);
                *(float2*)(C + (size_t)(row0 + 8) * ldc + coln) = make_float2(v2, v3);
            }
        }
    }
}

// ---------------------------------------------------------------------------
// Plain fp16 flash attention (Q/K/V/P rounded fp16, fp32 softmax + accum).
// Writes output directly as fp16 (feeds the next GEMM).
// ---------------------------------------------------------------------------
#define FSTR 72

template<int CAUSAL>
__global__ __launch_bounds__(256, 2)
void fa_kernel(const float* __restrict__ Q, int ldq,
               const float* __restrict__ Kp, int ldk,
               const float* __restrict__ Vp, int ldv,
               __half* __restrict__ OH, int ldo, int kvlen)
{
    __shared__ __half Kv[64 * FSTR];
    __shared__ __half Vv[64 * FSTR];

    int tid = threadIdx.x;
    int wid = tid >> 5, lane = tid & 31;
    int r   = lane >> 2;
    int cq  = (lane & 3) * 2;
    int b = blockIdx.z, h = blockIdx.y;
    int q0 = blockIdx.x * 128;
    int qrow0 = q0 + wid * 16 + r;
    int wmin  = q0 + wid * 16;
    int wmax  = wmin + 15;

    uint32_t qh[4][4];
    {
        const float* qb  = Q + (size_t)(b * SS + qrow0) * ldq + h * 64;
        const float* qb8 = qb + (size_t)8 * ldq;
        #pragma unroll
        for (int ks = 0; ks < 4; ks++) {
            float2 v0 = *(const float2*)(qb  + 16 * ks + cq);
            float2 v1 = *(const float2*)(qb8 + 16 * ks + cq);
            float2 v2 = *(const float2*)(qb  + 16 * ks + cq + 8);
            float2 v3 = *(const float2*)(qb8 + 16 * ks + cq + 8);
            qh[ks][0] = pack2h(v0.x * 0.125f, v0.y * 0.125f);
            qh[ks][1] = pack2h(v1.x * 0.125f, v1.y * 0.125f);
            qh[ks][2] = pack2h(v2.x * 0.125f, v2.y * 0.125f);
            qh[ks][3] = pack2h(v3.x * 0.125f, v3.y * 0.125f);
        }
    }

    float oacc[8][4];
    #pragma unroll
    for (int nf = 0; nf < 8; nf++)
        #pragma unroll
        for (int i = 0; i < 4; i++) oacc[nf][i] = 0.f;
    float mrun0 = -INFINITY, mrun1 = -INFINITY, l0 = 0.f, l1 = 0.f;

    int ntiles = CAUSAL ? ((q0 >> 6) + 2) : (kvlen >> 6);

    int kkey = tid >> 2, kdg = (tid & 3) * 16;
    int vkp  = tid >> 3, vdg = (tid & 7) * 8;

    for (int tile = 0; tile < ntiles; tile++) {
        int t0 = tile * 64;
        __syncthreads();
        {
            const float* kr = Kp + (size_t)(b * kvlen + t0 + kkey) * ldk + h * 64 + kdg;
            float4 x0 = *(const float4*)(kr);
            float4 x1 = *(const float4*)(kr + 4);
            float4 x2 = *(const float4*)(kr + 8);
            float4 x3 = *(const float4*)(kr + 12);
            uint4 hv;
            int base = kkey * FSTR + kdg;
            round8h(x0, x1, hv);
            *(uint4*)&Kv[base] = hv;
            round8h(x2, x3, hv);
            *(uint4*)&Kv[base + 8] = hv;
        }
        {
            const float* v0p = Vp + (size_t)(b * kvlen + t0 + 2 * vkp) * ldv + h * 64 + vdg;
            const float* v1p = v0p + ldv;
            float xa[8], ya[8];
            *(float4*)(xa)     = *(const float4*)(v0p);
            *(float4*)(xa + 4) = *(const float4*)(v0p + 4);
            *(float4*)(ya)     = *(const float4*)(v1p);
            *(float4*)(ya + 4) = *(const float4*)(v1p + 4);
            #pragma unroll
            for (int d = 0; d < 8; d++)
                *(uint32_t*)&Vv[(vdg + d) * FSTR + 2 * vkp] = pack2h(xa[d], ya[d]);
        }
        __syncthreads();

        bool active = !CAUSAL || (t0 <= wmax);
        if (!active) continue;

        float sc[8][4];
        #pragma unroll
        for (int nf = 0; nf < 8; nf++)
            #pragma unroll
            for (int i = 0; i < 4; i++) sc[nf][i] = 0.f;

        #pragma unroll
        for (int ks = 0; ks < 4; ks++) {
            #pragma unroll
            for (int nf = 0; nf < 8; nf++) {
                int off = (nf * 8 + r) * FSTR + cq + 16 * ks;
                uint32_t bh[2];
                bh[0] = *(const uint32_t*)&Kv[off];
                bh[1] = *(const uint32_t*)&Kv[off + 8];
                mma16816h(sc[nf], qh[ks], bh);
            }
        }

        if (CAUSAL && (t0 + 63 > wmin)) {
            #pragma unroll
            for (int nf = 0; nf < 8; nf++) {
                int jb = t0 + nf * 8 + cq;
                if (jb     > qrow0)     sc[nf][0] = -INFINITY;
                if (jb + 1 > qrow0)     sc[nf][1] = -INFINITY;
                if (jb     > qrow0 + 8) sc[nf][2] = -INFINITY;
                if (jb + 1 > qrow0 + 8) sc[nf][3] = -INFINITY;
            }
        }

        float mx0 = -INFINITY, mx1 = -INFINITY;
        #pragma unroll
        for (int nf = 0; nf < 8; nf++) {
            mx0 = fmaxf(mx0, fmaxf(sc[nf][0], sc[nf][1]));
            mx1 = fmaxf(mx1, fmaxf(sc[nf][2], sc[nf][3]));
        }
        mx0 = fmaxf(mx0, __shfl_xor_sync(0xffffffffu, mx0, 1));
        mx0 = fmaxf(mx0, __shfl_xor_sync(0xffffffffu, mx0, 2));
        mx1 = fmaxf(mx1, __shfl_xor_sync(0xffffffffu, mx1, 1));
        mx1 = fmaxf(mx1, __shfl_xor_sync(0xffffffffu, mx1, 2));
        float mn0 = fmaxf(mrun0, mx0), mn1 = fmaxf(mrun1, mx1);
        float c0 = __expf(mrun0 - mn0), c1 = __expf(mrun1 - mn1);
        float s0 = 0.f, s1 = 0.f;
        #pragma unroll
        for (int nf = 0; nf < 8; nf++) {
            sc[nf][0] = __expf(sc[nf][0] - mn0);
            sc[nf][1] = __expf(sc[nf][1] - mn0);
            sc[nf][2] = __expf(sc[nf][2] - mn1);
            sc[nf][3] = __expf(sc[nf][3] - mn1);
            s0 += sc[nf][0] + sc[nf][1];
            s1 += sc[nf][2] + sc[nf][3];
        }
        s0 += __shfl_xor_sync(0xffffffffu, s0, 1);
        s0 += __shfl_xor_sync(0xffffffffu, s0, 2);
        s1 += __shfl_xor_sync(0xffffffffu, s1, 1);
        s1 += __shfl_xor_sync(0xffffffffu, s1, 2);
        l0 = l0 * c0 + s0;
        l1 = l1 * c1 + s1;
        mrun0 = mn0; mrun1 = mn1;
        #pragma unroll
        for (int nf = 0; nf < 8; nf++) {
            oacc[nf][0] *= c0; oacc[nf][1] *= c0;
            oacc[nf][2] *= c1; oacc[nf][3] *= c1;
        }

        #pragma unroll
        for (int kg = 0; kg < 4; kg++) {
            uint32_t pah[4];
            pah[0] = pack2h(sc[2 * kg][0],     sc[2 * kg][1]);
            pah[1] = pack2h(sc[2 * kg][2],     sc[2 * kg][3]);
            pah[2] = pack2h(sc[2 * kg + 1][0], sc[2 * kg + 1][1]);
            pah[3] = pack2h(sc[2 * kg + 1][2], sc[2 * kg + 1][3]);
            #pragma unroll
            for (int nf = 0; nf < 8; nf++) {
                int off = (nf * 8 + r) * FSTR + cq + 16 * kg;
                uint32_t bh[2];
                bh[0] = *(const uint32_t*)&Vv[off];
                bh[1] = *(const uint32_t*)&Vv[off + 8];
                mma16816h(oacc[nf], pah, bh);
            }
        }
    }

    float inv0 = 1.0f / l0, inv1 = 1.0f / l1;
    size_t ob  = (size_t)(b * SS + qrow0) * ldo + h * 64;
    size_t ob8 = ob + (size_t)8 * ldo;
    #pragma unroll
    for (int nf = 0; nf < 8; nf++) {
        *(uint32_t*)(OH + ob  + nf * 8 + cq) = pack2h(oacc[nf][0] * inv0, oacc[nf][1] * inv0);
        *(uint32_t*)(OH + ob8 + nf * 8 + cq) = pack2h(oacc[nf][2] * inv1, oacc[nf][3] * inv1);
    }
}

// ---------------------------------------------------------------------------
// LayerNorm with fused fp16 output
// ---------------------------------------------------------------------------
__global__ __launch_bounds__(256)
void ln_round_kernel(const float* __restrict__ X, const float* __restrict__ gam,
                     const float* __restrict__ bet, __half* __restrict__ OH)
{
    int row = blockIdx.x;
    int t = threadIdx.x;
    int lane = t & 31, w = t >> 5;
    const float4* x4 = (const float4*)(X + (size_t)row * DD);
    float4 v = x4[t];
    float s  = v.x + v.y + v.z + v.w;
    float ss = v.x * v.x + v.y * v.y + v.z * v.z + v.w * v.w;
    #pragma unroll
    for (int o = 16; o > 0; o >>= 1) {
        s  += __shfl_xor_sync(0xffffffffu, s,  o);
        ss += __shfl_xor_sync(0xffffffffu, ss, o);
    }
    __shared__ float red[16];
    if (lane == 0) { red[w] = s; red[w + 8] = ss; }
    __syncthreads();
    float st = 0.f, sst = 0.f;
    #pragma unroll
    for (int i = 0; i < 8; i++) { st += red[i]; sst += red[i + 8]; }
    float mu   = st * (1.0f / DD);
    float var  = sst * (1.0f / DD) - mu * mu;
    float rstd = rsqrtf(var + 1e-5f);
    const float4* g4 = (const float4*)gam;
    const float4* b4 = (const float4*)bet;
    float4 gg = g4[t], bb = b4[t], o4;
    o4.x = (v.x - mu) * rstd * gg.x + bb.x;
    o4.y = (v.y - mu) * rstd * gg.y + bb.y;
    o4.z = (v.z - mu) * rstd * gg.z + bb.z;
    o4.w = (v.w - mu) * rstd * gg.w + bb.w;
    size_t off = (size_t)row * DD + t * 4;
    *(uint2*)(OH + off) = make_uint2(pack2h(o4.x, o4.y), pack2h(o4.z, o4.w));
}

// ---------------------------------------------------------------------------
// RoPE (in-place on q,k sections of fused qkv)
// ---------------------------------------------------------------------------
__global__ __launch_bounds__(256)
void rope_kernel(float* __restrict__ qkv, const float* __restrict__ cosb,
                 const float* __restrict__ sinb)
{
    int m = blockIdx.x;
    int s = m & (SS - 1);
    int t = threadIdx.x;
    #pragma unroll
    for (int r = 0; r < 2; r++) {
        int p = t + r * 256;
        int h = p >> 5;
        int i = p & 31;
        float c  = cosb[s * 32 + i];
        float sn = sinb[s * 32 + i];
        #pragma unroll
        for (int sec = 0; sec < 2; sec++) {
            size_t base = (size_t)m * 3072 + sec * 1024 + h * 64 + 2 * i;
            float x0 = qkv[base], x1 = qkv[base + 1];
            qkv[base]     = x0 * c - x1 * sn;
            qkv[base + 1] = x0 * sn + x1 * c;
        }
    }
}

// ---------------------------------------------------------------------------
// Host orchestration
// ---------------------------------------------------------------------------
extern "C" void kernel_launch(void* const* d_in, const int* in_sizes, int n_in,
                              void* d_out, int out_size)
{
    const float* tgt      = (const float*)d_in[0];
    const float* memory   = (const float*)d_in[1];
    const float* rope_cos = (const float*)d_in[3];
    const float* rope_sin = (const float*)d_in[4];
    const float* qkv_w    = (const float*)d_in[5];
    const float* qkv_b    = (const float*)d_in[6];
    const float* out_w    = (const float*)d_in[7];
    const float* out_b    = (const float*)d_in[8];
    const float* ca_in_w  = (const float*)d_in[9];
    const float* ca_in_b  = (const float*)d_in[10];
    const float* ca_out_w = (const float*)d_in[11];
    const float* ca_out_b = (const float*)d_in[12];
    const float* ffn_w1   = (const float*)d_in[13];
    const float* ffn_b1   = (const float*)d_in[14];
    const float* ffn_w2   = (const float*)d_in[15];
    const float* ffn_b2   = (const float*)d_in[16];
    const float* ln1_g    = (const float*)d_in[17];
    const float* ln1_b    = (const float*)d_in[18];
    const float* ln2_g    = (const float*)d_in[19];
    const float* ln2_b    = (const float*)d_in[20];
    const float* ln3_g    = (const float*)d_in[21];
    const float* ln3_b    = (const float*)d_in[22];
    float* outp = (float*)d_out;

    float* S_ = nullptr;
    cudaGetSymbolAddress((void**)&S_, g_scratch);
    float*  res = S_;                       // slice 0
    float*  qkv = S_ + SZ;                  // slices 1-3 (4096x3072)
    float*  caq = qkv;                      // reuse: 4096x1024
    float*  ckv = qkv + SZ;                 // 1024x2048
    __half* hb  = (__half*)(S_ + 4 * SZ);
    __half* AH  = hb;                       // activations (rounded fp16)
    __half* FH  = hb + HM;                  // ffn hidden (4096x4096 halves)
    __half* MH  = hb + 2 * HM;              // memory halves
    __half* WHb = hb + 3 * HM;
    __half* w_qkv  = WHb;
    __half* w_out  = WHb + 3145728;
    __half* w_cain = WHb + 4194304;
    __half* w_caout= WHb + 7340032;
    __half* w_ffn1 = WHb + 8388608;
    __half* w_ffn2 = WHb + 12582912;

    static bool attr_done = false;
    if (!attr_done) {
        cudaFuncSetAttribute(mma_gemm<0, false, false>, cudaFuncAttributeMaxDynamicSharedMemorySize, GSMEM_BYTES);
        cudaFuncSetAttribute(mma_gemm<0, true,  false>, cudaFuncAttributeMaxDynamicSharedMemorySize, GSMEM_BYTES);
        cudaFuncSetAttribute(mma_gemm<1, false, true>,  cudaFuncAttributeMaxDynamicSharedMemorySize, GSMEM_BYTES);
        attr_done = true;
    }

    // ---- one-time conversions (weights + memory) ----
    conv_round<<<1536, 256>>>(qkv_w,  w_qkv);
    conv_round<<<512,  256>>>(out_w,  w_out);
    conv_round<<<1536, 256>>>(ca_in_w, w_cain);
    conv_round<<<512,  256>>>(ca_out_w, w_caout);
    conv_round<<<2048, 256>>>(ffn_w1, w_ffn1);
    conv_round<<<2048, 256>>>(ffn_w2, w_ffn2);
    conv_round<<<512,  256>>>(memory, MH);

    // ---- self-attention block ----
    ln_round_kernel<<<ROWS, 256>>>(tgt, ln1_g, ln1_b, AH);
    mma_gemm<0, false, false><<<dim3(24, 32), 256, GSMEM_BYTES>>>(
        AH, w_qkv, DD, qkv_b, nullptr, qkv, nullptr, 3072);
    rope_kernel<<<ROWS, 256>>>(qkv, rope_cos, rope_sin);
    fa_kernel<1><<<dim3(SS / 128, HH, BB), 256>>>(
        qkv, 3072, qkv + 1024, 3072, qkv + 2048, 3072, AH, DD, SS);
    mma_gemm<0, true, false><<<dim3(8, 32), 256, GSMEM_BYTES>>>(
        AH, w_out, DD, out_b, tgt, res, nullptr, DD);

    // ---- cross-attention block ----
    ln_round_kernel<<<ROWS, 256>>>(res, ln2_g, ln2_b, AH);
    mma_gemm<0, false, false><<<dim3(8, 32), 256, GSMEM_BYTES>>>(
        AH, w_cain, DD, ca_in_b, nullptr, caq, nullptr, DD);
    mma_gemm<0, false, false><<<dim3(16, 8), 256, GSMEM_BYTES>>>(
        MH, w_cain + 1048576, DD, ca_in_b + 1024, nullptr, ckv, nullptr, 2048);
    fa_kernel<0><<<dim3(SS / 128, HH, BB), 256>>>(
        caq, DD, ckv, 2048, ckv + 1024, 2048, AH, DD, MEMN);
    mma_gemm<0, true, false><<<dim3(8, 32), 256, GSMEM_BYTES>>>(
        AH, w_caout, DD, ca_out_b, res, res, nullptr, DD);

    // ---- FFN block ----
    ln_round_kernel<<<ROWS, 256>>>(res, ln3_g, ln3_b, AH);
    mma_gemm<1, false, true><<<dim3(32, 32), 256, GSMEM_BYTES>>>(
        AH, w_ffn1, DD, ffn_b1, nullptr, nullptr, FH, DFF);
    mma_gemm<0, true, false><<<dim3(8, 32), 256, GSMEM_BYTES>>>(
        FH, w_ffn2, DFF, ffn_b2, res, outp, nullptr, DD);
}

// round 11
// speedup vs baseline: 6.5079x; 1.0207x over previous
#include <cuda_runtime.h>
#include <cuda_fp16.h>
#include <math.h>
#include <stdint.h>

// ---------------------------------------------------------------------------
// Problem constants
// ---------------------------------------------------------------------------
#define BB   4
#define SS   1024
#define DD   1024
#define HH   16
#define HD   64
#define DFF  4096
#define MEMN 256
#define ROWS (BB * SS)          // 4096

#define SZ   ((size_t)ROWS * DD)        // 4M floats per slice
__device__ float g_scratch[14 * SZ];

// ---------------------------------------------------------------------------
// helpers
// ---------------------------------------------------------------------------
__device__ __forceinline__ uint32_t smem_u32(const void* p) {
    uint32_t a;
    asm("{ .reg .u64 t; cvta.to.shared.u64 t, %1; cvt.u32.u64 %0, t; }"
        : "=r"(a) : "l"(p));
    return a;
}
#define CPA16(dst, src) \
    asm volatile("cp.async.ca.shared.global [%0], [%1], 16;" :: "r"(dst), "l"(src))
#define CP_COMMIT() asm volatile("cp.async.commit_group;" ::: "memory")
#define CP_WAIT1()  asm volatile("cp.async.wait_group 1;"  ::: "memory")
#define CP_WAIT0()  asm volatile("cp.async.wait_group 0;"  ::: "memory")

__device__ __forceinline__ void round8h(float4 a, float4 b, uint4& hi) {
    __half2 h0 = __floats2half2_rn(a.x, a.y);
    __half2 h1 = __floats2half2_rn(a.z, a.w);
    __half2 h2 = __floats2half2_rn(b.x, b.y);
    __half2 h3 = __floats2half2_rn(b.z, b.w);
    hi.x = *(uint32_t*)&h0; hi.y = *(uint32_t*)&h1; hi.z = *(uint32_t*)&h2; hi.w = *(uint32_t*)&h3;
}
__device__ __forceinline__ uint32_t pack2h(float x, float y) {
    __half2 h = __floats2half2_rn(x, y);
    return *(uint32_t*)&h;
}
__device__ __forceinline__ float gelu_exact(float x) {
    return 0.5f * x * (1.0f + erff(x * 0.70710678118654752440f));
}
__device__ __forceinline__ void mma16816h(float* d, const uint32_t* a, const uint32_t* b) {
    asm volatile("mma.sync.aligned.m16n8k16.row.col.f32.f16.f16.f32 "
        "{%0,%1,%2,%3}, {%4,%5,%6,%7}, {%8,%9}, {%0,%1,%2,%3};"
        : "+f"(d[0]), "+f"(d[1]), "+f"(d[2]), "+f"(d[3])
        : "r"(a[0]), "r"(a[1]), "r"(a[2]), "r"(a[3]), "r"(b[0]), "r"(b[1]));
}

// ---------------------------------------------------------------------------
// Merged conversion kernel: 7 segments (6 weights + memory), one launch.
// ---------------------------------------------------------------------------
struct ConvArgs {
    const float* src[7];
    __half* dst[7];
    int start[8];        // cumulative block starts
};
__global__ __launch_bounds__(256)
void conv_all(ConvArgs a) {
    int blk = blockIdx.x;
    int s = 0;
    #pragma unroll
    for (int k = 1; k < 7; k++) if (blk >= a.start[k]) s = k;
    int i = (blk - a.start[s]) * 2048 + threadIdx.x * 8;
    const float* in = a.src[s];
    float4 x = *(const float4*)(in + i);
    float4 y = *(const float4*)(in + i + 4);
    uint4 h;
    round8h(x, y, h);
    *(uint4*)(a.dst[s] + i) = h;
}

// ---------------------------------------------------------------------------
// Plain fp16 mma.sync GEMM (A and W both fp16, fp32 accumulate).
// C = A@W^T + bias (+gelu) (+residual). Output fp32 or rounded fp16 (OHALF).
// BM=BN=128, BK=32, 256 threads, cp.async double-buffered, 2 CTAs/SM.
// ---------------------------------------------------------------------------
#define TSTR 40
#define GASZ (128 * TSTR)
#define GBUF (2 * GASZ)
#define GBUFB (GBUF * 2)
#define GSMEM_BYTES (2 * GBUFB)   // 40960

template<int ACT, bool HASRES, bool OHALF>
__global__ __launch_bounds__(256, 2)
void mma_gemm(const __half* __restrict__ AH, const __half* __restrict__ WH,
              int K, const float* __restrict__ bias, const float* __restrict__ R,
              float* __restrict__ C, __half* __restrict__ OH, int ldc)
{
    extern __shared__ __half dsm[];
    uint32_t sb = smem_u32(dsm);

    int tid  = threadIdx.x;
    int wid  = tid >> 5, lane = tid & 31;
    int m0   = blockIdx.y * 128, n0 = blockIdx.x * 128;

    const __half* gp[4];
    uint32_t smoff[4];
    #pragma unroll
    for (int s = 0; s < 4; s++) {
        int seg = tid + s * 256;
        int arr = seg >> 9;
        int rem = seg & 511;
        int row = rem >> 2;
        int col = (rem & 3) * 8;
        const __half* base = (arr == 0) ? AH + (size_t)(m0 + row) * K
                                        : WH + (size_t)(n0 + row) * K;
        gp[s] = base + col;
        smoff[s] = (uint32_t)(arr * GASZ + row * TSTR + col) * 2;
    }

    int wm = (wid & 1) * 64;
    int wn = (wid >> 1) * 32;
    int r  = lane >> 2;
    int cq = (lane & 3) * 2;

    float acc[4][4][4];
    #pragma unroll
    for (int mt = 0; mt < 4; mt++)
        #pragma unroll
        for (int nt = 0; nt < 4; nt++)
            #pragma unroll
            for (int i = 0; i < 4; i++) acc[mt][nt][i] = 0.f;

    #pragma unroll
    for (int s = 0; s < 4; s++) CPA16(sb + smoff[s], gp[s]);
    CP_COMMIT();

    int NC = K >> 5;
    for (int c = 0; c < NC; ++c) {
        if (c + 1 < NC) {
            uint32_t boff = (uint32_t)(((c + 1) & 1) * GBUFB);
            #pragma unroll
            for (int s = 0; s < 4; s++) CPA16(sb + boff + smoff[s], gp[s] + (c + 1) * 32);
            CP_COMMIT();
            CP_WAIT1();
        } else {
            CP_WAIT0();
        }
        __syncthreads();

        {
            const __half* Ah = dsm + (c & 1) * GBUF;
            const __half* Bh = Ah + GASZ;
            #pragma unroll
            for (int kh = 0; kh < 2; kh++) {
                int cc = cq + kh * 16;
                uint32_t ah[4][4], bh[4][2];
                #pragma unroll
                for (int mt = 0; mt < 4; mt++) {
                    int rb = (wm + mt * 16 + r) * TSTR;
                    int rb8 = rb + 8 * TSTR;
                    ah[mt][0] = *(const uint32_t*)&Ah[rb + cc];
                    ah[mt][1] = *(const uint32_t*)&Ah[rb8 + cc];
                    ah[mt][2] = *(const uint32_t*)&Ah[rb + cc + 8];
                    ah[mt][3] = *(const uint32_t*)&Ah[rb8 + cc + 8];
                }
                #pragma unroll
                for (int nt = 0; nt < 4; nt++) {
                    int nb = (wn + nt * 8 + r) * TSTR;
                    bh[nt][0] = *(const uint32_t*)&Bh[nb + cc];
                    bh[nt][1] = *(const uint32_t*)&Bh[nb + cc + 8];
                }
                #pragma unroll
                for (int mt = 0; mt < 4; mt++)
                    #pragma unroll
                    for (int nt = 0; nt < 4; nt++)
                        mma16816h(acc[mt][nt], ah[mt], bh[nt]);
            }
        }
        __syncthreads();
    }

    #pragma unroll
    for (int mt = 0; mt < 4; mt++) {
        int row0 = m0 + wm + mt * 16 + r;
        #pragma unroll
        for (int nt = 0; nt < 4; nt++) {
            int coln = n0 + wn + nt * 8 + cq;
            float2 bv = *(const float2*)(bias + coln);
            float v0 = acc[mt][nt][0] + bv.x;
            float v1 = acc[mt][nt][1] + bv.y;
            float v2 = acc[mt][nt][2] + bv.x;
            float v3 = acc[mt][nt][3] + bv.y;
            if (ACT == 1) {
                v0 = gelu_exact(v0); v1 = gelu_exact(v1);
                v2 = gelu_exact(v2); v3 = gelu_exact(v3);
            }
            if (HASRES) {
                float2 r0 = *(const float2*)(R + (size_t)row0 * ldc + coln);
                float2 r1 = *(const float2*)(R + (size_t)(row0 + 8) * ldc + coln);
                v0 += r0.x; v1 += r0.y; v2 += r1.x; v3 += r1.y;
            }
            if (OHALF) {
                *(uint32_t*)(OH + (size_t)row0 * ldc + coln)       = pack2h(v0, v1);
                *(uint32_t*)(OH + (size_t)(row0 + 8) * ldc + coln) = pack2h(v2, v3);
            } else {
                *(float2*)(C + (size_t)row0 * ldc + coln)       = make_float2(v0, v1);
                *(float2*)(C + (size_t)(row0 + 8) * ldc + coln) = make_float2(v2, v3);
            }
        }
    }
}

// ---------------------------------------------------------------------------
// fp16 flash attention with fused RoPE (applied to Q fragments and K tiles
// at load). All fp16 inputs/outputs; fp32 softmax + accumulation.
// ---------------------------------------------------------------------------
#define FSTR 72

template<int CAUSAL, int ROPE>
__global__ __launch_bounds__(256, 2)
void fa_kernel(const __half* __restrict__ Q, int ldq,
               const __half* __restrict__ Kp, int ldk,
               const __half* __restrict__ Vp, int ldv,
               __half* __restrict__ OH, int ldo, int kvlen,
               const float* __restrict__ cosb, const float* __restrict__ sinb)
{
    __shared__ __half Kv[64 * FSTR];
    __shared__ __half Vv[64 * FSTR];

    int tid = threadIdx.x;
    int wid = tid >> 5, lane = tid & 31;
    int r   = lane >> 2;
    int cq  = (lane & 3) * 2;
    int b = blockIdx.z, h = blockIdx.y;
    int q0 = blockIdx.x * 128;
    int qrow0 = q0 + wid * 16 + r;
    int wmin  = q0 + wid * 16;
    int wmax  = wmin + 15;

    uint32_t qh[4][4];
    {
        const __half* qb  = Q + (size_t)(b * SS + qrow0) * ldq + h * 64;
        const __half* qb8 = qb + (size_t)8 * ldq;
        #pragma unroll
        for (int ks = 0; ks < 4; ks++) {
            float2 f0 = __half22float2(*(const __half2*)(qb  + 16 * ks + cq));
            float2 f1 = __half22float2(*(const __half2*)(qb8 + 16 * ks + cq));
            float2 f2 = __half22float2(*(const __half2*)(qb  + 16 * ks + cq + 8));
            float2 f3 = __half22float2(*(const __half2*)(qb8 + 16 * ks + cq + 8));
            if (ROPE) {
                int i0 = (16 * ks + cq) >> 1;
                int i1 = i0 + 4;
                float c0 = cosb[qrow0 * 32 + i0],       s0 = sinb[qrow0 * 32 + i0];
                float c8 = cosb[(qrow0 + 8) * 32 + i0], s8 = sinb[(qrow0 + 8) * 32 + i0];
                float c1 = cosb[qrow0 * 32 + i1],       s1 = sinb[qrow0 * 32 + i1];
                float c9 = cosb[(qrow0 + 8) * 32 + i1], s9 = sinb[(qrow0 + 8) * 32 + i1];
                f0 = make_float2(f0.x * c0 - f0.y * s0, f0.x * s0 + f0.y * c0);
                f1 = make_float2(f1.x * c8 - f1.y * s8, f1.x * s8 + f1.y * c8);
                f2 = make_float2(f2.x * c1 - f2.y * s1, f2.x * s1 + f2.y * c1);
                f3 = make_float2(f3.x * c9 - f3.y * s9, f3.x * s9 + f3.y * c9);
            }
            qh[ks][0] = pack2h(f0.x * 0.125f, f0.y * 0.125f);
            qh[ks][1] = pack2h(f1.x * 0.125f, f1.y * 0.125f);
            qh[ks][2] = pack2h(f2.x * 0.125f, f2.y * 0.125f);
            qh[ks][3] = pack2h(f3.x * 0.125f, f3.y * 0.125f);
        }
    }

    float oacc[8][4];
    #pragma unroll
    for (int nf = 0; nf < 8; nf++)
        #pragma unroll
        for (int i = 0; i < 4; i++) oacc[nf][i] = 0.f;
    float mrun0 = -INFINITY, mrun1 = -INFINITY, l0 = 0.f, l1 = 0.f;

    int ntiles = CAUSAL ? ((q0 >> 6) + 2) : (kvlen >> 6);

    int kkey = tid >> 2, kdg = (tid & 3) * 16;
    int vkp  = tid >> 3, vdg = (tid & 7) * 8;

    for (int tile = 0; tile < ntiles; tile++) {
        int t0 = tile * 64;
        __syncthreads();
        {   // K tile (optionally with rope)
            const __half* kr = Kp + (size_t)(b * kvlen + t0 + kkey) * ldk + h * 64 + kdg;
            uint4 p0 = *(const uint4*)(kr);
            uint4 p1 = *(const uint4*)(kr + 8);
            int base = kkey * FSTR + kdg;
            if (ROPE) {
                int s = t0 + kkey;
                const float* cb = cosb + s * 32 + (kdg >> 1);
                const float* sb = sinb + s * 32 + (kdg >> 1);
                uint32_t o[8];
                #pragma unroll
                for (int j = 0; j < 4; j++) {
                    float2 f = __half22float2(((const __half2*)&p0)[j]);
                    float c = cb[j], sn = sb[j];
                    o[j] = pack2h(f.x * c - f.y * sn, f.x * sn + f.y * c);
                }
                #pragma unroll
                for (int j = 0; j < 4; j++) {
                    float2 f = __half22float2(((const __half2*)&p1)[j]);
                    float c = cb[4 + j], sn = sb[4 + j];
                    o[4 + j] = pack2h(f.x * c - f.y * sn, f.x * sn + f.y * c);
                }
                *(uint4*)&Kv[base]     = *(uint4*)&o[0];
                *(uint4*)&Kv[base + 8] = *(uint4*)&o[4];
            } else {
                *(uint4*)&Kv[base]     = p0;
                *(uint4*)&Kv[base + 8] = p1;
            }
        }
        {   // V tile transposed [dim][key]
            const __half* v0p = Vp + (size_t)(b * kvlen + t0 + 2 * vkp) * ldv + h * 64 + vdg;
            const __half* v1p = v0p + ldv;
            uint4 pa = *(const uint4*)v0p;
            uint4 pb = *(const uint4*)v1p;
            #pragma unroll
            for (int j = 0; j < 4; j++) {
                __half2 ha = ((const __half2*)&pa)[j];
                __half2 hb = ((const __half2*)&pb)[j];
                __half2 lo = __halves2half2(__low2half(ha),  __low2half(hb));
                __half2 hi = __halves2half2(__high2half(ha), __high2half(hb));
                *(uint32_t*)&Vv[(vdg + 2 * j)     * FSTR + 2 * vkp] = *(uint32_t*)&lo;
                *(uint32_t*)&Vv[(vdg + 2 * j + 1) * FSTR + 2 * vkp] = *(uint32_t*)&hi;
            }
        }
        __syncthreads();

        bool active = !CAUSAL || (t0 <= wmax);
        if (!active) continue;

        float sc[8][4];
        #pragma unroll
        for (int nf = 0; nf < 8; nf++)
            #pragma unroll
            for (int i = 0; i < 4; i++) sc[nf][i] = 0.f;

        #pragma unroll
        for (int ks = 0; ks < 4; ks++) {
            #pragma unroll
            for (int nf = 0; nf < 8; nf++) {
                int off = (nf * 8 + r) * FSTR + cq + 16 * ks;
                uint32_t bh[2];
                bh[0] = *(const uint32_t*)&Kv[off];
                bh[1] = *(const uint32_t*)&Kv[off + 8];
                mma16816h(sc[nf], qh[ks], bh);
            }
        }

        if (CAUSAL && (t0 + 63 > wmin)) {
            #pragma unroll
            for (int nf = 0; nf < 8; nf++) {
                int jb = t0 + nf * 8 + cq;
                if (jb     > qrow0)     sc[nf][0] = -INFINITY;
                if (jb + 1 > qrow0)     sc[nf][1] = -INFINITY;
                if (jb     > qrow0 + 8) sc[nf][2] = -INFINITY;
                if (jb + 1 > qrow0 + 8) sc[nf][3] = -INFINITY;
            }
        }

        float mx0 = -INFINITY, mx1 = -INFINITY;
        #pragma unroll
        for (int nf = 0; nf < 8; nf++) {
            mx0 = fmaxf(mx0, fmaxf(sc[nf][0], sc[nf][1]));
            mx1 = fmaxf(mx1, fmaxf(sc[nf][2], sc[nf][3]));
        }
        mx0 = fmaxf(mx0, __shfl_xor_sync(0xffffffffu, mx0, 1));
        mx0 = fmaxf(mx0, __shfl_xor_sync(0xffffffffu, mx0, 2));
        mx1 = fmaxf(mx1, __shfl_xor_sync(0xffffffffu, mx1, 1));
        mx1 = fmaxf(mx1, __shfl_xor_sync(0xffffffffu, mx1, 2));
        float mn0 = fmaxf(mrun0, mx0), mn1 = fmaxf(mrun1, mx1);
        float c0 = __expf(mrun0 - mn0), c1 = __expf(mrun1 - mn1);
        float s0 = 0.f, s1 = 0.f;
        #pragma unroll
        for (int nf = 0; nf < 8; nf++) {
            sc[nf][0] = __expf(sc[nf][0] - mn0);
            sc[nf][1] = __expf(sc[nf][1] - mn0);
            sc[nf][2] = __expf(sc[nf][2] - mn1);
            sc[nf][3] = __expf(sc[nf][3] - mn1);
            s0 += sc[nf][0] + sc[nf][1];
            s1 += sc[nf][2] + sc[nf][3];
        }
        s0 += __shfl_xor_sync(0xffffffffu, s0, 1);
        s0 += __shfl_xor_sync(0xffffffffu, s0, 2);
        s1 += __shfl_xor_sync(0xffffffffu, s1, 1);
        s1 += __shfl_xor_sync(0xffffffffu, s1, 2);
        l0 = l0 * c0 + s0;
        l1 = l1 * c1 + s1;
        mrun0 = mn0; mrun1 = mn1;
        #pragma unroll
        for (int nf = 0; nf < 8; nf++) {
            oacc[nf][0] *= c0; oacc[nf][1] *= c0;
            oacc[nf][2] *= c1; oacc[nf][3] *= c1;
        }

        #pragma unroll
        for (int kg = 0; kg < 4; kg++) {
            uint32_t pah[4];
            pah[0] = pack2h(sc[2 * kg][0],     sc[2 * kg][1]);
            pah[1] = pack2h(sc[2 * kg][2],     sc[2 * kg][3]);
            pah[2] = pack2h(sc[2 * kg + 1][0], sc[2 * kg + 1][1]);
            pah[3] = pack2h(sc[2 * kg + 1][2], sc[2 * kg + 1][3]);
            #pragma unroll
            for (int nf = 0; nf < 8; nf++) {
                int off = (nf * 8 + r) * FSTR + cq + 16 * kg;
                uint32_t bh[2];
                bh[0] = *(const uint32_t*)&Vv[off];
                bh[1] = *(const uint32_t*)&Vv[off + 8];
                mma16816h(oacc[nf], pah, bh);
            }
        }
    }

    float inv0 = 1.0f / l0, inv1 = 1.0f / l1;
    size_t ob  = (size_t)(b * SS + qrow0) * ldo + h * 64;
    size_t ob8 = ob + (size_t)8 * ldo;
    #pragma unroll
    for (int nf = 0; nf < 8; nf++) {
        *(uint32_t*)(OH + ob  + nf * 8 + cq) = pack2h(oacc[nf][0] * inv0, oacc[nf][1] * inv0);
        *(uint32_t*)(OH + ob8 + nf * 8 + cq) = pack2h(oacc[nf][2] * inv1, oacc[nf][3] * inv1);
    }
}

// ---------------------------------------------------------------------------
// LayerNorm with fused fp16 output
// ---------------------------------------------------------------------------
__global__ __launch_bounds__(256)
void ln_round_kernel(const float* __restrict__ X, const float* __restrict__ gam,
                     const float* __restrict__ bet, __half* __restrict__ OH)
{
    int row = blockIdx.x;
    int t = threadIdx.x;
    int lane = t & 31, w = t >> 5;
    const float4* x4 = (const float4*)(X + (size_t)row * DD);
    float4 v = x4[t];
    float s  = v.x + v.y + v.z + v.w;
    float ss = v.x * v.x + v.y * v.y + v.z * v.z + v.w * v.w;
    #pragma unroll
    for (int o = 16; o > 0; o >>= 1) {
        s  += __shfl_xor_sync(0xffffffffu, s,  o);
        ss += __shfl_xor_sync(0xffffffffu, ss, o);
    }
    __shared__ float red[16];
    if (lane == 0) { red[w] = s; red[w + 8] = ss; }
    __syncthreads();
    float st = 0.f, sst = 0.f;
    #pragma unroll
    for (int i = 0; i < 8; i++) { st += red[i]; sst += red[i + 8]; }
    float mu   = st * (1.0f / DD);
    float var  = sst * (1.0f / DD) - mu * mu;
    float rstd = rsqrtf(var + 1e-5f);
    const float4* g4 = (const float4*)gam;
    const float4* b4 = (const float4*)bet;
    float4 gg = g4[t], bb = b4[t], o4;
    o4.x = (v.x - mu) * rstd * gg.x + bb.x;
    o4.y = (v.y - mu) * rstd * gg.y + bb.y;
    o4.z = (v.z - mu) * rstd * gg.z + bb.z;
    o4.w = (v.w - mu) * rstd * gg.w + bb.w;
    size_t off = (size_t)row * DD + t * 4;
    *(uint2*)(OH + off) = make_uint2(pack2h(o4.x, o4.y), pack2h(o4.z, o4.w));
}

// ---------------------------------------------------------------------------
// Host orchestration
// ---------------------------------------------------------------------------
extern "C" void kernel_launch(void* const* d_in, const int* in_sizes, int n_in,
                              void* d_out, int out_size)
{
    const float* tgt      = (const float*)d_in[0];
    const float* memory   = (const float*)d_in[1];
    const float* rope_cos = (const float*)d_in[3];
    const float* rope_sin = (const float*)d_in[4];
    const float* qkv_w    = (const float*)d_in[5];
    const float* qkv_b    = (const float*)d_in[6];
    const float* out_w    = (const float*)d_in[7];
    const float* out_b    = (const float*)d_in[8];
    const float* ca_in_w  = (const float*)d_in[9];
    const float* ca_in_b  = (const float*)d_in[10];
    const float* ca_out_w = (const float*)d_in[11];
    const float* ca_out_b = (const float*)d_in[12];
    const float* ffn_w1   = (const float*)d_in[13];
    const float* ffn_b1   = (const float*)d_in[14];
    const float* ffn_w2   = (const float*)d_in[15];
    const float* ffn_b2   = (const float*)d_in[16];
    const float* ln1_g    = (const float*)d_in[17];
    const float* ln1_b    = (const float*)d_in[18];
    const float* ln2_g    = (const float*)d_in[19];
    const float* ln2_b    = (const float*)d_in[20];
    const float* ln3_g    = (const float*)d_in[21];
    const float* ln3_b    = (const float*)d_in[22];
    float* outp = (float*)d_out;

    float* S_ = nullptr;
    cudaGetSymbolAddress((void**)&S_, g_scratch);
    float*  res = S_;                         // fp32 slice 0
    __half* hb  = (__half*)(S_ + SZ);
    __half* AH   = hb;                        // 4M halves  (attn io / ln out)
    __half* qkvh = hb + 4194304u;             // 12.58M halves (4096x3072)
    __half* caqh = qkvh;                      // reuse
    __half* ckvh = hb + 16777216u;            // 2M halves (1024x2048)
    __half* FH   = hb + 18874368u;            // 16.78M halves (4096x4096)
    __half* MH   = hb + 35651584u;            // 1M halves
    __half* Wb   = hb + 36700160u;            // 16.78M halves
    __half* w_qkv  = Wb;
    __half* w_out  = Wb + 3145728;
    __half* w_cain = Wb + 4194304;
    __half* w_caout= Wb + 7340032;
    __half* w_ffn1 = Wb + 8388608;
    __half* w_ffn2 = Wb + 12582912;

    static bool attr_done = false;
    if (!attr_done) {
        cudaFuncSetAttribute(mma_gemm<0, false, false>, cudaFuncAttributeMaxDynamicSharedMemorySize, GSMEM_BYTES);
        cudaFuncSetAttribute(mma_gemm<0, true,  false>, cudaFuncAttributeMaxDynamicSharedMemorySize, GSMEM_BYTES);
        cudaFuncSetAttribute(mma_gemm<0, false, true>,  cudaFuncAttributeMaxDynamicSharedMemorySize, GSMEM_BYTES);
        cudaFuncSetAttribute(mma_gemm<1, false, true>,  cudaFuncAttributeMaxDynamicSharedMemorySize, GSMEM_BYTES);
        attr_done = true;
    }

    // ---- merged conversions: 6 weights + memory, one launch ----
    {
        ConvArgs ca;
        ca.src[0] = qkv_w;    ca.dst[0] = w_qkv;
        ca.src[1] = out_w;    ca.dst[1] = w_out;
        ca.src[2] = ca_in_w;  ca.dst[2] = w_cain;
        ca.src[3] = ca_out_w; ca.dst[3] = w_caout;
        ca.src[4] = ffn_w1;   ca.dst[4] = w_ffn1;
        ca.src[5] = ffn_w2;   ca.dst[5] = w_ffn2;
        ca.src[6] = memory;   ca.dst[6] = MH;
        int blks[7] = {1536, 512, 1536, 512, 2048, 2048, 512};
        int acc = 0;
        for (int i = 0; i < 7; i++) { ca.start[i] = acc; acc += blks[i]; }
        ca.start[7] = acc;
        conv_all<<<acc, 256>>>(ca);
    }

    // ---- self-attention block ----
    ln_round_kernel<<<ROWS, 256>>>(tgt, ln1_g, ln1_b, AH);
    mma_gemm<0, false, true><<<dim3(24, 32), 256, GSMEM_BYTES>>>(
        AH, w_qkv, DD, qkv_b, nullptr, nullptr, qkvh, 3072);
    fa_kernel<1, 1><<<dim3(SS / 128, HH, BB), 256>>>(
        qkvh, 3072, qkvh + 1024, 3072, qkvh + 2048, 3072, AH, DD, SS,
        rope_cos, rope_sin);
    mma_gemm<0, true, false><<<dim3(8, 32), 256, GSMEM_BYTES>>>(
        AH, w_out, DD, out_b, tgt, res, nullptr, DD);

    // ---- cross-attention block ----
    ln_round_kernel<<<ROWS, 256>>>(res, ln2_g, ln2_b, AH);
    mma_gemm<0, false, true><<<dim3(8, 32), 256, GSMEM_BYTES>>>(
        AH, w_cain, DD, ca_in_b, nullptr, nullptr, caqh, DD);
    mma_gemm<0, false, true><<<dim3(16, 8), 256, GSMEM_BYTES>>>(
        MH, w_cain + 1048576, DD, ca_in_b + 1024, nullptr, nullptr, ckvh, 2048);
    fa_kernel<0, 0><<<dim3(SS / 128, HH, BB), 256>>>(
        caqh, DD, ckvh, 2048, ckvh + 1024, 2048, AH, DD, MEMN,
        rope_cos, rope_sin);
    mma_gemm<0, true, false><<<dim3(8, 32), 256, GSMEM_BYTES>>>(
        AH, w_caout, DD, ca_out_b, res, res, nullptr, DD);

    // ---- FFN block ----
    ln_round_kernel<<<ROWS, 256>>>(res, ln3_g, ln3_b, AH);
    mma_gemm<1, false, true><<<dim3(32, 32), 256, GSMEM_BYTES>>>(
        AH, w_ffn1, DD, ffn_b1, nullptr, nullptr, FH, DFF);
    mma_gemm<0, true, false><<<dim3(8, 32), 256, GSMEM_BYTES>>>(
        FH, w_ffn2, DFF, ffn_b2, res, outp, nullptr, DD);
}

// round 12
// speedup vs baseline: 6.6008x; 1.0143x over previous
#include <cuda_runtime.h>
#include <cuda_fp16.h>
#include <math.h>
#include <stdint.h>

// ---------------------------------------------------------------------------
// Problem constants
// ---------------------------------------------------------------------------
#define BB   4
#define SS   1024
#define DD   1024
#define HH   16
#define HD   64
#define DFF  4096
#define MEMN 256
#define ROWS (BB * SS)          // 4096

#define SZ   ((size_t)ROWS * DD)        // 4M floats per slice
__device__ float g_scratch[14 * SZ];

// ---------------------------------------------------------------------------
// helpers
// ---------------------------------------------------------------------------
__device__ __forceinline__ uint32_t smem_u32(const void* p) {
    uint32_t a;
    asm("{ .reg .u64 t; cvta.to.shared.u64 t, %1; cvt.u32.u64 %0, t; }"
        : "=r"(a) : "l"(p));
    return a;
}
#define CPA16(dst, src) \
    asm volatile("cp.async.ca.shared.global [%0], [%1], 16;" :: "r"(dst), "l"(src))
#define CP_COMMIT() asm volatile("cp.async.commit_group;" ::: "memory")
#define CP_WAIT1()  asm volatile("cp.async.wait_group 1;"  ::: "memory")
#define CP_WAIT0()  asm volatile("cp.async.wait_group 0;"  ::: "memory")

__device__ __forceinline__ void round8h(float4 a, float4 b, uint4& hi) {
    __half2 h0 = __floats2half2_rn(a.x, a.y);
    __half2 h1 = __floats2half2_rn(a.z, a.w);
    __half2 h2 = __floats2half2_rn(b.x, b.y);
    __half2 h3 = __floats2half2_rn(b.z, b.w);
    hi.x = *(uint32_t*)&h0; hi.y = *(uint32_t*)&h1; hi.z = *(uint32_t*)&h2; hi.w = *(uint32_t*)&h3;
}
__device__ __forceinline__ uint32_t pack2h(float x, float y) {
    __half2 h = __floats2half2_rn(x, y);
    return *(uint32_t*)&h;
}
__device__ __forceinline__ float gelu_exact(float x) {
    return 0.5f * x * (1.0f + erff(x * 0.70710678118654752440f));
}
__device__ __forceinline__ void mma16816h(float* d, const uint32_t* a, const uint32_t* b) {
    asm volatile("mma.sync.aligned.m16n8k16.row.col.f32.f16.f16.f32 "
        "{%0,%1,%2,%3}, {%4,%5,%6,%7}, {%8,%9}, {%0,%1,%2,%3};"
        : "+f"(d[0]), "+f"(d[1]), "+f"(d[2]), "+f"(d[3])
        : "r"(a[0]), "r"(a[1]), "r"(a[2]), "r"(a[3]), "r"(b[0]), "r"(b[1]));
}
__device__ __forceinline__ void ldsm4(uint32_t* r, uint32_t addr) {
    asm volatile("ldmatrix.sync.aligned.m8n8.x4.shared.b16 {%0,%1,%2,%3}, [%4];"
        : "=r"(r[0]), "=r"(r[1]), "=r"(r[2]), "=r"(r[3]) : "r"(addr));
}
__device__ __forceinline__ void ldsm4t(uint32_t* r, uint32_t addr) {
    asm volatile("ldmatrix.sync.aligned.m8n8.x4.trans.shared.b16 {%0,%1,%2,%3}, [%4];"
        : "=r"(r[0]), "=r"(r[1]), "=r"(r[2]), "=r"(r[3]) : "r"(addr));
}

// ---------------------------------------------------------------------------
// Merged conversion kernel: 7 segments (6 weights + memory), one launch.
// ---------------------------------------------------------------------------
struct ConvArgs {
    const float* src[7];
    __half* dst[7];
    int start[8];
};
__global__ __launch_bounds__(256)
void conv_all(ConvArgs a) {
    int blk = blockIdx.x;
    int s = 0;
    #pragma unroll
    for (int k = 1; k < 7; k++) if (blk >= a.start[k]) s = k;
    int i = (blk - a.start[s]) * 2048 + threadIdx.x * 8;
    const float* in = a.src[s];
    float4 x = *(const float4*)(in + i);
    float4 y = *(const float4*)(in + i + 4);
    uint4 h;
    round8h(x, y, h);
    *(uint4*)(a.dst[s] + i) = h;
}

// ---------------------------------------------------------------------------
// Plain fp16 mma.sync GEMM (unchanged from R11 passing kernel)
// ---------------------------------------------------------------------------
#define TSTR 40
#define GASZ (128 * TSTR)
#define GBUF (2 * GASZ)
#define GBUFB (GBUF * 2)
#define GSMEM_BYTES (2 * GBUFB)   // 40960

template<int ACT, bool HASRES, bool OHALF>
__global__ __launch_bounds__(256, 2)
void mma_gemm(const __half* __restrict__ AH, const __half* __restrict__ WH,
              int K, const float* __restrict__ bias, const float* __restrict__ R,
              float* __restrict__ C, __half* __restrict__ OH, int ldc)
{
    extern __shared__ __half dsm[];
    uint32_t sb = smem_u32(dsm);

    int tid  = threadIdx.x;
    int wid  = tid >> 5, lane = tid & 31;
    int m0   = blockIdx.y * 128, n0 = blockIdx.x * 128;

    const __half* gp[4];
    uint32_t smoff[4];
    #pragma unroll
    for (int s = 0; s < 4; s++) {
        int seg = tid + s * 256;
        int arr = seg >> 9;
        int rem = seg & 511;
        int row = rem >> 2;
        int col = (rem & 3) * 8;
        const __half* base = (arr == 0) ? AH + (size_t)(m0 + row) * K
                                        : WH + (size_t)(n0 + row) * K;
        gp[s] = base + col;
        smoff[s] = (uint32_t)(arr * GASZ + row * TSTR + col) * 2;
    }

    int wm = (wid & 1) * 64;
    int wn = (wid >> 1) * 32;
    int r  = lane >> 2;
    int cq = (lane & 3) * 2;

    float acc[4][4][4];
    #pragma unroll
    for (int mt = 0; mt < 4; mt++)
        #pragma unroll
        for (int nt = 0; nt < 4; nt++)
            #pragma unroll
            for (int i = 0; i < 4; i++) acc[mt][nt][i] = 0.f;

    #pragma unroll
    for (int s = 0; s < 4; s++) CPA16(sb + smoff[s], gp[s]);
    CP_COMMIT();

    int NC = K >> 5;
    for (int c = 0; c < NC; ++c) {
        if (c + 1 < NC) {
            uint32_t boff = (uint32_t)(((c + 1) & 1) * GBUFB);
            #pragma unroll
            for (int s = 0; s < 4; s++) CPA16(sb + boff + smoff[s], gp[s] + (c + 1) * 32);
            CP_COMMIT();
            CP_WAIT1();
        } else {
            CP_WAIT0();
        }
        __syncthreads();

        {
            const __half* Ah = dsm + (c & 1) * GBUF;
            const __half* Bh = Ah + GASZ;
            #pragma unroll
            for (int kh = 0; kh < 2; kh++) {
                int cc = cq + kh * 16;
                uint32_t ah[4][4], bh[4][2];
                #pragma unroll
                for (int mt = 0; mt < 4; mt++) {
                    int rb = (wm + mt * 16 + r) * TSTR;
                    int rb8 = rb + 8 * TSTR;
                    ah[mt][0] = *(const uint32_t*)&Ah[rb + cc];
                    ah[mt][1] = *(const uint32_t*)&Ah[rb8 + cc];
                    ah[mt][2] = *(const uint32_t*)&Ah[rb + cc + 8];
                    ah[mt][3] = *(const uint32_t*)&Ah[rb8 + cc + 8];
                }
                #pragma unroll
                for (int nt = 0; nt < 4; nt++) {
                    int nb = (wn + nt * 8 + r) * TSTR;
                    bh[nt][0] = *(const uint32_t*)&Bh[nb + cc];
                    bh[nt][1] = *(const uint32_t*)&Bh[nb + cc + 8];
                }
                #pragma unroll
                for (int mt = 0; mt < 4; mt++)
                    #pragma unroll
                    for (int nt = 0; nt < 4; nt++)
                        mma16816h(acc[mt][nt], ah[mt], bh[nt]);
            }
        }
        __syncthreads();
    }

    #pragma unroll
    for (int mt = 0; mt < 4; mt++) {
        int row0 = m0 + wm + mt * 16 + r;
        #pragma unroll
        for (int nt = 0; nt < 4; nt++) {
            int coln = n0 + wn + nt * 8 + cq;
            float2 bv = *(const float2*)(bias + coln);
            float v0 = acc[mt][nt][0] + bv.x;
            float v1 = acc[mt][nt][1] + bv.y;
            float v2 = acc[mt][nt][2] + bv.x;
            float v3 = acc[mt][nt][3] + bv.y;
            if (ACT == 1) {
                v0 = gelu_exact(v0); v1 = gelu_exact(v1);
                v2 = gelu_exact(v2); v3 = gelu_exact(v3);
            }
            if (HASRES) {
                float2 r0 = *(const float2*)(R + (size_t)row0 * ldc + coln);
                float2 r1 = *(const float2*)(R + (size_t)(row0 + 8) * ldc + coln);
                v0 += r0.x; v1 += r0.y; v2 += r1.x; v3 += r1.y;
            }
            if (OHALF) {
                *(uint32_t*)(OH + (size_t)row0 * ldc + coln)       = pack2h(v0, v1);
                *(uint32_t*)(OH + (size_t)(row0 + 8) * ldc + coln) = pack2h(v2, v3);
            } else {
                *(float2*)(C + (size_t)row0 * ldc + coln)       = make_float2(v0, v1);
                *(float2*)(C + (size_t)(row0 + 8) * ldc + coln) = make_float2(v2, v3);
            }
        }
    }
}

// ---------------------------------------------------------------------------
// fp16 flash attention, ldmatrix fragment path.
// K and V both stored [key][dim] (stride 72 halves, conflict-free).
// QK B-fragments via ldmatrix.x4; PV B-fragments via ldmatrix.x4.trans.
// Fused RoPE on Q fragments and K tiles.
// ---------------------------------------------------------------------------
#define FSTR 72

template<int CAUSAL, int ROPE>
__global__ __launch_bounds__(256, 2)
void fa_kernel(const __half* __restrict__ Q, int ldq,
               const __half* __restrict__ Kp, int ldk,
               const __half* __restrict__ Vp, int ldv,
               __half* __restrict__ OH, int ldo, int kvlen,
               const float* __restrict__ cosb, const float* __restrict__ sinb)
{
    __shared__ __half Kv[64 * FSTR];
    __shared__ __half Vv[64 * FSTR];

    int tid = threadIdx.x;
    int wid = tid >> 5, lane = tid & 31;
    int r   = lane >> 2;
    int cq  = (lane & 3) * 2;
    int b = blockIdx.z, h = blockIdx.y;
    int q0 = blockIdx.x * 128;
    int qrow0 = q0 + wid * 16 + r;
    int wmin  = q0 + wid * 16;
    int wmax  = wmin + 15;

    uint32_t kbase = smem_u32(Kv);
    uint32_t vbase = smem_u32(Vv);
    int lm  = lane & 7;
    int grp = lane >> 3;
    // per-lane ldmatrix row-address offsets (bytes), see derivation in theory
    uint32_t kfrag0 = (uint32_t)((((grp >> 1) * 8 + lm) * FSTR + 8 * (grp & 1))) * 2;
    uint32_t vfrag0 = (uint32_t)(((8 * (grp & 1) + lm) * FSTR + (grp >> 1) * 8)) * 2;

    uint32_t qh[4][4];
    {
        const __half* qb  = Q + (size_t)(b * SS + qrow0) * ldq + h * 64;
        const __half* qb8 = qb + (size_t)8 * ldq;
        #pragma unroll
        for (int ks = 0; ks < 4; ks++) {
            float2 f0 = __half22float2(*(const __half2*)(qb  + 16 * ks + cq));
            float2 f1 = __half22float2(*(const __half2*)(qb8 + 16 * ks + cq));
            float2 f2 = __half22float2(*(const __half2*)(qb  + 16 * ks + cq + 8));
            float2 f3 = __half22float2(*(const __half2*)(qb8 + 16 * ks + cq + 8));
            if (ROPE) {
                int i0 = (16 * ks + cq) >> 1;
                int i1 = i0 + 4;
                float c0 = cosb[qrow0 * 32 + i0],       s0 = sinb[qrow0 * 32 + i0];
                float c8 = cosb[(qrow0 + 8) * 32 + i0], s8 = sinb[(qrow0 + 8) * 32 + i0];
                float c1 = cosb[qrow0 * 32 + i1],       s1 = sinb[qrow0 * 32 + i1];
                float c9 = cosb[(qrow0 + 8) * 32 + i1], s9 = sinb[(qrow0 + 8) * 32 + i1];
                f0 = make_float2(f0.x * c0 - f0.y * s0, f0.x * s0 + f0.y * c0);
                f1 = make_float2(f1.x * c8 - f1.y * s8, f1.x * s8 + f1.y * c8);
                f2 = make_float2(f2.x * c1 - f2.y * s1, f2.x * s1 + f2.y * c1);
                f3 = make_float2(f3.x * c9 - f3.y * s9, f3.x * s9 + f3.y * c9);
            }
            qh[ks][0] = pack2h(f0.x * 0.125f, f0.y * 0.125f);
            qh[ks][1] = pack2h(f1.x * 0.125f, f1.y * 0.125f);
            qh[ks][2] = pack2h(f2.x * 0.125f, f2.y * 0.125f);
            qh[ks][3] = pack2h(f3.x * 0.125f, f3.y * 0.125f);
        }
    }

    float oacc[8][4];
    #pragma unroll
    for (int nf = 0; nf < 8; nf++)
        #pragma unroll
        for (int i = 0; i < 4; i++) oacc[nf][i] = 0.f;
    float mrun0 = -INFINITY, mrun1 = -INFINITY, l0 = 0.f, l1 = 0.f;

    int ntiles = CAUSAL ? ((q0 >> 6) + 2) : (kvlen >> 6);

    int kkey = tid >> 2, kdg = (tid & 3) * 16;

    for (int tile = 0; tile < ntiles; tile++) {
        int t0 = tile * 64;
        __syncthreads();
        {   // K tile [key][dim] (optionally with rope)
            const __half* kr = Kp + (size_t)(b * kvlen + t0 + kkey) * ldk + h * 64 + kdg;
            uint4 p0 = *(const uint4*)(kr);
            uint4 p1 = *(const uint4*)(kr + 8);
            int base = kkey * FSTR + kdg;
            if (ROPE) {
                int s = t0 + kkey;
                const float* cb = cosb + s * 32 + (kdg >> 1);
                const float* sb = sinb + s * 32 + (kdg >> 1);
                uint32_t o[8];
                #pragma unroll
                for (int j = 0; j < 4; j++) {
                    float2 f = __half22float2(((const __half2*)&p0)[j]);
                    float c = cb[j], sn = sb[j];
                    o[j] = pack2h(f.x * c - f.y * sn, f.x * sn + f.y * c);
                }
                #pragma unroll
                for (int j = 0; j < 4; j++) {
                    float2 f = __half22float2(((const __half2*)&p1)[j]);
                    float c = cb[4 + j], sn = sb[4 + j];
                    o[4 + j] = pack2h(f.x * c - f.y * sn, f.x * sn + f.y * c);
                }
                *(uint4*)&Kv[base]     = *(uint4*)&o[0];
                *(uint4*)&Kv[base + 8] = *(uint4*)&o[4];
            } else {
                *(uint4*)&Kv[base]     = p0;
                *(uint4*)&Kv[base + 8] = p1;
            }
        }
        {   // V tile [key][dim] — straight copy, conflict-free
            const __half* vr = Vp + (size_t)(b * kvlen + t0 + kkey) * ldv + h * 64 + kdg;
            int base = kkey * FSTR + kdg;
            *(uint4*)&Vv[base]     = *(const uint4*)(vr);
            *(uint4*)&Vv[base + 8] = *(const uint4*)(vr + 8);
        }
        __syncthreads();

        bool active = !CAUSAL || (t0 <= wmax);
        if (!active) continue;

        // S = Q K^T via ldmatrix B-fragments
        float sc[8][4];
        #pragma unroll
        for (int nf = 0; nf < 8; nf++)
            #pragma unroll
            for (int i = 0; i < 4; i++) sc[nf][i] = 0.f;

        #pragma unroll
        for (int ks = 0; ks < 4; ks++) {
            #pragma unroll
            for (int i = 0; i < 4; i++) {
                uint32_t bh[4];
                ldsm4(bh, kbase + kfrag0 + (uint32_t)(i * 16 * FSTR + 16 * ks) * 2);
                mma16816h(sc[2 * i],     qh[ks], bh);
                mma16816h(sc[2 * i + 1], qh[ks], bh + 2);
            }
        }

        if (CAUSAL && (t0 + 63 > wmin)) {
            #pragma unroll
            for (int nf = 0; nf < 8; nf++) {
                int jb = t0 + nf * 8 + cq;
                if (jb     > qrow0)     sc[nf][0] = -INFINITY;
                if (jb + 1 > qrow0)     sc[nf][1] = -INFINITY;
                if (jb     > qrow0 + 8) sc[nf][2] = -INFINITY;
                if (jb + 1 > qrow0 + 8) sc[nf][3] = -INFINITY;
            }
        }

        float mx0 = -INFINITY, mx1 = -INFINITY;
        #pragma unroll
        for (int nf = 0; nf < 8; nf++) {
            mx0 = fmaxf(mx0, fmaxf(sc[nf][0], sc[nf][1]));
            mx1 = fmaxf(mx1, fmaxf(sc[nf][2], sc[nf][3]));
        }
        mx0 = fmaxf(mx0, __shfl_xor_sync(0xffffffffu, mx0, 1));
        mx0 = fmaxf(mx0, __shfl_xor_sync(0xffffffffu, mx0, 2));
        mx1 = fmaxf(mx1, __shfl_xor_sync(0xffffffffu, mx1, 1));
        mx1 = fmaxf(mx1, __shfl_xor_sync(0xffffffffu, mx1, 2));
        float mn0 = fmaxf(mrun0, mx0), mn1 = fmaxf(mrun1, mx1);
        float c0 = __expf(mrun0 - mn0), c1 = __expf(mrun1 - mn1);
        float s0 = 0.f, s1 = 0.f;
        #pragma unroll
        for (int nf = 0; nf < 8; nf++) {
            sc[nf][0] = __expf(sc[nf][0] - mn0);
            sc[nf][1] = __expf(sc[nf][1] - mn0);
            sc[nf][2] = __expf(sc[nf][2] - mn1);
            sc[nf][3] = __expf(sc[nf][3] - mn1);
            s0 += sc[nf][0] + sc[nf][1];
            s1 += sc[nf][2] + sc[nf][3];
        }
        s0 += __shfl_xor_sync(0xffffffffu, s0, 1);
        s0 += __shfl_xor_sync(0xffffffffu, s0, 2);
        s1 += __shfl_xor_sync(0xffffffffu, s1, 1);
        s1 += __shfl_xor_sync(0xffffffffu, s1, 2);
        l0 = l0 * c0 + s0;
        l1 = l1 * c1 + s1;
        mrun0 = mn0; mrun1 = mn1;
        #pragma unroll
        for (int nf = 0; nf < 8; nf++) {
            oacc[nf][0] *= c0; oacc[nf][1] *= c0;
            oacc[nf][2] *= c1; oacc[nf][3] *= c1;
        }

        // O += P V via ldmatrix.trans B-fragments
        #pragma unroll
        for (int kg = 0; kg < 4; kg++) {
            uint32_t pah[4];
            pah[0] = pack2h(sc[2 * kg][0],     sc[2 * kg][1]);
            pah[1] = pack2h(sc[2 * kg][2],     sc[2 * kg][3]);
            pah[2] = pack2h(sc[2 * kg + 1][0], sc[2 * kg + 1][1]);
            pah[3] = pack2h(sc[2 * kg + 1][2], sc[2 * kg + 1][3]);
            #pragma unroll
            for (int i = 0; i < 4; i++) {
                uint32_t bv[4];
                ldsm4t(bv, vbase + vfrag0 + (uint32_t)(16 * kg * FSTR + i * 16) * 2);
                mma16816h(oacc[2 * i],     pah, bv);
                mma16816h(oacc[2 * i + 1], pah, bv + 2);
            }
        }
    }

    float inv0 = 1.0f / l0, inv1 = 1.0f / l1;
    size_t ob  = (size_t)(b * SS + qrow0) * ldo + h * 64;
    size_t ob8 = ob + (size_t)8 * ldo;
    #pragma unroll
    for (int nf = 0; nf < 8; nf++) {
        *(uint32_t*)(OH + ob  + nf * 8 + cq) = pack2h(oacc[nf][0] * inv0, oacc[nf][1] * inv0);
        *(uint32_t*)(OH + ob8 + nf * 8 + cq) = pack2h(oacc[nf][2] * inv1, oacc[nf][3] * inv1);
    }
}

// ---------------------------------------------------------------------------
// LayerNorm with fused fp16 output
// ---------------------------------------------------------------------------
__global__ __launch_bounds__(256)
void ln_round_kernel(const float* __restrict__ X, const float* __restrict__ gam,
                     const float* __restrict__ bet, __half* __restrict__ OH)
{
    int row = blockIdx.x;
    int t = threadIdx.x;
    int lane = t & 31, w = t >> 5;
    const float4* x4 = (const float4*)(X + (size_t)row * DD);
    float4 v = x4[t];
    float s  = v.x + v.y + v.z + v.w;
    float ss = v.x * v.x + v.y * v.y + v.z * v.z + v.w * v.w;
    #pragma unroll
    for (int o = 16; o > 0; o >>= 1) {
        s  += __shfl_xor_sync(0xffffffffu, s,  o);
        ss += __shfl_xor_sync(0xffffffffu, ss, o);
    }
    __shared__ float red[16];
    if (lane == 0) { red[w] = s; red[w + 8] = ss; }
    __syncthreads();
    float st = 0.f, sst = 0.f;
    #pragma unroll
    for (int i = 0; i < 8; i++) { st += red[i]; sst += red[i + 8]; }
    float mu   = st * (1.0f / DD);
    float var  = sst * (1.0f / DD) - mu * mu;
    float rstd = rsqrtf(var + 1e-5f);
    const float4* g4 = (const float4*)gam;
    const float4* b4 = (const float4*)bet;
    float4 gg = g4[t], bb = b4[t], o4;
    o4.x = (v.x - mu) * rstd * gg.x + bb.x;
    o4.y = (v.y - mu) * rstd * gg.y + bb.y;
    o4.z = (v.z - mu) * rstd * gg.z + bb.z;
    o4.w = (v.w - mu) * rstd * gg.w + bb.w;
    size_t off = (size_t)row * DD + t * 4;
    *(uint2*)(OH + off) = make_uint2(pack2h(o4.x, o4.y), pack2h(o4.z, o4.w));
}

// ---------------------------------------------------------------------------
// Host orchestration
// ---------------------------------------------------------------------------
extern "C" void kernel_launch(void* const* d_in, const int* in_sizes, int n_in,
                              void* d_out, int out_size)
{
    const float* tgt      = (const float*)d_in[0];
    const float* memory   = (const float*)d_in[1];
    const float* rope_cos = (const float*)d_in[3];
    const float* rope_sin = (const float*)d_in[4];
    const float* qkv_w    = (const float*)d_in[5];
    const float* qkv_b    = (const float*)d_in[6];
    const float* out_w    = (const float*)d_in[7];
    const float* out_b    = (const float*)d_in[8];
    const float* ca_in_w  = (const float*)d_in[9];
    const float* ca_in_b  = (const float*)d_in[10];
    const float* ca_out_w = (const float*)d_in[11];
    const float* ca_out_b = (const float*)d_in[12];
    const float* ffn_w1   = (const float*)d_in[13];
    const float* ffn_b1   = (const float*)d_in[14];
    const float* ffn_w2   = (const float*)d_in[15];
    const float* ffn_b2   = (const float*)d_in[16];
    const float* ln1_g    = (const float*)d_in[17];
    const float* ln1_b    = (const float*)d_in[18];
    const float* ln2_g    = (const float*)d_in[19];
    const float* ln2_b    = (const float*)d_in[20];
    const float* ln3_g    = (const float*)d_in[21];
    const float* ln3_b    = (const float*)d_in[22];
    float* outp = (float*)d_out;

    float* S_ = nullptr;
    cudaGetSymbolAddress((void**)&S_, g_scratch);
    float*  res = S_;                         // fp32 slice 0
    __half* hb  = (__half*)(S_ + SZ);
    __half* AH   = hb;                        // 4M halves  (attn io / ln out)
    __half* qkvh = hb + 4194304u;             // 12.58M halves (4096x3072)
    __half* caqh = qkvh;                      // reuse
    __half* ckvh = hb + 16777216u;            // 2M halves (1024x2048)
    __half* FH   = hb + 18874368u;            // 16.78M halves (4096x4096)
    __half* MH   = hb + 35651584u;            // 1M halves
    __half* Wb   = hb + 36700160u;            // 16.78M halves
    __half* w_qkv  = Wb;
    __half* w_out  = Wb + 3145728;
    __half* w_cain = Wb + 4194304;
    __half* w_caout= Wb + 7340032;
    __half* w_ffn1 = Wb + 8388608;
    __half* w_ffn2 = Wb + 12582912;

    static bool attr_done = false;
    if (!attr_done) {
        cudaFuncSetAttribute(mma_gemm<0, false, false>, cudaFuncAttributeMaxDynamicSharedMemorySize, GSMEM_BYTES);
        cudaFuncSetAttribute(mma_gemm<0, true,  false>, cudaFuncAttributeMaxDynamicSharedMemorySize, GSMEM_BYTES);
        cudaFuncSetAttribute(mma_gemm<0, false, true>,  cudaFuncAttributeMaxDynamicSharedMemorySize, GSMEM_BYTES);
        cudaFuncSetAttribute(mma_gemm<1, false, true>,  cudaFuncAttributeMaxDynamicSharedMemorySize, GSMEM_BYTES);
        attr_done = true;
    }

    // ---- merged conversions: 6 weights + memory, one launch ----
    {
        ConvArgs ca;
        ca.src[0] = qkv_w;    ca.dst[0] = w_qkv;
        ca.src[1] = out_w;    ca.dst[1] = w_out;
        ca.src[2] = ca_in_w;  ca.dst[2] = w_cain;
        ca.src[3] = ca_out_w; ca.dst[3] = w_caout;
        ca.src[4] = ffn_w1;   ca.dst[4] = w_ffn1;
        ca.src[5] = ffn_w2;   ca.dst[5] = w_ffn2;
        ca.src[6] = memory;   ca.dst[6] = MH;
        int blks[7] = {1536, 512, 1536, 512, 2048, 2048, 512};
        int acc = 0;
        for (int i = 0; i < 7; i++) { ca.start[i] = acc; acc += blks[i]; }
        ca.start[7] = acc;
        conv_all<<<acc, 256>>>(ca);
    }

    // ---- self-attention block ----
    ln_round_kernel<<<ROWS, 256>>>(tgt, ln1_g, ln1_b, AH);
    mma_gemm<0, false, true><<<dim3(24, 32), 256, GSMEM_BYTES>>>(
        AH, w_qkv, DD, qkv_b, nullptr, nullptr, qkvh, 3072);
    fa_kernel<1, 1><<<dim3(SS / 128, HH, BB), 256>>>(
        qkvh, 3072, qkvh + 1024, 3072, qkvh + 2048, 3072, AH, DD, SS,
        rope_cos, rope_sin);
    mma_gemm<0, true, false><<<dim3(8, 32), 256, GSMEM_BYTES>>>(
        AH, w_out, DD, out_b, tgt, res, nullptr, DD);

    // ---- cross-attention block ----
    ln_round_kernel<<<ROWS, 256>>>(res, ln2_g, ln2_b, AH);
    mma_gemm<0, false, true><<<dim3(8, 32), 256, GSMEM_BYTES>>>(
        AH, w_cain, DD, ca_in_b, nullptr, nullptr, caqh, DD);
    mma_gemm<0, false, true><<<dim3(16, 8), 256, GSMEM_BYTES>>>(
        MH, w_cain + 1048576, DD, ca_in_b + 1024, nullptr, nullptr, ckvh, 2048);
    fa_kernel<0, 0><<<dim3(SS / 128, HH, BB), 256>>>(
        caqh, DD, ckvh, 2048, ckvh + 1024, 2048, AH, DD, MEMN,
        rope_cos, rope_sin);
    mma_gemm<0, true, false><<<dim3(8, 32), 256, GSMEM_BYTES>>>(
        AH, w_caout, DD, ca_out_b, res, res, nullptr, DD);

    // ---- FFN block ----
    ln_round_kernel<<<ROWS, 256>>>(res, ln3_g, ln3_b, AH);
    mma_gemm<1, false, true><<<dim3(32, 32), 256, GSMEM_BYTES>>>(
        AH, w_ffn1, DD, ffn_b1, nullptr, nullptr, FH, DFF);
    mma_gemm<0, true, false><<<dim3(8, 32), 256, GSMEM_BYTES>>>(
        FH, w_ffn2, DFF, ffn_b2, res, outp, nullptr, DD);
}